// round 7
// baseline (speedup 1.0000x reference)
#include <cuda_runtime.h>
#include <cuda_bf16.h>
#include <cstdint>

#define Bn 16
#define Cc 256
#define Sn 4096   // H*W
#define C8 32     // C/8
#define C2 128    // C/2
#define Dn 1024   // down = HW/4

typedef unsigned long long ull;
typedef unsigned int uint;

// ---- packed fp32x2 helpers ----
__device__ __forceinline__ ull ffma2(ull a, ull b, ull c) {
    ull d;
    asm("fma.rn.f32x2 %0, %1, %2, %3;" : "=l"(d) : "l"(a), "l"(b), "l"(c));
    return d;
}
__device__ __forceinline__ ull dup2(float v) {
    ull d;
    asm("mov.b64 %0, {%1, %1};" : "=l"(d) : "f"(v));
    return d;
}

// ---- mma/ldmatrix helpers ----
__device__ __forceinline__ uint32_t smem_u32(const void* p) {
    uint32_t a;
    asm("{ .reg .u64 t; cvta.to.shared.u64 t, %1; cvt.u32.u64 %0, t; }" : "=r"(a) : "l"(p));
    return a;
}
__device__ __forceinline__ void ldsm4(uint32_t a, uint& r0, uint& r1, uint& r2, uint& r3) {
    asm volatile("ldmatrix.sync.aligned.m8n8.x4.shared.b16 {%0,%1,%2,%3}, [%4];"
                 : "=r"(r0), "=r"(r1), "=r"(r2), "=r"(r3) : "r"(a));
}
__device__ __forceinline__ void ldsm4t(uint32_t a, uint& r0, uint& r1, uint& r2, uint& r3) {
    asm volatile("ldmatrix.sync.aligned.m8n8.x4.trans.shared.b16 {%0,%1,%2,%3}, [%4];"
                 : "=r"(r0), "=r"(r1), "=r"(r2), "=r"(r3) : "r"(a));
}
__device__ __forceinline__ void mma16816(float* d, uint a0, uint a1, uint a2, uint a3,
                                         uint b0, uint b1) {
    asm volatile(
        "mma.sync.aligned.m16n8k16.row.col.f32.bf16.bf16.f32 "
        "{%0,%1,%2,%3}, {%4,%5,%6,%7}, {%8,%9}, {%0,%1,%2,%3};"
        : "+f"(d[0]), "+f"(d[1]), "+f"(d[2]), "+f"(d[3])
        : "r"(a0), "r"(a1), "r"(a2), "r"(a3), "r"(b0), "r"(b1));
}

// split fp32 pair -> packed bf16 hi-pair / lo-pair
__device__ __forceinline__ void split2(float x, float y, uint& hi, uint& lo) {
    __nv_bfloat16 hx = __float2bfloat16_rn(x), hy = __float2bfloat16_rn(y);
    float rx = x - __bfloat162float(hx), ry = y - __bfloat162float(hy);
    __nv_bfloat16 lx = __float2bfloat16_rn(rx), ly = __float2bfloat16_rn(ry);
    __nv_bfloat162 hp, lp;
    hp.x = hx; hp.y = hy; lp.x = lx; lp.y = ly;
    hi = *(uint*)&hp;
    lo = *(uint*)&lp;
}
__device__ __forceinline__ void split1(float x, unsigned short& h, unsigned short& l) {
    __nv_bfloat16 hb = __float2bfloat16_rn(x);
    float r = x - __bfloat162float(hb);
    __nv_bfloat16 lb = __float2bfloat16_rn(r);
    h = *(unsigned short*)&hb;
    l = *(unsigned short*)&lb;
}

// ---- scratch ----
__device__ float g_q[(size_t)Bn * C8 * Sn];
__device__ float g_k[(size_t)Bn * C8 * Dn];
__device__ float g_v[(size_t)Bn * C2 * Dn];
__device__ float g_attn[(size_t)Bn * Sn * Dn];           // fp32 logits
__device__ unsigned short g_ah[(size_t)Bn * Sn * Dn];    // exp(logit) hi bf16
__device__ unsigned short g_al[(size_t)Bn * Sn * Dn];    // exp(logit) lo bf16
__device__ unsigned short g_vh[(size_t)Bn * C2 * Dn];    // crs*v hi
__device__ unsigned short g_vl[(size_t)Bn * C2 * Dn];    // crs*v lo
__device__ float g_crs[Bn * Dn];
__device__ float g_app[(size_t)Bn * Sn * C2];

// ---------------------------------------------------------------------------
// Fused conv: q / k-pooled / v-pooled (unchanged, known-good)
// ---------------------------------------------------------------------------
__global__ __launch_bounds__(128) void conv_all_k(
    const float* __restrict__ x,
    const float* __restrict__ qw, const float* __restrict__ qb,
    const float* __restrict__ kw, const float* __restrict__ kb,
    const float* __restrict__ vw, const float* __restrict__ vb) {
    int b = blockIdx.z, ot = blockIdx.y, st = blockIdx.x;
    int s0 = st * 128;
    int t = threadIdx.x;

    __shared__ __align__(16) union {
        struct { float Ws[2][16][68]; float Xs[2][16][128]; } p;
        float Cs[64][128];
    } sm;

    int wrow = t >> 1;
    int wkg = (t & 1) << 3;
    int gch = ot * 64 + wrow;
    const float* wsrc;
    if (gch < 32) wsrc = qw + (size_t)gch * Cc;
    else if (gch < 64) wsrc = kw + (size_t)(gch - 32) * Cc;
    else wsrc = vw + (size_t)(gch - 64) * Cc;
    wsrc += wkg;

    int xkk = t >> 3;
    int xsg = (t & 7) << 4;
    const float* xsrc = x + (size_t)b * Cc * Sn + (size_t)xkk * Sn + s0 + xsg;

    int ty = t >> 4, tx = t & 15;

    ull acc[8][4];
#pragma unroll
    for (int i = 0; i < 8; i++)
#pragma unroll
        for (int j = 0; j < 4; j++) acc[i][j] = 0ULL;

    {
#pragma unroll
        for (int u = 0; u < 2; u++) {
            float4 v = *(const float4*)(wsrc + u * 4);
            sm.p.Ws[0][wkg + u * 4 + 0][wrow] = v.x;
            sm.p.Ws[0][wkg + u * 4 + 1][wrow] = v.y;
            sm.p.Ws[0][wkg + u * 4 + 2][wrow] = v.z;
            sm.p.Ws[0][wkg + u * 4 + 3][wrow] = v.w;
        }
#pragma unroll
        for (int u = 0; u < 4; u++)
            *(float4*)&sm.p.Xs[0][xkk][xsg + u * 4] = *(const float4*)(xsrc + u * 4);
    }
    __syncthreads();

    for (int ch = 0; ch < 16; ch++) {
        int cb = ch & 1;
        float4 wpre[2], xpre[4];
        if (ch < 15) {
            const float* wp = wsrc + (ch + 1) * 16;
            wpre[0] = *(const float4*)(wp);
            wpre[1] = *(const float4*)(wp + 4);
            const float* xp = xsrc + (size_t)(ch + 1) * 16 * Sn;
#pragma unroll
            for (int u = 0; u < 4; u++) xpre[u] = *(const float4*)(xp + u * 4);
        }
#pragma unroll
        for (int kk = 0; kk < 16; kk++) {
            float4 a0 = *(const float4*)&sm.p.Ws[cb][kk][ty * 8];
            float4 a1 = *(const float4*)&sm.p.Ws[cb][kk][ty * 8 + 4];
            ulonglong2 b0 = *(const ulonglong2*)&sm.p.Xs[cb][kk][tx * 8];
            ulonglong2 b1 = *(const ulonglong2*)&sm.p.Xs[cb][kk][tx * 8 + 4];
            ull bp[4] = {b0.x, b0.y, b1.x, b1.y};
            float aa[8] = {a0.x, a0.y, a0.z, a0.w, a1.x, a1.y, a1.z, a1.w};
#pragma unroll
            for (int i = 0; i < 8; i++) {
                ull ad = dup2(aa[i]);
#pragma unroll
                for (int j = 0; j < 4; j++) acc[i][j] = ffma2(ad, bp[j], acc[i][j]);
            }
        }
        if (ch < 15) {
            int nb = cb ^ 1;
#pragma unroll
            for (int u = 0; u < 2; u++) {
                sm.p.Ws[nb][wkg + u * 4 + 0][wrow] = (&wpre[u].x)[0];
                sm.p.Ws[nb][wkg + u * 4 + 1][wrow] = (&wpre[u].x)[1];
                sm.p.Ws[nb][wkg + u * 4 + 2][wrow] = (&wpre[u].x)[2];
                sm.p.Ws[nb][wkg + u * 4 + 3][wrow] = (&wpre[u].x)[3];
            }
#pragma unroll
            for (int u = 0; u < 4; u++)
                *(float4*)&sm.p.Xs[nb][xkk][xsg + u * 4] = xpre[u];
        }
        __syncthreads();
    }

#pragma unroll
    for (int i = 0; i < 8; i++) {
        ulonglong2 u0, u1;
        u0.x = acc[i][0]; u0.y = acc[i][1];
        u1.x = acc[i][2]; u1.y = acc[i][3];
        *(ulonglong2*)&sm.Cs[ty * 8 + i][tx * 8] = u0;
        *(ulonglong2*)&sm.Cs[ty * 8 + i][tx * 8 + 4] = u1;
    }
    __syncthreads();

    if (ot == 0) {
#pragma unroll
        for (int i = 0; i < 8; i++) {
            int o = i * 4 + (t >> 5);
            int sp = (t & 31) * 4;
            float4 v = *(const float4*)&sm.Cs[o][sp];
            float bb = qb[o];
            v.x += bb; v.y += bb; v.z += bb; v.w += bb;
            *(float4*)(g_q + (size_t)b * C8 * Sn + (size_t)o * Sn + s0 + sp) = v;
        }
        {
            int o = 32 + (t >> 2);
            int qcb = (t & 3) * 8;
            float bb = kb[o - 32];
            float* dst = g_k + (size_t)b * C8 * Dn + (size_t)(o - 32) * Dn + st * 32;
#pragma unroll
            for (int jj = 0; jj < 8; jj++) {
                int qc = qcb + jj;
                float m = fmaxf(fmaxf(sm.Cs[o][2 * qc], sm.Cs[o][2 * qc + 1]),
                                fmaxf(sm.Cs[o][64 + 2 * qc], sm.Cs[o][64 + 2 * qc + 1]));
                dst[qc] = m + bb;
            }
        }
    } else {
        int vg0 = (ot - 1) * 64;
        int o = t >> 1;
        int qcb = (t & 1) * 16;
        float bb = vb[vg0 + o];
        float* dst = g_v + (size_t)b * C2 * Dn + (size_t)(vg0 + o) * Dn + st * 32;
#pragma unroll
        for (int jj = 0; jj < 16; jj++) {
            int qc = qcb + jj;
            float m = fmaxf(fmaxf(sm.Cs[o][2 * qc], sm.Cs[o][2 * qc + 1]),
                            fmaxf(sm.Cs[o][64 + 2 * qc], sm.Cs[o][64 + 2 * qc + 1]));
            dst[qc] = m + bb;
        }
    }
}

// ---------------------------------------------------------------------------
// attn logits via split-bf16 HMMA: attn[l,j] = dot(q[l][0:32], k[j][0:32])
// tile 128x128, K=32 one-shot, 8 warps (4l x 2j), warp tile 32x64.
// grid (Dn/128, Sn/128, Bn)
// ---------------------------------------------------------------------------
__global__ __launch_bounds__(256) void attn_hmma_k() {
    __shared__ __align__(16) unsigned short QAh[128][40], QAl[128][40];  // 80B rows
    __shared__ __align__(16) unsigned short KBh[128][40], KBl[128][40];

    int t = threadIdx.x, lane = t & 31, wid = t >> 5;
    int b = blockIdx.z, l0 = blockIdx.y * 128, j0 = blockIdx.x * 128;

    // load + split q and k tiles
    {
        int row = t >> 1, fs = (t & 1) * 16;
        const float* qp = g_q + (size_t)b * C8 * Sn + (size_t)(l0 + row) * 32 + fs;
        const float* kp = g_k + (size_t)b * C8 * Dn + (size_t)(j0 + row) * 32 + fs;
        uint h[8], l[8];
#pragma unroll
        for (int u = 0; u < 4; u++) {
            float4 v = *(const float4*)(qp + u * 4);
            split2(v.x, v.y, h[2 * u], l[2 * u]);
            split2(v.z, v.w, h[2 * u + 1], l[2 * u + 1]);
        }
        *(uint4*)&QAh[row][fs] = make_uint4(h[0], h[1], h[2], h[3]);
        *(uint4*)&QAh[row][fs + 8] = make_uint4(h[4], h[5], h[6], h[7]);
        *(uint4*)&QAl[row][fs] = make_uint4(l[0], l[1], l[2], l[3]);
        *(uint4*)&QAl[row][fs + 8] = make_uint4(l[4], l[5], l[6], l[7]);
#pragma unroll
        for (int u = 0; u < 4; u++) {
            float4 v = *(const float4*)(kp + u * 4);
            split2(v.x, v.y, h[2 * u], l[2 * u]);
            split2(v.z, v.w, h[2 * u + 1], l[2 * u + 1]);
        }
        *(uint4*)&KBh[row][fs] = make_uint4(h[0], h[1], h[2], h[3]);
        *(uint4*)&KBh[row][fs + 8] = make_uint4(h[4], h[5], h[6], h[7]);
        *(uint4*)&KBl[row][fs] = make_uint4(l[0], l[1], l[2], l[3]);
        *(uint4*)&KBl[row][fs + 8] = make_uint4(l[4], l[5], l[6], l[7]);
    }
    __syncthreads();

    int wl = wid >> 1, wc = wid & 1;
    uint32_t aoff = (uint32_t)((wl * 32 + (lane & 7) + ((lane >> 3) & 1) * 8) * 80 +
                               (lane >> 4) * 16);
    uint32_t boff = (uint32_t)((wc * 64 + (lane & 7) + ((lane >> 4) & 1) * 8) * 80 +
                               ((lane >> 3) & 1) * 16);
    uint32_t ah_b = smem_u32(QAh) + aoff, al_b = smem_u32(QAl) + aoff;
    uint32_t bh_b = smem_u32(KBh) + boff, bl_b = smem_u32(KBl) + boff;

    float acc[2][8][4];
#pragma unroll
    for (int i = 0; i < 2; i++)
#pragma unroll
        for (int n = 0; n < 8; n++)
#pragma unroll
            for (int q = 0; q < 4; q++) acc[i][n][q] = 0.f;

#pragma unroll
    for (int kc = 0; kc < 2; kc++) {
        uint ah[2][4], al2[2][4];
#pragma unroll
        for (int ln = 0; ln < 2; ln++) {
            ldsm4(ah_b + kc * 32 + ln * 16 * 80, ah[ln][0], ah[ln][1], ah[ln][2], ah[ln][3]);
            ldsm4(al_b + kc * 32 + ln * 16 * 80, al2[ln][0], al2[ln][1], al2[ln][2], al2[ln][3]);
        }
#pragma unroll
        for (int p = 0; p < 4; p++) {
            uint bh0, bh1, bh2, bh3, bl0, bl1, bl2, bl3;
            ldsm4(bh_b + kc * 32 + p * 16 * 80, bh0, bh1, bh2, bh3);
            ldsm4(bl_b + kc * 32 + p * 16 * 80, bl0, bl1, bl2, bl3);
#pragma unroll
            for (int ln = 0; ln < 2; ln++) {
                mma16816(acc[ln][2 * p], ah[ln][0], ah[ln][1], ah[ln][2], ah[ln][3], bh0, bh1);
                mma16816(acc[ln][2 * p], ah[ln][0], ah[ln][1], ah[ln][2], ah[ln][3], bl0, bl1);
                mma16816(acc[ln][2 * p], al2[ln][0], al2[ln][1], al2[ln][2], al2[ln][3], bh0, bh1);
                mma16816(acc[ln][2 * p + 1], ah[ln][0], ah[ln][1], ah[ln][2], ah[ln][3], bh2, bh3);
                mma16816(acc[ln][2 * p + 1], ah[ln][0], ah[ln][1], ah[ln][2], ah[ln][3], bl2, bl3);
                mma16816(acc[ln][2 * p + 1], al2[ln][0], al2[ln][1], al2[ln][2], al2[ln][3], bh2, bh3);
            }
        }
    }

    float* ob = g_attn + (size_t)b * Sn * Dn;
#pragma unroll
    for (int ln = 0; ln < 2; ln++) {
        int r0 = l0 + wl * 32 + ln * 16 + (lane >> 2);
#pragma unroll
        for (int n = 0; n < 8; n++) {
            int c = j0 + wc * 64 + n * 8 + (lane & 3) * 2;
            *(float2*)(ob + (size_t)r0 * Dn + c) = make_float2(acc[ln][n][0], acc[ln][n][1]);
            *(float2*)(ob + (size_t)(r0 + 8) * Dn + c) = make_float2(acc[ln][n][2], acc[ln][n][3]);
        }
    }
}

// ---------------------------------------------------------------------------
// statsexp: e = exp(a) (no max needed; |a| < ~45 safe in fp32), write e as
// bf16 hi/lo, accumulate column sums, g_crs = 1/sum.
// block (128,4): tx -> 2 columns, ty -> 1024-row chunk. grid (Dn/256, Bn)
// ---------------------------------------------------------------------------
__global__ void statsexp_k() {
    int b = blockIdx.y;
    int tx = threadIdx.x, ty = threadIdx.y;
    int j = blockIdx.x * 256 + tx * 2;
    size_t base = (size_t)b * Sn * Dn + (size_t)ty * 1024 * Dn + j;
    const float* col = g_attn + base;
    unsigned short* ah = g_ah + base;
    unsigned short* al = g_al + base;

    float s0 = 0.f, s1 = 0.f;
#pragma unroll 4
    for (int r = 0; r < 1024; r++) {
        float2 v = *(const float2*)(col + (size_t)r * Dn);
        float e0 = __expf(v.x), e1 = __expf(v.y);
        s0 += e0; s1 += e1;
        unsigned short h0, l0, h1, l1;
        split1(e0, h0, l0);
        split1(e1, h1, l1);
        *(uint*)(ah + (size_t)r * Dn) = (uint)h0 | ((uint)h1 << 16);
        *(uint*)(al + (size_t)r * Dn) = (uint)l0 | ((uint)l1 << 16);
    }

    __shared__ float ss[4][256];
    ss[ty][tx * 2] = s0;
    ss[ty][tx * 2 + 1] = s1;
    __syncthreads();
    if (ty == 0) {
#pragma unroll
        for (int tt = 1; tt < 4; tt++) {
            s0 += ss[tt][tx * 2];
            s1 += ss[tt][tx * 2 + 1];
        }
        g_crs[b * Dn + j] = 1.f / s0;
        g_crs[b * Dn + j + 1] = 1.f / s1;
    }
}

// ---------------------------------------------------------------------------
// vsplit: g_vh/g_vl = split-bf16( crs[j] * v[j][c] ).  2M elts.
// ---------------------------------------------------------------------------
__global__ void vsplit_k() {
    int idx = blockIdx.x * 256 + threadIdx.x;   // 262144 threads, 8 floats each
    int lin = idx * 8;
    int b = lin >> 17;                           // / (Dn*C2)
    int rem = lin & (Dn * C2 - 1);
    int j = rem >> 7;
    float rs = g_crs[b * Dn + j];
    const float* vp = g_v + (size_t)b * C2 * Dn + rem;
    float4 v0 = *(const float4*)(vp);
    float4 v1 = *(const float4*)(vp + 4);
    uint h[4], l[4];
    split2(v0.x * rs, v0.y * rs, h[0], l[0]);
    split2(v0.z * rs, v0.w * rs, h[1], l[1]);
    split2(v1.x * rs, v1.y * rs, h[2], l[2]);
    split2(v1.z * rs, v1.w * rs, h[3], l[3]);
    size_t o = (size_t)b * C2 * Dn + rem;
    *(uint4*)(g_vh + o) = make_uint4(h[0], h[1], h[2], h[3]);
    *(uint4*)(g_vl + o) = make_uint4(l[0], l[1], l[2], l[3]);
}

// ---------------------------------------------------------------------------
// applied GEMM, pure split-bf16 HMMA (loaders are plain copies):
//   app[128l x 128c] = sum_j e[l,j] * vn[j,c]   (e, vn pre-split bf16 hi/lo)
// 8 warps (4l x 2c), warp tile 32x64, K chunks of 16, dbl-buffered.
// grid (Sn/128, Bn)
// ---------------------------------------------------------------------------
__global__ __launch_bounds__(256) void applied_hmma_k() {
    __shared__ __align__(16) unsigned short Ah[2][128][24];
    __shared__ __align__(16) unsigned short Al[2][128][24];
    __shared__ __align__(16) unsigned short Bh[2][16][136];
    __shared__ __align__(16) unsigned short Bl[2][16][136];

    int t = threadIdx.x, lane = t & 31, wid = t >> 5;
    int b = blockIdx.y, l0 = blockIdx.x * 128;

    int arow = t >> 1, ak = (t & 1) * 8;
    const unsigned short* ahg = g_ah + (size_t)b * Sn * Dn + (size_t)(l0 + arow) * Dn + ak;
    const unsigned short* alg = g_al + (size_t)b * Sn * Dn + (size_t)(l0 + arow) * Dn + ak;
    int bj = t >> 4, bc = (t & 15) * 8;
    const unsigned short* bhg = g_vh + (size_t)b * C2 * Dn + (size_t)bj * C2 + bc;
    const unsigned short* blg = g_vl + (size_t)b * C2 * Dn + (size_t)bj * C2 + bc;

    int wl = wid >> 1, wc = wid & 1;
    uint32_t a_off = (uint32_t)((wl * 32 + (lane & 7) + ((lane >> 3) & 1) * 8) * 48 +
                                ((lane >> 4) * 8) * 2);
    uint32_t b_off = (uint32_t)(((lane & 7) + ((lane >> 3) & 1) * 8) * 272 +
                                (wc * 64 + (lane >> 4) * 8) * 2);

    float acc[2][8][4];
#pragma unroll
    for (int i = 0; i < 2; i++)
#pragma unroll
        for (int n = 0; n < 8; n++)
#pragma unroll
            for (int q = 0; q < 4; q++) acc[i][n][q] = 0.f;

    {
        *(uint4*)&Ah[0][arow][ak] = *(const uint4*)(ahg);
        *(uint4*)&Al[0][arow][ak] = *(const uint4*)(alg);
        *(uint4*)&Bh[0][bj][bc] = *(const uint4*)(bhg);
        *(uint4*)&Bl[0][bj][bc] = *(const uint4*)(blg);
    }
    __syncthreads();

    for (int ch = 0; ch < 64; ch++) {
        int buf = ch & 1;
        uint4 pah, pal, pbh, pbl;
        if (ch < 63) {
            pah = *(const uint4*)(ahg + (ch + 1) * 16);
            pal = *(const uint4*)(alg + (ch + 1) * 16);
            pbh = *(const uint4*)(bhg + (size_t)(ch + 1) * 16 * C2);
            pbl = *(const uint4*)(blg + (size_t)(ch + 1) * 16 * C2);
        }

        {
            uint32_t ah_base = smem_u32(&Ah[buf][0][0]) + a_off;
            uint32_t al_base = smem_u32(&Al[buf][0][0]) + a_off;
            uint32_t bh_base = smem_u32(&Bh[buf][0][0]) + b_off;
            uint32_t bl_base = smem_u32(&Bl[buf][0][0]) + b_off;

            uint ah[2][4], al2[2][4];
#pragma unroll
            for (int ln = 0; ln < 2; ln++) {
                ldsm4(ah_base + ln * 16 * 48, ah[ln][0], ah[ln][1], ah[ln][2], ah[ln][3]);
                ldsm4(al_base + ln * 16 * 48, al2[ln][0], al2[ln][1], al2[ln][2], al2[ln][3]);
            }
#pragma unroll
            for (int nn = 0; nn < 4; nn++) {
                uint bh0, bh1, bh2, bh3, bl0, bl1, bl2, bl3;
                ldsm4t(bh_base + nn * 32, bh0, bh1, bh2, bh3);
                ldsm4t(bl_base + nn * 32, bl0, bl1, bl2, bl3);
#pragma unroll
                for (int ln = 0; ln < 2; ln++) {
                    mma16816(acc[ln][2 * nn], ah[ln][0], ah[ln][1], ah[ln][2], ah[ln][3], bh0, bh1);
                    mma16816(acc[ln][2 * nn], ah[ln][0], ah[ln][1], ah[ln][2], ah[ln][3], bl0, bl1);
                    mma16816(acc[ln][2 * nn], al2[ln][0], al2[ln][1], al2[ln][2], al2[ln][3], bh0, bh1);
                    mma16816(acc[ln][2 * nn + 1], ah[ln][0], ah[ln][1], ah[ln][2], ah[ln][3], bh2, bh3);
                    mma16816(acc[ln][2 * nn + 1], ah[ln][0], ah[ln][1], ah[ln][2], ah[ln][3], bl2, bl3);
                    mma16816(acc[ln][2 * nn + 1], al2[ln][0], al2[ln][1], al2[ln][2], al2[ln][3], bh2, bh3);
                }
            }
        }

        if (ch < 63) {
            int nb = buf ^ 1;
            *(uint4*)&Ah[nb][arow][ak] = pah;
            *(uint4*)&Al[nb][arow][ak] = pal;
            *(uint4*)&Bh[nb][bj][bc] = pbh;
            *(uint4*)&Bl[nb][bj][bc] = pbl;
        }
        __syncthreads();
    }

    float* ob = g_app + (size_t)b * Sn * C2;
#pragma unroll
    for (int ln = 0; ln < 2; ln++) {
        int r0 = l0 + wl * 32 + ln * 16 + (lane >> 2);
#pragma unroll
        for (int n = 0; n < 8; n++) {
            int c = wc * 64 + n * 8 + (lane & 3) * 2;
            *(float2*)(ob + (size_t)r0 * C2 + c) = make_float2(acc[ln][n][0], acc[ln][n][1]);
            *(float2*)(ob + (size_t)(r0 + 8) * C2 + c) = make_float2(acc[ln][n][2], acc[ln][n][3]);
        }
    }
}

// ---------------------------------------------------------------------------
// output conv + residual via split-bf16 HMMA:
//   out[128o x 128sp] = gamma*(W2 x appflat + b2) + x
// Same structure as applied; A=w2 (split on load), B=g_app flat (split on load).
// grid (Sn/128, Cc/128, Bn)
// ---------------------------------------------------------------------------
__global__ __launch_bounds__(256) void out_conv_hmma_k(
    const float* __restrict__ x, const float* __restrict__ w2,
    const float* __restrict__ b2, const float* __restrict__ gamma,
    float* __restrict__ out) {
    __shared__ __align__(16) unsigned short Ah[2][128][24];
    __shared__ __align__(16) unsigned short Al[2][128][24];
    __shared__ __align__(16) unsigned short Bh[2][16][136];
    __shared__ __align__(16) unsigned short Bl[2][16][136];

    int t = threadIdx.x, lane = t & 31, wid = t >> 5;
    int b = blockIdx.z, o0 = blockIdx.y * 128, sp0 = blockIdx.x * 128;

    int arow = t >> 1, ak = (t & 1) * 8;
    const float* wsrc = w2 + (size_t)(o0 + arow) * C2 + ak;
    int bkk = t >> 4, bsg = (t & 15) * 8;
    const float* asrc = g_app + (size_t)b * Sn * C2 + (size_t)bkk * Sn + sp0 + bsg;

    int wl = wid >> 1, wc = wid & 1;
    uint32_t a_off = (uint32_t)((wl * 32 + (lane & 7) + ((lane >> 3) & 1) * 8) * 48 +
                                ((lane >> 4) * 8) * 2);
    uint32_t b_off = (uint32_t)(((lane & 7) + ((lane >> 3) & 1) * 8) * 272 +
                                (wc * 64 + (lane >> 4) * 8) * 2);

    float acc[2][8][4];
#pragma unroll
    for (int i = 0; i < 2; i++)
#pragma unroll
        for (int n = 0; n < 8; n++)
#pragma unroll
            for (int q = 0; q < 4; q++) acc[i][n][q] = 0.f;

    {
        float4 w0 = *(const float4*)(wsrc);
        float4 w1 = *(const float4*)(wsrc + 4);
        uint h[4], l[4];
        split2(w0.x, w0.y, h[0], l[0]);
        split2(w0.z, w0.w, h[1], l[1]);
        split2(w1.x, w1.y, h[2], l[2]);
        split2(w1.z, w1.w, h[3], l[3]);
        *(uint4*)&Ah[0][arow][ak] = make_uint4(h[0], h[1], h[2], h[3]);
        *(uint4*)&Al[0][arow][ak] = make_uint4(l[0], l[1], l[2], l[3]);
        float4 a0 = *(const float4*)(asrc);
        float4 a1 = *(const float4*)(asrc + 4);
        split2(a0.x, a0.y, h[0], l[0]);
        split2(a0.z, a0.w, h[1], l[1]);
        split2(a1.x, a1.y, h[2], l[2]);
        split2(a1.z, a1.w, h[3], l[3]);
        *(uint4*)&Bh[0][bkk][bsg] = make_uint4(h[0], h[1], h[2], h[3]);
        *(uint4*)&Bl[0][bkk][bsg] = make_uint4(l[0], l[1], l[2], l[3]);
    }
    __syncthreads();

    for (int ch = 0; ch < 8; ch++) {
        int buf = ch & 1;
        float4 w0, w1, a0, a1;
        if (ch < 7) {
            w0 = *(const float4*)(wsrc + (ch + 1) * 16);
            w1 = *(const float4*)(wsrc + (ch + 1) * 16 + 4);
            const float* ap = asrc + (size_t)(ch + 1) * 16 * Sn;
            a0 = *(const float4*)(ap);
            a1 = *(const float4*)(ap + 4);
        }

        {
            uint32_t ah_base = smem_u32(&Ah[buf][0][0]) + a_off;
            uint32_t al_base = smem_u32(&Al[buf][0][0]) + a_off;
            uint32_t bh_base = smem_u32(&Bh[buf][0][0]) + b_off;
            uint32_t bl_base = smem_u32(&Bl[buf][0][0]) + b_off;

            uint ah[2][4], al2[2][4];
#pragma unroll
            for (int ln = 0; ln < 2; ln++) {
                ldsm4(ah_base + ln * 16 * 48, ah[ln][0], ah[ln][1], ah[ln][2], ah[ln][3]);
                ldsm4(al_base + ln * 16 * 48, al2[ln][0], al2[ln][1], al2[ln][2], al2[ln][3]);
            }
#pragma unroll
            for (int nn = 0; nn < 4; nn++) {
                uint bh0, bh1, bh2, bh3, bl0, bl1, bl2, bl3;
                ldsm4t(bh_base + nn * 32, bh0, bh1, bh2, bh3);
                ldsm4t(bl_base + nn * 32, bl0, bl1, bl2, bl3);
#pragma unroll
                for (int ln = 0; ln < 2; ln++) {
                    mma16816(acc[ln][2 * nn], ah[ln][0], ah[ln][1], ah[ln][2], ah[ln][3], bh0, bh1);
                    mma16816(acc[ln][2 * nn], ah[ln][0], ah[ln][1], ah[ln][2], ah[ln][3], bl0, bl1);
                    mma16816(acc[ln][2 * nn], al2[ln][0], al2[ln][1], al2[ln][2], al2[ln][3], bh0, bh1);
                    mma16816(acc[ln][2 * nn + 1], ah[ln][0], ah[ln][1], ah[ln][2], ah[ln][3], bh2, bh3);
                    mma16816(acc[ln][2 * nn + 1], ah[ln][0], ah[ln][1], ah[ln][2], ah[ln][3], bl2, bl3);
                    mma16816(acc[ln][2 * nn + 1], al2[ln][0], al2[ln][1], al2[ln][2], al2[ln][3], bh2, bh3);
                }
            }
        }

        if (ch < 7) {
            int nb = buf ^ 1;
            uint h[4], l[4];
            split2(w0.x, w0.y, h[0], l[0]);
            split2(w0.z, w0.w, h[1], l[1]);
            split2(w1.x, w1.y, h[2], l[2]);
            split2(w1.z, w1.w, h[3], l[3]);
            *(uint4*)&Ah[nb][arow][ak] = make_uint4(h[0], h[1], h[2], h[3]);
            *(uint4*)&Al[nb][arow][ak] = make_uint4(l[0], l[1], l[2], l[3]);
            split2(a0.x, a0.y, h[0], l[0]);
            split2(a0.z, a0.w, h[1], l[1]);
            split2(a1.x, a1.y, h[2], l[2]);
            split2(a1.z, a1.w, h[3], l[3]);
            *(uint4*)&Bh[nb][bkk][bsg] = make_uint4(h[0], h[1], h[2], h[3]);
            *(uint4*)&Bl[nb][bkk][bsg] = make_uint4(l[0], l[1], l[2], l[3]);
        }
        __syncthreads();
    }

    float g = gamma[0];
#pragma unroll
    for (int ln = 0; ln < 2; ln++) {
        int o1 = o0 + wl * 32 + ln * 16 + (lane >> 2);
        int o2 = o1 + 8;
        float bb1 = b2[o1], bb2 = b2[o2];
#pragma unroll
        for (int n = 0; n < 8; n++) {
            int sp = sp0 + wc * 64 + n * 8 + (lane & 3) * 2;
            const float* x1 = x + (size_t)b * Cc * Sn + (size_t)o1 * Sn + sp;
            const float* x2 = x + (size_t)b * Cc * Sn + (size_t)o2 * Sn + sp;
            float* y1 = out + (size_t)b * Cc * Sn + (size_t)o1 * Sn + sp;
            float* y2 = out + (size_t)b * Cc * Sn + (size_t)o2 * Sn + sp;
            float2 xa = *(const float2*)(x1);
            float2 xb = *(const float2*)(x2);
            float2 r1, r2;
            r1.x = fmaf(g, acc[ln][n][0] + bb1, xa.x);
            r1.y = fmaf(g, acc[ln][n][1] + bb1, xa.y);
            r2.x = fmaf(g, acc[ln][n][2] + bb2, xb.x);
            r2.y = fmaf(g, acc[ln][n][3] + bb2, xb.y);
            *(float2*)(y1) = r1;
            *(float2*)(y2) = r2;
        }
    }
}

// ---------------------------------------------------------------------------
extern "C" void kernel_launch(void* const* d_in, const int* in_sizes, int n_in,
                              void* d_out, int out_size) {
    const float* x   = (const float*)d_in[0];
    const float* qw  = (const float*)d_in[1];
    const float* qb  = (const float*)d_in[2];
    const float* kw  = (const float*)d_in[3];
    const float* kb  = (const float*)d_in[4];
    const float* vw  = (const float*)d_in[5];
    const float* vb  = (const float*)d_in[6];
    const float* v2w = (const float*)d_in[7];
    const float* v2b = (const float*)d_in[8];
    const float* gm  = (const float*)d_in[9];
    float* out = (float*)d_out;

    conv_all_k<<<dim3(32, 3, Bn), 128>>>(x, qw, qb, kw, kb, vw, vb);
    attn_hmma_k<<<dim3(Dn / 128, Sn / 128, Bn), 256>>>();
    statsexp_k<<<dim3(Dn / 256, Bn), dim3(128, 4)>>>();
    vsplit_k<<<(Bn * C2 * Dn / 8) / 256, 256>>>();
    applied_hmma_k<<<dim3(Sn / 128, Bn), 256>>>();
    out_conv_hmma_k<<<dim3(Sn / 128, Cc / 128, Bn), 256>>>(x, v2w, v2b, gm, out);
}

// round 8
// speedup vs baseline: 1.7951x; 1.7951x over previous
#include <cuda_runtime.h>
#include <cuda_bf16.h>
#include <cstdint>

#define Bn 16
#define Cc 256
#define Sn 4096   // H*W
#define C8 32     // C/8
#define C2 128    // C/2
#define Dn 1024   // down = HW/4

typedef unsigned long long ull;
typedef unsigned int uint;

// ---- packed fp32x2 helpers ----
__device__ __forceinline__ ull ffma2(ull a, ull b, ull c) {
    ull d;
    asm("fma.rn.f32x2 %0, %1, %2, %3;" : "=l"(d) : "l"(a), "l"(b), "l"(c));
    return d;
}
__device__ __forceinline__ ull dup2(float v) {
    ull d;
    asm("mov.b64 %0, {%1, %1};" : "=l"(d) : "f"(v));
    return d;
}

// ---- mma/ldmatrix helpers ----
__device__ __forceinline__ uint32_t smem_u32(const void* p) {
    uint32_t a;
    asm("{ .reg .u64 t; cvta.to.shared.u64 t, %1; cvt.u32.u64 %0, t; }" : "=r"(a) : "l"(p));
    return a;
}
__device__ __forceinline__ void ldsm4(uint32_t a, uint& r0, uint& r1, uint& r2, uint& r3) {
    asm volatile("ldmatrix.sync.aligned.m8n8.x4.shared.b16 {%0,%1,%2,%3}, [%4];"
                 : "=r"(r0), "=r"(r1), "=r"(r2), "=r"(r3) : "r"(a));
}
__device__ __forceinline__ void ldsm4t(uint32_t a, uint& r0, uint& r1, uint& r2, uint& r3) {
    asm volatile("ldmatrix.sync.aligned.m8n8.x4.trans.shared.b16 {%0,%1,%2,%3}, [%4];"
                 : "=r"(r0), "=r"(r1), "=r"(r2), "=r"(r3) : "r"(a));
}
__device__ __forceinline__ void mma16816(float* d, uint a0, uint a1, uint a2, uint a3,
                                         uint b0, uint b1) {
    asm volatile(
        "mma.sync.aligned.m16n8k16.row.col.f32.bf16.bf16.f32 "
        "{%0,%1,%2,%3}, {%4,%5,%6,%7}, {%8,%9}, {%0,%1,%2,%3};"
        : "+f"(d[0]), "+f"(d[1]), "+f"(d[2]), "+f"(d[3])
        : "r"(a0), "r"(a1), "r"(a2), "r"(a3), "r"(b0), "r"(b1));
}

// split fp32 pair -> packed bf16 hi-pair / lo-pair
__device__ __forceinline__ void split2(float x, float y, uint& hi, uint& lo) {
    __nv_bfloat16 hx = __float2bfloat16_rn(x), hy = __float2bfloat16_rn(y);
    float rx = x - __bfloat162float(hx), ry = y - __bfloat162float(hy);
    __nv_bfloat16 lx = __float2bfloat16_rn(rx), ly = __float2bfloat16_rn(ry);
    __nv_bfloat162 hp, lp;
    hp.x = hx; hp.y = hy; lp.x = lx; lp.y = ly;
    hi = *(uint*)&hp;
    lo = *(uint*)&lp;
}

// ---- scratch ----
__device__ float g_q[(size_t)Bn * C8 * Sn];
__device__ float g_k[(size_t)Bn * C8 * Dn];
__device__ float g_v[(size_t)Bn * C2 * Dn];
__device__ float g_attn[(size_t)Bn * Sn * Dn];  // fp32 logits
__device__ float g_crs[Bn * Dn];                // 1 / sum_l exp(attn[l,j])
__device__ float g_app[(size_t)Bn * Sn * C2];

// ---------------------------------------------------------------------------
// Fused conv: q / k-pooled / v-pooled (unchanged, known-good)
// ---------------------------------------------------------------------------
__global__ __launch_bounds__(128) void conv_all_k(
    const float* __restrict__ x,
    const float* __restrict__ qw, const float* __restrict__ qb,
    const float* __restrict__ kw, const float* __restrict__ kb,
    const float* __restrict__ vw, const float* __restrict__ vb) {
    int b = blockIdx.z, ot = blockIdx.y, st = blockIdx.x;
    int s0 = st * 128;
    int t = threadIdx.x;

    __shared__ __align__(16) union {
        struct { float Ws[2][16][68]; float Xs[2][16][128]; } p;
        float Cs[64][128];
    } sm;

    int wrow = t >> 1;
    int wkg = (t & 1) << 3;
    int gch = ot * 64 + wrow;
    const float* wsrc;
    if (gch < 32) wsrc = qw + (size_t)gch * Cc;
    else if (gch < 64) wsrc = kw + (size_t)(gch - 32) * Cc;
    else wsrc = vw + (size_t)(gch - 64) * Cc;
    wsrc += wkg;

    int xkk = t >> 3;
    int xsg = (t & 7) << 4;
    const float* xsrc = x + (size_t)b * Cc * Sn + (size_t)xkk * Sn + s0 + xsg;

    int ty = t >> 4, tx = t & 15;

    ull acc[8][4];
#pragma unroll
    for (int i = 0; i < 8; i++)
#pragma unroll
        for (int j = 0; j < 4; j++) acc[i][j] = 0ULL;

    {
#pragma unroll
        for (int u = 0; u < 2; u++) {
            float4 v = *(const float4*)(wsrc + u * 4);
            sm.p.Ws[0][wkg + u * 4 + 0][wrow] = v.x;
            sm.p.Ws[0][wkg + u * 4 + 1][wrow] = v.y;
            sm.p.Ws[0][wkg + u * 4 + 2][wrow] = v.z;
            sm.p.Ws[0][wkg + u * 4 + 3][wrow] = v.w;
        }
#pragma unroll
        for (int u = 0; u < 4; u++)
            *(float4*)&sm.p.Xs[0][xkk][xsg + u * 4] = *(const float4*)(xsrc + u * 4);
    }
    __syncthreads();

    for (int ch = 0; ch < 16; ch++) {
        int cb = ch & 1;
        float4 wpre[2], xpre[4];
        if (ch < 15) {
            const float* wp = wsrc + (ch + 1) * 16;
            wpre[0] = *(const float4*)(wp);
            wpre[1] = *(const float4*)(wp + 4);
            const float* xp = xsrc + (size_t)(ch + 1) * 16 * Sn;
#pragma unroll
            for (int u = 0; u < 4; u++) xpre[u] = *(const float4*)(xp + u * 4);
        }
#pragma unroll
        for (int kk = 0; kk < 16; kk++) {
            float4 a0 = *(const float4*)&sm.p.Ws[cb][kk][ty * 8];
            float4 a1 = *(const float4*)&sm.p.Ws[cb][kk][ty * 8 + 4];
            ulonglong2 b0 = *(const ulonglong2*)&sm.p.Xs[cb][kk][tx * 8];
            ulonglong2 b1 = *(const ulonglong2*)&sm.p.Xs[cb][kk][tx * 8 + 4];
            ull bp[4] = {b0.x, b0.y, b1.x, b1.y};
            float aa[8] = {a0.x, a0.y, a0.z, a0.w, a1.x, a1.y, a1.z, a1.w};
#pragma unroll
            for (int i = 0; i < 8; i++) {
                ull ad = dup2(aa[i]);
#pragma unroll
                for (int j = 0; j < 4; j++) acc[i][j] = ffma2(ad, bp[j], acc[i][j]);
            }
        }
        if (ch < 15) {
            int nb = cb ^ 1;
#pragma unroll
            for (int u = 0; u < 2; u++) {
                sm.p.Ws[nb][wkg + u * 4 + 0][wrow] = (&wpre[u].x)[0];
                sm.p.Ws[nb][wkg + u * 4 + 1][wrow] = (&wpre[u].x)[1];
                sm.p.Ws[nb][wkg + u * 4 + 2][wrow] = (&wpre[u].x)[2];
                sm.p.Ws[nb][wkg + u * 4 + 3][wrow] = (&wpre[u].x)[3];
            }
#pragma unroll
            for (int u = 0; u < 4; u++)
                *(float4*)&sm.p.Xs[nb][xkk][xsg + u * 4] = xpre[u];
        }
        __syncthreads();
    }

#pragma unroll
    for (int i = 0; i < 8; i++) {
        ulonglong2 u0, u1;
        u0.x = acc[i][0]; u0.y = acc[i][1];
        u1.x = acc[i][2]; u1.y = acc[i][3];
        *(ulonglong2*)&sm.Cs[ty * 8 + i][tx * 8] = u0;
        *(ulonglong2*)&sm.Cs[ty * 8 + i][tx * 8 + 4] = u1;
    }
    __syncthreads();

    if (ot == 0) {
#pragma unroll
        for (int i = 0; i < 8; i++) {
            int o = i * 4 + (t >> 5);
            int sp = (t & 31) * 4;
            float4 v = *(const float4*)&sm.Cs[o][sp];
            float bb = qb[o];
            v.x += bb; v.y += bb; v.z += bb; v.w += bb;
            *(float4*)(g_q + (size_t)b * C8 * Sn + (size_t)o * Sn + s0 + sp) = v;
        }
        {
            int o = 32 + (t >> 2);
            int qcb = (t & 3) * 8;
            float bb = kb[o - 32];
            float* dst = g_k + (size_t)b * C8 * Dn + (size_t)(o - 32) * Dn + st * 32;
#pragma unroll
            for (int jj = 0; jj < 8; jj++) {
                int qc = qcb + jj;
                float m = fmaxf(fmaxf(sm.Cs[o][2 * qc], sm.Cs[o][2 * qc + 1]),
                                fmaxf(sm.Cs[o][64 + 2 * qc], sm.Cs[o][64 + 2 * qc + 1]));
                dst[qc] = m + bb;
            }
        }
    } else {
        int vg0 = (ot - 1) * 64;
        int o = t >> 1;
        int qcb = (t & 1) * 16;
        float bb = vb[vg0 + o];
        float* dst = g_v + (size_t)b * C2 * Dn + (size_t)(vg0 + o) * Dn + st * 32;
#pragma unroll
        for (int jj = 0; jj < 16; jj++) {
            int qc = qcb + jj;
            float m = fmaxf(fmaxf(sm.Cs[o][2 * qc], sm.Cs[o][2 * qc + 1]),
                            fmaxf(sm.Cs[o][64 + 2 * qc], sm.Cs[o][64 + 2 * qc + 1]));
            dst[qc] = m + bb;
        }
    }
}

// ---------------------------------------------------------------------------
// attn logits via split-bf16 HMMA (proven in R6):
// attn[l,j] = dot(q[l][0:32], k[j][0:32]); tile 128x128, K=32 one-shot.
// grid (Dn/128, Sn/128, Bn)
// ---------------------------------------------------------------------------
__global__ __launch_bounds__(256) void attn_hmma_k() {
    __shared__ __align__(16) unsigned short QAh[128][40], QAl[128][40];  // 80B rows
    __shared__ __align__(16) unsigned short KBh[128][40], KBl[128][40];

    int t = threadIdx.x, lane = t & 31, wid = t >> 5;
    int b = blockIdx.z, l0 = blockIdx.y * 128, j0 = blockIdx.x * 128;

    {
        int row = t >> 1, fs = (t & 1) * 16;
        const float* qp = g_q + (size_t)b * C8 * Sn + (size_t)(l0 + row) * 32 + fs;
        const float* kp = g_k + (size_t)b * C8 * Dn + (size_t)(j0 + row) * 32 + fs;
        uint h[8], l[8];
#pragma unroll
        for (int u = 0; u < 4; u++) {
            float4 v = *(const float4*)(qp + u * 4);
            split2(v.x, v.y, h[2 * u], l[2 * u]);
            split2(v.z, v.w, h[2 * u + 1], l[2 * u + 1]);
        }
        *(uint4*)&QAh[row][fs] = make_uint4(h[0], h[1], h[2], h[3]);
        *(uint4*)&QAh[row][fs + 8] = make_uint4(h[4], h[5], h[6], h[7]);
        *(uint4*)&QAl[row][fs] = make_uint4(l[0], l[1], l[2], l[3]);
        *(uint4*)&QAl[row][fs + 8] = make_uint4(l[4], l[5], l[6], l[7]);
#pragma unroll
        for (int u = 0; u < 4; u++) {
            float4 v = *(const float4*)(kp + u * 4);
            split2(v.x, v.y, h[2 * u], l[2 * u]);
            split2(v.z, v.w, h[2 * u + 1], l[2 * u + 1]);
        }
        *(uint4*)&KBh[row][fs] = make_uint4(h[0], h[1], h[2], h[3]);
        *(uint4*)&KBh[row][fs + 8] = make_uint4(h[4], h[5], h[6], h[7]);
        *(uint4*)&KBl[row][fs] = make_uint4(l[0], l[1], l[2], l[3]);
        *(uint4*)&KBl[row][fs + 8] = make_uint4(l[4], l[5], l[6], l[7]);
    }
    __syncthreads();

    int wl = wid >> 1, wc = wid & 1;
    uint32_t aoff = (uint32_t)((wl * 32 + (lane & 7) + ((lane >> 3) & 1) * 8) * 80 +
                               (lane >> 4) * 16);
    uint32_t boff = (uint32_t)((wc * 64 + (lane & 7) + ((lane >> 4) & 1) * 8) * 80 +
                               ((lane >> 3) & 1) * 16);
    uint32_t ah_b = smem_u32(QAh) + aoff, al_b = smem_u32(QAl) + aoff;
    uint32_t bh_b = smem_u32(KBh) + boff, bl_b = smem_u32(KBl) + boff;

    float acc[2][8][4];
#pragma unroll
    for (int i = 0; i < 2; i++)
#pragma unroll
        for (int n = 0; n < 8; n++)
#pragma unroll
            for (int q = 0; q < 4; q++) acc[i][n][q] = 0.f;

#pragma unroll
    for (int kc = 0; kc < 2; kc++) {
        uint ah[2][4], al2[2][4];
#pragma unroll
        for (int ln = 0; ln < 2; ln++) {
            ldsm4(ah_b + kc * 32 + ln * 16 * 80, ah[ln][0], ah[ln][1], ah[ln][2], ah[ln][3]);
            ldsm4(al_b + kc * 32 + ln * 16 * 80, al2[ln][0], al2[ln][1], al2[ln][2], al2[ln][3]);
        }
#pragma unroll
        for (int p = 0; p < 4; p++) {
            uint bh0, bh1, bh2, bh3, bl0, bl1, bl2, bl3;
            ldsm4(bh_b + kc * 32 + p * 16 * 80, bh0, bh1, bh2, bh3);
            ldsm4(bl_b + kc * 32 + p * 16 * 80, bl0, bl1, bl2, bl3);
#pragma unroll
            for (int ln = 0; ln < 2; ln++) {
                mma16816(acc[ln][2 * p], ah[ln][0], ah[ln][1], ah[ln][2], ah[ln][3], bh0, bh1);
                mma16816(acc[ln][2 * p], ah[ln][0], ah[ln][1], ah[ln][2], ah[ln][3], bl0, bl1);
                mma16816(acc[ln][2 * p], al2[ln][0], al2[ln][1], al2[ln][2], al2[ln][3], bh0, bh1);
                mma16816(acc[ln][2 * p + 1], ah[ln][0], ah[ln][1], ah[ln][2], ah[ln][3], bh2, bh3);
                mma16816(acc[ln][2 * p + 1], ah[ln][0], ah[ln][1], ah[ln][2], ah[ln][3], bl2, bl3);
                mma16816(acc[ln][2 * p + 1], al2[ln][0], al2[ln][1], al2[ln][2], al2[ln][3], bh2, bh3);
            }
        }
    }

    float* ob = g_attn + (size_t)b * Sn * Dn;
#pragma unroll
    for (int ln = 0; ln < 2; ln++) {
        int r0 = l0 + wl * 32 + ln * 16 + (lane >> 2);
#pragma unroll
        for (int n = 0; n < 8; n++) {
            int c = j0 + wc * 64 + n * 8 + (lane & 3) * 2;
            *(float2*)(ob + (size_t)r0 * Dn + c) = make_float2(acc[ln][n][0], acc[ln][n][1]);
            *(float2*)(ob + (size_t)(r0 + 8) * Dn + c) = make_float2(acc[ln][n][2], acc[ln][n][3]);
        }
    }
}

// ---------------------------------------------------------------------------
// Column sum of exp (no max subtraction; |logit| < ~45 is fp32-safe).
// grid (Dn/64, Bn) = 256 CTAs, block (64,16) = 1024 thr, 256 rows/thread.
// ---------------------------------------------------------------------------
__global__ void stats_k() {
    int b = blockIdx.y;
    int tx = threadIdx.x, ty = threadIdx.y;
    int j = blockIdx.x * 64 + tx;
    const float* col = g_attn + (size_t)b * Sn * Dn + (size_t)ty * 256 * Dn + j;

    float s = 0.f;
#pragma unroll 4
    for (int r = 0; r < 256; r++) s += __expf(col[(size_t)r * Dn]);

    __shared__ float ss[16][64];
    ss[ty][tx] = s;
    __syncthreads();
    if (ty == 0) {
#pragma unroll
        for (int tt = 1; tt < 16; tt++) s += ss[tt][tx];
        g_crs[b * Dn + j] = 1.f / s;
    }
}

// ---------------------------------------------------------------------------
// applied GEMM via split-bf16 HMMA (R5-proven structure; exp fused, no cmax):
//   app[128l x 128c] = sum_j exp(attn[l,j]) * (crs[j]*v[j,c])
// grid (Sn/128, Bn)
// ---------------------------------------------------------------------------
__global__ __launch_bounds__(256) void applied_hmma_k() {
    __shared__ __align__(16) unsigned short Ah[2][128][24];
    __shared__ __align__(16) unsigned short Al[2][128][24];
    __shared__ __align__(16) unsigned short Bh[2][16][136];
    __shared__ __align__(16) unsigned short Bl[2][16][136];

    int t = threadIdx.x, lane = t & 31, wid = t >> 5;
    int b = blockIdx.y, l0 = blockIdx.x * 128;

    int arow = t >> 1, ak = (t & 1) * 8;
    const float* abase = g_attn + (size_t)b * Sn * Dn + (size_t)(l0 + arow) * Dn + ak;
    int bj = t >> 4, bc = (t & 15) * 8;
    const float* vbase = g_v + (size_t)b * C2 * Dn;
    const float* crb = g_crs + b * Dn;

    int wl = wid >> 1, wc = wid & 1;
    uint32_t a_off = (uint32_t)((wl * 32 + (lane & 7) + ((lane >> 3) & 1) * 8) * 48 +
                                ((lane >> 4) * 8) * 2);
    uint32_t b_off = (uint32_t)(((lane & 7) + ((lane >> 3) & 1) * 8) * 272 +
                                (wc * 64 + (lane >> 4) * 8) * 2);

    float acc[2][8][4];
#pragma unroll
    for (int i = 0; i < 2; i++)
#pragma unroll
        for (int n = 0; n < 8; n++)
#pragma unroll
            for (int q = 0; q < 4; q++) acc[i][n][q] = 0.f;

    {
        float4 av0 = *(const float4*)(abase);
        float4 av1 = *(const float4*)(abase + 4);
        float p[8] = {__expf(av0.x), __expf(av0.y), __expf(av0.z), __expf(av0.w),
                      __expf(av1.x), __expf(av1.y), __expf(av1.z), __expf(av1.w)};
        uint h[4], l[4];
#pragma unroll
        for (int i = 0; i < 4; i++) split2(p[2 * i], p[2 * i + 1], h[i], l[i]);
        *(uint4*)&Ah[0][arow][ak] = make_uint4(h[0], h[1], h[2], h[3]);
        *(uint4*)&Al[0][arow][ak] = make_uint4(l[0], l[1], l[2], l[3]);

        float sc = crb[bj];
        const float* vp = vbase + (size_t)bj * C2 + bc;
        float4 bv0 = *(const float4*)(vp);
        float4 bv1 = *(const float4*)(vp + 4);
        float q[8] = {bv0.x * sc, bv0.y * sc, bv0.z * sc, bv0.w * sc,
                      bv1.x * sc, bv1.y * sc, bv1.z * sc, bv1.w * sc};
#pragma unroll
        for (int i = 0; i < 4; i++) split2(q[2 * i], q[2 * i + 1], h[i], l[i]);
        *(uint4*)&Bh[0][bj][bc] = make_uint4(h[0], h[1], h[2], h[3]);
        *(uint4*)&Bl[0][bj][bc] = make_uint4(l[0], l[1], l[2], l[3]);
    }
    __syncthreads();

    for (int ch = 0; ch < 64; ch++) {
        int buf = ch & 1;
        float pa[8], qb2[8];
        if (ch < 63) {
            const float* ap = abase + (ch + 1) * 16;
            float4 av0 = *(const float4*)(ap);
            float4 av1 = *(const float4*)(ap + 4);
            pa[0] = __expf(av0.x); pa[1] = __expf(av0.y);
            pa[2] = __expf(av0.z); pa[3] = __expf(av0.w);
            pa[4] = __expf(av1.x); pa[5] = __expf(av1.y);
            pa[6] = __expf(av1.z); pa[7] = __expf(av1.w);
            int j = (ch + 1) * 16 + bj;
            float sc = crb[j];
            const float* vp = vbase + (size_t)j * C2 + bc;
            float4 bv0 = *(const float4*)(vp);
            float4 bv1 = *(const float4*)(vp + 4);
            qb2[0] = bv0.x * sc; qb2[1] = bv0.y * sc; qb2[2] = bv0.z * sc; qb2[3] = bv0.w * sc;
            qb2[4] = bv1.x * sc; qb2[5] = bv1.y * sc; qb2[6] = bv1.z * sc; qb2[7] = bv1.w * sc;
        }

        {
            uint32_t ah_base = smem_u32(&Ah[buf][0][0]) + a_off;
            uint32_t al_base = smem_u32(&Al[buf][0][0]) + a_off;
            uint32_t bh_base = smem_u32(&Bh[buf][0][0]) + b_off;
            uint32_t bl_base = smem_u32(&Bl[buf][0][0]) + b_off;

            uint ah[2][4], al2[2][4];
#pragma unroll
            for (int ln = 0; ln < 2; ln++) {
                ldsm4(ah_base + ln * 16 * 48, ah[ln][0], ah[ln][1], ah[ln][2], ah[ln][3]);
                ldsm4(al_base + ln * 16 * 48, al2[ln][0], al2[ln][1], al2[ln][2], al2[ln][3]);
            }
#pragma unroll
            for (int nn = 0; nn < 4; nn++) {
                uint bh0, bh1, bh2, bh3, bl0, bl1, bl2, bl3;
                ldsm4t(bh_base + nn * 32, bh0, bh1, bh2, bh3);
                ldsm4t(bl_base + nn * 32, bl0, bl1, bl2, bl3);
#pragma unroll
                for (int ln = 0; ln < 2; ln++) {
                    mma16816(acc[ln][2 * nn], ah[ln][0], ah[ln][1], ah[ln][2], ah[ln][3], bh0, bh1);
                    mma16816(acc[ln][2 * nn], ah[ln][0], ah[ln][1], ah[ln][2], ah[ln][3], bl0, bl1);
                    mma16816(acc[ln][2 * nn], al2[ln][0], al2[ln][1], al2[ln][2], al2[ln][3], bh0, bh1);
                    mma16816(acc[ln][2 * nn + 1], ah[ln][0], ah[ln][1], ah[ln][2], ah[ln][3], bh2, bh3);
                    mma16816(acc[ln][2 * nn + 1], ah[ln][0], ah[ln][1], ah[ln][2], ah[ln][3], bl2, bl3);
                    mma16816(acc[ln][2 * nn + 1], al2[ln][0], al2[ln][1], al2[ln][2], al2[ln][3], bh2, bh3);
                }
            }
        }

        if (ch < 63) {
            int nb = buf ^ 1;
            uint h[4], l[4];
#pragma unroll
            for (int i = 0; i < 4; i++) split2(pa[2 * i], pa[2 * i + 1], h[i], l[i]);
            *(uint4*)&Ah[nb][arow][ak] = make_uint4(h[0], h[1], h[2], h[3]);
            *(uint4*)&Al[nb][arow][ak] = make_uint4(l[0], l[1], l[2], l[3]);
#pragma unroll
            for (int i = 0; i < 4; i++) split2(qb2[2 * i], qb2[2 * i + 1], h[i], l[i]);
            *(uint4*)&Bh[nb][bj][bc] = make_uint4(h[0], h[1], h[2], h[3]);
            *(uint4*)&Bl[nb][bj][bc] = make_uint4(l[0], l[1], l[2], l[3]);
        }
        __syncthreads();
    }

    float* ob = g_app + (size_t)b * Sn * C2;
#pragma unroll
    for (int ln = 0; ln < 2; ln++) {
        int r0 = l0 + wl * 32 + ln * 16 + (lane >> 2);
#pragma unroll
        for (int n = 0; n < 8; n++) {
            int c = wc * 64 + n * 8 + (lane & 3) * 2;
            *(float2*)(ob + (size_t)r0 * C2 + c) = make_float2(acc[ln][n][0], acc[ln][n][1]);
            *(float2*)(ob + (size_t)(r0 + 8) * C2 + c) = make_float2(acc[ln][n][2], acc[ln][n][3]);
        }
    }
}

// ---------------------------------------------------------------------------
// output conv + residual via split-bf16 HMMA (proven in R6)
// grid (Sn/128, Cc/128, Bn)
// ---------------------------------------------------------------------------
__global__ __launch_bounds__(256) void out_conv_hmma_k(
    const float* __restrict__ x, const float* __restrict__ w2,
    const float* __restrict__ b2, const float* __restrict__ gamma,
    float* __restrict__ out) {
    __shared__ __align__(16) unsigned short Ah[2][128][24];
    __shared__ __align__(16) unsigned short Al[2][128][24];
    __shared__ __align__(16) unsigned short Bh[2][16][136];
    __shared__ __align__(16) unsigned short Bl[2][16][136];

    int t = threadIdx.x, lane = t & 31, wid = t >> 5;
    int b = blockIdx.z, o0 = blockIdx.y * 128, sp0 = blockIdx.x * 128;

    int arow = t >> 1, ak = (t & 1) * 8;
    const float* wsrc = w2 + (size_t)(o0 + arow) * C2 + ak;
    int bkk = t >> 4, bsg = (t & 15) * 8;
    const float* asrc = g_app + (size_t)b * Sn * C2 + (size_t)bkk * Sn + sp0 + bsg;

    int wl = wid >> 1, wc = wid & 1;
    uint32_t a_off = (uint32_t)((wl * 32 + (lane & 7) + ((lane >> 3) & 1) * 8) * 48 +
                                ((lane >> 4) * 8) * 2);
    uint32_t b_off = (uint32_t)(((lane & 7) + ((lane >> 3) & 1) * 8) * 272 +
                                (wc * 64 + (lane >> 4) * 8) * 2);

    float acc[2][8][4];
#pragma unroll
    for (int i = 0; i < 2; i++)
#pragma unroll
        for (int n = 0; n < 8; n++)
#pragma unroll
            for (int q = 0; q < 4; q++) acc[i][n][q] = 0.f;

    {
        float4 w0 = *(const float4*)(wsrc);
        float4 w1 = *(const float4*)(wsrc + 4);
        uint h[4], l[4];
        split2(w0.x, w0.y, h[0], l[0]);
        split2(w0.z, w0.w, h[1], l[1]);
        split2(w1.x, w1.y, h[2], l[2]);
        split2(w1.z, w1.w, h[3], l[3]);
        *(uint4*)&Ah[0][arow][ak] = make_uint4(h[0], h[1], h[2], h[3]);
        *(uint4*)&Al[0][arow][ak] = make_uint4(l[0], l[1], l[2], l[3]);
        float4 a0 = *(const float4*)(asrc);
        float4 a1 = *(const float4*)(asrc + 4);
        split2(a0.x, a0.y, h[0], l[0]);
        split2(a0.z, a0.w, h[1], l[1]);
        split2(a1.x, a1.y, h[2], l[2]);
        split2(a1.z, a1.w, h[3], l[3]);
        *(uint4*)&Bh[0][bkk][bsg] = make_uint4(h[0], h[1], h[2], h[3]);
        *(uint4*)&Bl[0][bkk][bsg] = make_uint4(l[0], l[1], l[2], l[3]);
    }
    __syncthreads();

    for (int ch = 0; ch < 8; ch++) {
        int buf = ch & 1;
        float4 w0, w1, a0, a1;
        if (ch < 7) {
            w0 = *(const float4*)(wsrc + (ch + 1) * 16);
            w1 = *(const float4*)(wsrc + (ch + 1) * 16 + 4);
            const float* ap = asrc + (size_t)(ch + 1) * 16 * Sn;
            a0 = *(const float4*)(ap);
            a1 = *(const float4*)(ap + 4);
        }

        {
            uint32_t ah_base = smem_u32(&Ah[buf][0][0]) + a_off;
            uint32_t al_base = smem_u32(&Al[buf][0][0]) + a_off;
            uint32_t bh_base = smem_u32(&Bh[buf][0][0]) + b_off;
            uint32_t bl_base = smem_u32(&Bl[buf][0][0]) + b_off;

            uint ah[2][4], al2[2][4];
#pragma unroll
            for (int ln = 0; ln < 2; ln++) {
                ldsm4(ah_base + ln * 16 * 48, ah[ln][0], ah[ln][1], ah[ln][2], ah[ln][3]);
                ldsm4(al_base + ln * 16 * 48, al2[ln][0], al2[ln][1], al2[ln][2], al2[ln][3]);
            }
#pragma unroll
            for (int nn = 0; nn < 4; nn++) {
                uint bh0, bh1, bh2, bh3, bl0, bl1, bl2, bl3;
                ldsm4t(bh_base + nn * 32, bh0, bh1, bh2, bh3);
                ldsm4t(bl_base + nn * 32, bl0, bl1, bl2, bl3);
#pragma unroll
                for (int ln = 0; ln < 2; ln++) {
                    mma16816(acc[ln][2 * nn], ah[ln][0], ah[ln][1], ah[ln][2], ah[ln][3], bh0, bh1);
                    mma16816(acc[ln][2 * nn], ah[ln][0], ah[ln][1], ah[ln][2], ah[ln][3], bl0, bl1);
                    mma16816(acc[ln][2 * nn], al2[ln][0], al2[ln][1], al2[ln][2], al2[ln][3], bh0, bh1);
                    mma16816(acc[ln][2 * nn + 1], ah[ln][0], ah[ln][1], ah[ln][2], ah[ln][3], bh2, bh3);
                    mma16816(acc[ln][2 * nn + 1], ah[ln][0], ah[ln][1], ah[ln][2], ah[ln][3], bl2, bl3);
                    mma16816(acc[ln][2 * nn + 1], al2[ln][0], al2[ln][1], al2[ln][2], al2[ln][3], bh2, bh3);
                }
            }
        }

        if (ch < 7) {
            int nb = buf ^ 1;
            uint h[4], l[4];
            split2(w0.x, w0.y, h[0], l[0]);
            split2(w0.z, w0.w, h[1], l[1]);
            split2(w1.x, w1.y, h[2], l[2]);
            split2(w1.z, w1.w, h[3], l[3]);
            *(uint4*)&Ah[nb][arow][ak] = make_uint4(h[0], h[1], h[2], h[3]);
            *(uint4*)&Al[nb][arow][ak] = make_uint4(l[0], l[1], l[2], l[3]);
            split2(a0.x, a0.y, h[0], l[0]);
            split2(a0.z, a0.w, h[1], l[1]);
            split2(a1.x, a1.y, h[2], l[2]);
            split2(a1.z, a1.w, h[3], l[3]);
            *(uint4*)&Bh[nb][bkk][bsg] = make_uint4(h[0], h[1], h[2], h[3]);
            *(uint4*)&Bl[nb][bkk][bsg] = make_uint4(l[0], l[1], l[2], l[3]);
        }
        __syncthreads();
    }

    float g = gamma[0];
#pragma unroll
    for (int ln = 0; ln < 2; ln++) {
        int o1 = o0 + wl * 32 + ln * 16 + (lane >> 2);
        int o2 = o1 + 8;
        float bb1 = b2[o1], bb2 = b2[o2];
#pragma unroll
        for (int n = 0; n < 8; n++) {
            int sp = sp0 + wc * 64 + n * 8 + (lane & 3) * 2;
            const float* x1 = x + (size_t)b * Cc * Sn + (size_t)o1 * Sn + sp;
            const float* x2 = x + (size_t)b * Cc * Sn + (size_t)o2 * Sn + sp;
            float* y1 = out + (size_t)b * Cc * Sn + (size_t)o1 * Sn + sp;
            float* y2 = out + (size_t)b * Cc * Sn + (size_t)o2 * Sn + sp;
            float2 xa = *(const float2*)(x1);
            float2 xb = *(const float2*)(x2);
            float2 r1, r2;
            r1.x = fmaf(g, acc[ln][n][0] + bb1, xa.x);
            r1.y = fmaf(g, acc[ln][n][1] + bb1, xa.y);
            r2.x = fmaf(g, acc[ln][n][2] + bb2, xb.x);
            r2.y = fmaf(g, acc[ln][n][3] + bb2, xb.y);
            *(float2*)(y1) = r1;
            *(float2*)(y2) = r2;
        }
    }
}

// ---------------------------------------------------------------------------
extern "C" void kernel_launch(void* const* d_in, const int* in_sizes, int n_in,
                              void* d_out, int out_size) {
    const float* x   = (const float*)d_in[0];
    const float* qw  = (const float*)d_in[1];
    const float* qb  = (const float*)d_in[2];
    const float* kw  = (const float*)d_in[3];
    const float* kb  = (const float*)d_in[4];
    const float* vw  = (const float*)d_in[5];
    const float* vb  = (const float*)d_in[6];
    const float* v2w = (const float*)d_in[7];
    const float* v2b = (const float*)d_in[8];
    const float* gm  = (const float*)d_in[9];
    float* out = (float*)d_out;

    conv_all_k<<<dim3(32, 3, Bn), 128>>>(x, qw, qb, kw, kb, vw, vb);
    attn_hmma_k<<<dim3(Dn / 128, Sn / 128, Bn), 256>>>();
    stats_k<<<dim3(Dn / 64, Bn), dim3(64, 16)>>>();
    applied_hmma_k<<<dim3(Sn / 128, Bn), 256>>>();
    out_conv_hmma_k<<<dim3(Sn / 128, Cc / 128, Bn), 256>>>(x, v2w, v2b, gm, out);
}

// round 9
// speedup vs baseline: 1.9978x; 1.1129x over previous
#include <cuda_runtime.h>
#include <cuda_bf16.h>
#include <cstdint>

#define Bn 16
#define Cc 256
#define Sn 4096   // H*W
#define C8 32     // C/8
#define C2 128    // C/2
#define Dn 1024   // down = HW/4

typedef unsigned long long ull;
typedef unsigned int uint;

// ---- packed fp32x2 helpers ----
__device__ __forceinline__ ull ffma2(ull a, ull b, ull c) {
    ull d;
    asm("fma.rn.f32x2 %0, %1, %2, %3;" : "=l"(d) : "l"(a), "l"(b), "l"(c));
    return d;
}
__device__ __forceinline__ ull dup2(float v) {
    ull d;
    asm("mov.b64 %0, {%1, %1};" : "=l"(d) : "f"(v));
    return d;
}

// ---- mma/ldmatrix helpers ----
__device__ __forceinline__ uint32_t smem_u32(const void* p) {
    uint32_t a;
    asm("{ .reg .u64 t; cvta.to.shared.u64 t, %1; cvt.u32.u64 %0, t; }" : "=r"(a) : "l"(p));
    return a;
}
__device__ __forceinline__ void ldsm4(uint32_t a, uint& r0, uint& r1, uint& r2, uint& r3) {
    asm volatile("ldmatrix.sync.aligned.m8n8.x4.shared.b16 {%0,%1,%2,%3}, [%4];"
                 : "=r"(r0), "=r"(r1), "=r"(r2), "=r"(r3) : "r"(a));
}
__device__ __forceinline__ void ldsm4t(uint32_t a, uint& r0, uint& r1, uint& r2, uint& r3) {
    asm volatile("ldmatrix.sync.aligned.m8n8.x4.trans.shared.b16 {%0,%1,%2,%3}, [%4];"
                 : "=r"(r0), "=r"(r1), "=r"(r2), "=r"(r3) : "r"(a));
}
__device__ __forceinline__ void mma16816(float* d, uint a0, uint a1, uint a2, uint a3,
                                         uint b0, uint b1) {
    asm volatile(
        "mma.sync.aligned.m16n8k16.row.col.f32.bf16.bf16.f32 "
        "{%0,%1,%2,%3}, {%4,%5,%6,%7}, {%8,%9}, {%0,%1,%2,%3};"
        : "+f"(d[0]), "+f"(d[1]), "+f"(d[2]), "+f"(d[3])
        : "r"(a0), "r"(a1), "r"(a2), "r"(a3), "r"(b0), "r"(b1));
}

// split fp32 pair -> packed bf16 hi-pair / lo-pair
__device__ __forceinline__ void split2(float x, float y, uint& hi, uint& lo) {
    __nv_bfloat16 hx = __float2bfloat16_rn(x), hy = __float2bfloat16_rn(y);
    float rx = x - __bfloat162float(hx), ry = y - __bfloat162float(hy);
    __nv_bfloat16 lx = __float2bfloat16_rn(rx), ly = __float2bfloat16_rn(ry);
    __nv_bfloat162 hp, lp;
    hp.x = hx; hp.y = hy; lp.x = lx; lp.y = ly;
    hi = *(uint*)&hp;
    lo = *(uint*)&lp;
}

// ---- scratch ----
__device__ float g_q[(size_t)Bn * C8 * Sn];
__device__ float g_k[(size_t)Bn * C8 * Dn];
__device__ float g_v[(size_t)Bn * C2 * Dn];
__device__ unsigned short g_eh[(size_t)Bn * Sn * Dn];  // exp(logit) hi bf16
__device__ unsigned short g_el[(size_t)Bn * Sn * Dn];  // exp(logit) lo bf16
__device__ float g_colsum[Bn * Dn];                    // sum_l exp(attn[l,j])
__device__ float g_crs[Bn * Dn];                       // 1 / colsum
__device__ float g_app[(size_t)Bn * Sn * C2];

// ---------------------------------------------------------------------------
// Fused conv: q / k-pooled / v-pooled (unchanged, known-good)
// ---------------------------------------------------------------------------
__global__ __launch_bounds__(128) void conv_all_k(
    const float* __restrict__ x,
    const float* __restrict__ qw, const float* __restrict__ qb,
    const float* __restrict__ kw, const float* __restrict__ kb,
    const float* __restrict__ vw, const float* __restrict__ vb) {
    int b = blockIdx.z, ot = blockIdx.y, st = blockIdx.x;
    int s0 = st * 128;
    int t = threadIdx.x;

    __shared__ __align__(16) union {
        struct { float Ws[2][16][68]; float Xs[2][16][128]; } p;
        float Cs[64][128];
    } sm;

    int wrow = t >> 1;
    int wkg = (t & 1) << 3;
    int gch = ot * 64 + wrow;
    const float* wsrc;
    if (gch < 32) wsrc = qw + (size_t)gch * Cc;
    else if (gch < 64) wsrc = kw + (size_t)(gch - 32) * Cc;
    else wsrc = vw + (size_t)(gch - 64) * Cc;
    wsrc += wkg;

    int xkk = t >> 3;
    int xsg = (t & 7) << 4;
    const float* xsrc = x + (size_t)b * Cc * Sn + (size_t)xkk * Sn + s0 + xsg;

    int ty = t >> 4, tx = t & 15;

    ull acc[8][4];
#pragma unroll
    for (int i = 0; i < 8; i++)
#pragma unroll
        for (int j = 0; j < 4; j++) acc[i][j] = 0ULL;

    {
#pragma unroll
        for (int u = 0; u < 2; u++) {
            float4 v = *(const float4*)(wsrc + u * 4);
            sm.p.Ws[0][wkg + u * 4 + 0][wrow] = v.x;
            sm.p.Ws[0][wkg + u * 4 + 1][wrow] = v.y;
            sm.p.Ws[0][wkg + u * 4 + 2][wrow] = v.z;
            sm.p.Ws[0][wkg + u * 4 + 3][wrow] = v.w;
        }
#pragma unroll
        for (int u = 0; u < 4; u++)
            *(float4*)&sm.p.Xs[0][xkk][xsg + u * 4] = *(const float4*)(xsrc + u * 4);
    }
    __syncthreads();

    for (int ch = 0; ch < 16; ch++) {
        int cb = ch & 1;
        float4 wpre[2], xpre[4];
        if (ch < 15) {
            const float* wp = wsrc + (ch + 1) * 16;
            wpre[0] = *(const float4*)(wp);
            wpre[1] = *(const float4*)(wp + 4);
            const float* xp = xsrc + (size_t)(ch + 1) * 16 * Sn;
#pragma unroll
            for (int u = 0; u < 4; u++) xpre[u] = *(const float4*)(xp + u * 4);
        }
#pragma unroll
        for (int kk = 0; kk < 16; kk++) {
            float4 a0 = *(const float4*)&sm.p.Ws[cb][kk][ty * 8];
            float4 a1 = *(const float4*)&sm.p.Ws[cb][kk][ty * 8 + 4];
            ulonglong2 b0 = *(const ulonglong2*)&sm.p.Xs[cb][kk][tx * 8];
            ulonglong2 b1 = *(const ulonglong2*)&sm.p.Xs[cb][kk][tx * 8 + 4];
            ull bp[4] = {b0.x, b0.y, b1.x, b1.y};
            float aa[8] = {a0.x, a0.y, a0.z, a0.w, a1.x, a1.y, a1.z, a1.w};
#pragma unroll
            for (int i = 0; i < 8; i++) {
                ull ad = dup2(aa[i]);
#pragma unroll
                for (int j = 0; j < 4; j++) acc[i][j] = ffma2(ad, bp[j], acc[i][j]);
            }
        }
        if (ch < 15) {
            int nb = cb ^ 1;
#pragma unroll
            for (int u = 0; u < 2; u++) {
                sm.p.Ws[nb][wkg + u * 4 + 0][wrow] = (&wpre[u].x)[0];
                sm.p.Ws[nb][wkg + u * 4 + 1][wrow] = (&wpre[u].x)[1];
                sm.p.Ws[nb][wkg + u * 4 + 2][wrow] = (&wpre[u].x)[2];
                sm.p.Ws[nb][wkg + u * 4 + 3][wrow] = (&wpre[u].x)[3];
            }
#pragma unroll
            for (int u = 0; u < 4; u++)
                *(float4*)&sm.p.Xs[nb][xkk][xsg + u * 4] = xpre[u];
        }
        __syncthreads();
    }

#pragma unroll
    for (int i = 0; i < 8; i++) {
        ulonglong2 u0, u1;
        u0.x = acc[i][0]; u0.y = acc[i][1];
        u1.x = acc[i][2]; u1.y = acc[i][3];
        *(ulonglong2*)&sm.Cs[ty * 8 + i][tx * 8] = u0;
        *(ulonglong2*)&sm.Cs[ty * 8 + i][tx * 8 + 4] = u1;
    }
    __syncthreads();

    if (ot == 0) {
#pragma unroll
        for (int i = 0; i < 8; i++) {
            int o = i * 4 + (t >> 5);
            int sp = (t & 31) * 4;
            float4 v = *(const float4*)&sm.Cs[o][sp];
            float bb = qb[o];
            v.x += bb; v.y += bb; v.z += bb; v.w += bb;
            *(float4*)(g_q + (size_t)b * C8 * Sn + (size_t)o * Sn + s0 + sp) = v;
        }
        {
            int o = 32 + (t >> 2);
            int qcb = (t & 3) * 8;
            float bb = kb[o - 32];
            float* dst = g_k + (size_t)b * C8 * Dn + (size_t)(o - 32) * Dn + st * 32;
#pragma unroll
            for (int jj = 0; jj < 8; jj++) {
                int qc = qcb + jj;
                float m = fmaxf(fmaxf(sm.Cs[o][2 * qc], sm.Cs[o][2 * qc + 1]),
                                fmaxf(sm.Cs[o][64 + 2 * qc], sm.Cs[o][64 + 2 * qc + 1]));
                dst[qc] = m + bb;
            }
        }
    } else {
        int vg0 = (ot - 1) * 64;
        int o = t >> 1;
        int qcb = (t & 1) * 16;
        float bb = vb[vg0 + o];
        float* dst = g_v + (size_t)b * C2 * Dn + (size_t)(vg0 + o) * Dn + st * 32;
#pragma unroll
        for (int jj = 0; jj < 16; jj++) {
            int qc = qcb + jj;
            float m = fmaxf(fmaxf(sm.Cs[o][2 * qc], sm.Cs[o][2 * qc + 1]),
                            fmaxf(sm.Cs[o][64 + 2 * qc], sm.Cs[o][64 + 2 * qc + 1]));
            dst[qc] = m + bb;
        }
    }
}

// ---------------------------------------------------------------------------
// zero column sums (graph-replayed every call)
// ---------------------------------------------------------------------------
__global__ void zero_k() {
    g_colsum[blockIdx.x * 1024 + threadIdx.x] = 0.f;
}
// crs = 1/colsum
__global__ void recip_k() {
    int i = blockIdx.x * 1024 + threadIdx.x;
    g_crs[i] = 1.f / g_colsum[i];
}

// ---------------------------------------------------------------------------
// attn logits via split-bf16 HMMA + fused exp/split epilogue + column sums.
// Writes exp(logit) pre-split to g_eh/g_el; atomically accumulates column
// sums into g_colsum.  grid (Dn/128, Sn/128, Bn)
// ---------------------------------------------------------------------------
__global__ __launch_bounds__(256) void attn_hmma_k() {
    __shared__ __align__(16) unsigned short QAh[128][40], QAl[128][40];  // 80B rows
    __shared__ __align__(16) unsigned short KBh[128][40], KBl[128][40];
    __shared__ float sm_cp[4][128];

    int t = threadIdx.x, lane = t & 31, wid = t >> 5;
    int b = blockIdx.z, l0 = blockIdx.y * 128, j0 = blockIdx.x * 128;

    {
        int row = t >> 1, fs = (t & 1) * 16;
        const float* qp = g_q + (size_t)b * C8 * Sn + (size_t)(l0 + row) * 32 + fs;
        const float* kp = g_k + (size_t)b * C8 * Dn + (size_t)(j0 + row) * 32 + fs;
        uint h[8], l[8];
#pragma unroll
        for (int u = 0; u < 4; u++) {
            float4 v = *(const float4*)(qp + u * 4);
            split2(v.x, v.y, h[2 * u], l[2 * u]);
            split2(v.z, v.w, h[2 * u + 1], l[2 * u + 1]);
        }
        *(uint4*)&QAh[row][fs] = make_uint4(h[0], h[1], h[2], h[3]);
        *(uint4*)&QAh[row][fs + 8] = make_uint4(h[4], h[5], h[6], h[7]);
        *(uint4*)&QAl[row][fs] = make_uint4(l[0], l[1], l[2], l[3]);
        *(uint4*)&QAl[row][fs + 8] = make_uint4(l[4], l[5], l[6], l[7]);
#pragma unroll
        for (int u = 0; u < 4; u++) {
            float4 v = *(const float4*)(kp + u * 4);
            split2(v.x, v.y, h[2 * u], l[2 * u]);
            split2(v.z, v.w, h[2 * u + 1], l[2 * u + 1]);
        }
        *(uint4*)&KBh[row][fs] = make_uint4(h[0], h[1], h[2], h[3]);
        *(uint4*)&KBh[row][fs + 8] = make_uint4(h[4], h[5], h[6], h[7]);
        *(uint4*)&KBl[row][fs] = make_uint4(l[0], l[1], l[2], l[3]);
        *(uint4*)&KBl[row][fs + 8] = make_uint4(l[4], l[5], l[6], l[7]);
    }
    __syncthreads();

    int wl = wid >> 1, wc = wid & 1;
    uint32_t aoff = (uint32_t)((wl * 32 + (lane & 7) + ((lane >> 3) & 1) * 8) * 80 +
                               (lane >> 4) * 16);
    uint32_t boff = (uint32_t)((wc * 64 + (lane & 7) + ((lane >> 4) & 1) * 8) * 80 +
                               ((lane >> 3) & 1) * 16);
    uint32_t ah_b = smem_u32(QAh) + aoff, al_b = smem_u32(QAl) + aoff;
    uint32_t bh_b = smem_u32(KBh) + boff, bl_b = smem_u32(KBl) + boff;

    float acc[2][8][4];
#pragma unroll
    for (int i = 0; i < 2; i++)
#pragma unroll
        for (int n = 0; n < 8; n++)
#pragma unroll
            for (int q = 0; q < 4; q++) acc[i][n][q] = 0.f;

#pragma unroll
    for (int kc = 0; kc < 2; kc++) {
        uint ah[2][4], al2[2][4];
#pragma unroll
        for (int ln = 0; ln < 2; ln++) {
            ldsm4(ah_b + kc * 32 + ln * 16 * 80, ah[ln][0], ah[ln][1], ah[ln][2], ah[ln][3]);
            ldsm4(al_b + kc * 32 + ln * 16 * 80, al2[ln][0], al2[ln][1], al2[ln][2], al2[ln][3]);
        }
#pragma unroll
        for (int p = 0; p < 4; p++) {
            uint bh0, bh1, bh2, bh3, bl0, bl1, bl2, bl3;
            ldsm4(bh_b + kc * 32 + p * 16 * 80, bh0, bh1, bh2, bh3);
            ldsm4(bl_b + kc * 32 + p * 16 * 80, bl0, bl1, bl2, bl3);
#pragma unroll
            for (int ln = 0; ln < 2; ln++) {
                mma16816(acc[ln][2 * p], ah[ln][0], ah[ln][1], ah[ln][2], ah[ln][3], bh0, bh1);
                mma16816(acc[ln][2 * p], ah[ln][0], ah[ln][1], ah[ln][2], ah[ln][3], bl0, bl1);
                mma16816(acc[ln][2 * p], al2[ln][0], al2[ln][1], al2[ln][2], al2[ln][3], bh0, bh1);
                mma16816(acc[ln][2 * p + 1], ah[ln][0], ah[ln][1], ah[ln][2], ah[ln][3], bh2, bh3);
                mma16816(acc[ln][2 * p + 1], ah[ln][0], ah[ln][1], ah[ln][2], ah[ln][3], bl2, bl3);
                mma16816(acc[ln][2 * p + 1], al2[ln][0], al2[ln][1], al2[ln][2], al2[ln][3], bh2, bh3);
            }
        }
    }

    // ---- epilogue: exp in place, split-store, column partial sums ----
#pragma unroll
    for (int i = 0; i < 2; i++)
#pragma unroll
        for (int n = 0; n < 8; n++)
#pragma unroll
            for (int q = 0; q < 4; q++) acc[i][n][q] = __expf(acc[i][n][q]);

    unsigned short* ehb = g_eh + (size_t)b * Sn * Dn;
    unsigned short* elb = g_el + (size_t)b * Sn * Dn;
#pragma unroll
    for (int ln = 0; ln < 2; ln++) {
        int r0 = l0 + wl * 32 + ln * 16 + (lane >> 2);
#pragma unroll
        for (int n = 0; n < 8; n++) {
            int c = j0 + wc * 64 + n * 8 + (lane & 3) * 2;
            uint h01, l01, h23, l23;
            split2(acc[ln][n][0], acc[ln][n][1], h01, l01);
            split2(acc[ln][n][2], acc[ln][n][3], h23, l23);
            *(uint*)(ehb + (size_t)r0 * Dn + c) = h01;
            *(uint*)(elb + (size_t)r0 * Dn + c) = l01;
            *(uint*)(ehb + (size_t)(r0 + 8) * Dn + c) = h23;
            *(uint*)(elb + (size_t)(r0 + 8) * Dn + c) = l23;
        }
    }

#pragma unroll
    for (int n = 0; n < 8; n++) {
        float s0 = acc[0][n][0] + acc[0][n][2] + acc[1][n][0] + acc[1][n][2];
        float s1 = acc[0][n][1] + acc[0][n][3] + acc[1][n][1] + acc[1][n][3];
        s0 += __shfl_xor_sync(0xffffffffu, s0, 4);
        s0 += __shfl_xor_sync(0xffffffffu, s0, 8);
        s0 += __shfl_xor_sync(0xffffffffu, s0, 16);
        s1 += __shfl_xor_sync(0xffffffffu, s1, 4);
        s1 += __shfl_xor_sync(0xffffffffu, s1, 8);
        s1 += __shfl_xor_sync(0xffffffffu, s1, 16);
        if ((lane >> 2) == 0) {
            int cl = wc * 64 + n * 8 + (lane & 3) * 2;
            sm_cp[wl][cl] = s0;
            sm_cp[wl][cl + 1] = s1;
        }
    }
    __syncthreads();
    if (t < 128) {
        float cs = sm_cp[0][t] + sm_cp[1][t] + sm_cp[2][t] + sm_cp[3][t];
        atomicAdd(&g_colsum[b * Dn + j0 + t], cs);
    }
}

// ---------------------------------------------------------------------------
// applied GEMM via split-bf16 HMMA, pure-copy loaders (exp/split pre-done):
//   app[128l x 128c] = sum_j e[l,j] * (crs[j]*v[j,c])
// grid (Sn/128, Bn)
// ---------------------------------------------------------------------------
__global__ __launch_bounds__(256) void applied_hmma_k() {
    __shared__ __align__(16) unsigned short Ah[2][128][24];
    __shared__ __align__(16) unsigned short Al[2][128][24];
    __shared__ __align__(16) unsigned short Bh[2][16][136];
    __shared__ __align__(16) unsigned short Bl[2][16][136];

    int t = threadIdx.x, lane = t & 31, wid = t >> 5;
    int b = blockIdx.y, l0 = blockIdx.x * 128;

    int arow = t >> 1, ak = (t & 1) * 8;
    const unsigned short* ahg = g_eh + (size_t)b * Sn * Dn + (size_t)(l0 + arow) * Dn + ak;
    const unsigned short* alg = g_el + (size_t)b * Sn * Dn + (size_t)(l0 + arow) * Dn + ak;
    int bj = t >> 4, bc = (t & 15) * 8;
    const float* vbase = g_v + (size_t)b * C2 * Dn;
    const float* crb = g_crs + b * Dn;

    int wl = wid >> 1, wc = wid & 1;
    uint32_t a_off = (uint32_t)((wl * 32 + (lane & 7) + ((lane >> 3) & 1) * 8) * 48 +
                                ((lane >> 4) * 8) * 2);
    uint32_t b_off = (uint32_t)(((lane & 7) + ((lane >> 3) & 1) * 8) * 272 +
                                (wc * 64 + (lane >> 4) * 8) * 2);

    float acc[2][8][4];
#pragma unroll
    for (int i = 0; i < 2; i++)
#pragma unroll
        for (int n = 0; n < 8; n++)
#pragma unroll
            for (int q = 0; q < 4; q++) acc[i][n][q] = 0.f;

    {
        *(uint4*)&Ah[0][arow][ak] = *(const uint4*)(ahg);
        *(uint4*)&Al[0][arow][ak] = *(const uint4*)(alg);
        float sc = crb[bj];
        const float* vp = vbase + (size_t)bj * C2 + bc;
        float4 bv0 = *(const float4*)(vp);
        float4 bv1 = *(const float4*)(vp + 4);
        uint h[4], l[4];
        split2(bv0.x * sc, bv0.y * sc, h[0], l[0]);
        split2(bv0.z * sc, bv0.w * sc, h[1], l[1]);
        split2(bv1.x * sc, bv1.y * sc, h[2], l[2]);
        split2(bv1.z * sc, bv1.w * sc, h[3], l[3]);
        *(uint4*)&Bh[0][bj][bc] = make_uint4(h[0], h[1], h[2], h[3]);
        *(uint4*)&Bl[0][bj][bc] = make_uint4(l[0], l[1], l[2], l[3]);
    }
    __syncthreads();

    for (int ch = 0; ch < 64; ch++) {
        int buf = ch & 1;
        uint4 pah, pal;
        float4 bv0, bv1;
        float sc;
        if (ch < 63) {
            pah = *(const uint4*)(ahg + (ch + 1) * 16);
            pal = *(const uint4*)(alg + (ch + 1) * 16);
            int j = (ch + 1) * 16 + bj;
            sc = crb[j];
            const float* vp = vbase + (size_t)j * C2 + bc;
            bv0 = *(const float4*)(vp);
            bv1 = *(const float4*)(vp + 4);
        }

        {
            uint32_t ah_base = smem_u32(&Ah[buf][0][0]) + a_off;
            uint32_t al_base = smem_u32(&Al[buf][0][0]) + a_off;
            uint32_t bh_base = smem_u32(&Bh[buf][0][0]) + b_off;
            uint32_t bl_base = smem_u32(&Bl[buf][0][0]) + b_off;

            uint ah[2][4], al2[2][4];
#pragma unroll
            for (int ln = 0; ln < 2; ln++) {
                ldsm4(ah_base + ln * 16 * 48, ah[ln][0], ah[ln][1], ah[ln][2], ah[ln][3]);
                ldsm4(al_base + ln * 16 * 48, al2[ln][0], al2[ln][1], al2[ln][2], al2[ln][3]);
            }
#pragma unroll
            for (int nn = 0; nn < 4; nn++) {
                uint bh0, bh1, bh2, bh3, bl0, bl1, bl2, bl3;
                ldsm4t(bh_base + nn * 32, bh0, bh1, bh2, bh3);
                ldsm4t(bl_base + nn * 32, bl0, bl1, bl2, bl3);
#pragma unroll
                for (int ln = 0; ln < 2; ln++) {
                    mma16816(acc[ln][2 * nn], ah[ln][0], ah[ln][1], ah[ln][2], ah[ln][3], bh0, bh1);
                    mma16816(acc[ln][2 * nn], ah[ln][0], ah[ln][1], ah[ln][2], ah[ln][3], bl0, bl1);
                    mma16816(acc[ln][2 * nn], al2[ln][0], al2[ln][1], al2[ln][2], al2[ln][3], bh0, bh1);
                    mma16816(acc[ln][2 * nn + 1], ah[ln][0], ah[ln][1], ah[ln][2], ah[ln][3], bh2, bh3);
                    mma16816(acc[ln][2 * nn + 1], ah[ln][0], ah[ln][1], ah[ln][2], ah[ln][3], bl2, bl3);
                    mma16816(acc[ln][2 * nn + 1], al2[ln][0], al2[ln][1], al2[ln][2], al2[ln][3], bh2, bh3);
                }
            }
        }

        if (ch < 63) {
            int nb = buf ^ 1;
            *(uint4*)&Ah[nb][arow][ak] = pah;
            *(uint4*)&Al[nb][arow][ak] = pal;
            uint h[4], l[4];
            split2(bv0.x * sc, bv0.y * sc, h[0], l[0]);
            split2(bv0.z * sc, bv0.w * sc, h[1], l[1]);
            split2(bv1.x * sc, bv1.y * sc, h[2], l[2]);
            split2(bv1.z * sc, bv1.w * sc, h[3], l[3]);
            *(uint4*)&Bh[nb][bj][bc] = make_uint4(h[0], h[1], h[2], h[3]);
            *(uint4*)&Bl[nb][bj][bc] = make_uint4(l[0], l[1], l[2], l[3]);
        }
        __syncthreads();
    }

    float* ob = g_app + (size_t)b * Sn * C2;
#pragma unroll
    for (int ln = 0; ln < 2; ln++) {
        int r0 = l0 + wl * 32 + ln * 16 + (lane >> 2);
#pragma unroll
        for (int n = 0; n < 8; n++) {
            int c = wc * 64 + n * 8 + (lane & 3) * 2;
            *(float2*)(ob + (size_t)r0 * C2 + c) = make_float2(acc[ln][n][0], acc[ln][n][1]);
            *(float2*)(ob + (size_t)(r0 + 8) * C2 + c) = make_float2(acc[ln][n][2], acc[ln][n][3]);
        }
    }
}

// ---------------------------------------------------------------------------
// output conv + residual via split-bf16 HMMA (proven)
// grid (Sn/128, Cc/128, Bn)
// ---------------------------------------------------------------------------
__global__ __launch_bounds__(256) void out_conv_hmma_k(
    const float* __restrict__ x, const float* __restrict__ w2,
    const float* __restrict__ b2, const float* __restrict__ gamma,
    float* __restrict__ out) {
    __shared__ __align__(16) unsigned short Ah[2][128][24];
    __shared__ __align__(16) unsigned short Al[2][128][24];
    __shared__ __align__(16) unsigned short Bh[2][16][136];
    __shared__ __align__(16) unsigned short Bl[2][16][136];

    int t = threadIdx.x, lane = t & 31, wid = t >> 5;
    int b = blockIdx.z, o0 = blockIdx.y * 128, sp0 = blockIdx.x * 128;

    int arow = t >> 1, ak = (t & 1) * 8;
    const float* wsrc = w2 + (size_t)(o0 + arow) * C2 + ak;
    int bkk = t >> 4, bsg = (t & 15) * 8;
    const float* asrc = g_app + (size_t)b * Sn * C2 + (size_t)bkk * Sn + sp0 + bsg;

    int wl = wid >> 1, wc = wid & 1;
    uint32_t a_off = (uint32_t)((wl * 32 + (lane & 7) + ((lane >> 3) & 1) * 8) * 48 +
                                ((lane >> 4) * 8) * 2);
    uint32_t b_off = (uint32_t)(((lane & 7) + ((lane >> 3) & 1) * 8) * 272 +
                                (wc * 64 + (lane >> 4) * 8) * 2);

    float acc[2][8][4];
#pragma unroll
    for (int i = 0; i < 2; i++)
#pragma unroll
        for (int n = 0; n < 8; n++)
#pragma unroll
            for (int q = 0; q < 4; q++) acc[i][n][q] = 0.f;

    {
        float4 w0 = *(const float4*)(wsrc);
        float4 w1 = *(const float4*)(wsrc + 4);
        uint h[4], l[4];
        split2(w0.x, w0.y, h[0], l[0]);
        split2(w0.z, w0.w, h[1], l[1]);
        split2(w1.x, w1.y, h[2], l[2]);
        split2(w1.z, w1.w, h[3], l[3]);
        *(uint4*)&Ah[0][arow][ak] = make_uint4(h[0], h[1], h[2], h[3]);
        *(uint4*)&Al[0][arow][ak] = make_uint4(l[0], l[1], l[2], l[3]);
        float4 a0 = *(const float4*)(asrc);
        float4 a1 = *(const float4*)(asrc + 4);
        split2(a0.x, a0.y, h[0], l[0]);
        split2(a0.z, a0.w, h[1], l[1]);
        split2(a1.x, a1.y, h[2], l[2]);
        split2(a1.z, a1.w, h[3], l[3]);
        *(uint4*)&Bh[0][bkk][bsg] = make_uint4(h[0], h[1], h[2], h[3]);
        *(uint4*)&Bl[0][bkk][bsg] = make_uint4(l[0], l[1], l[2], l[3]);
    }
    __syncthreads();

    for (int ch = 0; ch < 8; ch++) {
        int buf = ch & 1;
        float4 w0, w1, a0, a1;
        if (ch < 7) {
            w0 = *(const float4*)(wsrc + (ch + 1) * 16);
            w1 = *(const float4*)(wsrc + (ch + 1) * 16 + 4);
            const float* ap = asrc + (size_t)(ch + 1) * 16 * Sn;
            a0 = *(const float4*)(ap);
            a1 = *(const float4*)(ap + 4);
        }

        {
            uint32_t ah_base = smem_u32(&Ah[buf][0][0]) + a_off;
            uint32_t al_base = smem_u32(&Al[buf][0][0]) + a_off;
            uint32_t bh_base = smem_u32(&Bh[buf][0][0]) + b_off;
            uint32_t bl_base = smem_u32(&Bl[buf][0][0]) + b_off;

            uint ah[2][4], al2[2][4];
#pragma unroll
            for (int ln = 0; ln < 2; ln++) {
                ldsm4(ah_base + ln * 16 * 48, ah[ln][0], ah[ln][1], ah[ln][2], ah[ln][3]);
                ldsm4(al_base + ln * 16 * 48, al2[ln][0], al2[ln][1], al2[ln][2], al2[ln][3]);
            }
#pragma unroll
            for (int nn = 0; nn < 4; nn++) {
                uint bh0, bh1, bh2, bh3, bl0, bl1, bl2, bl3;
                ldsm4t(bh_base + nn * 32, bh0, bh1, bh2, bh3);
                ldsm4t(bl_base + nn * 32, bl0, bl1, bl2, bl3);
#pragma unroll
                for (int ln = 0; ln < 2; ln++) {
                    mma16816(acc[ln][2 * nn], ah[ln][0], ah[ln][1], ah[ln][2], ah[ln][3], bh0, bh1);
                    mma16816(acc[ln][2 * nn], ah[ln][0], ah[ln][1], ah[ln][2], ah[ln][3], bl0, bl1);
                    mma16816(acc[ln][2 * nn], al2[ln][0], al2[ln][1], al2[ln][2], al2[ln][3], bh0, bh1);
                    mma16816(acc[ln][2 * nn + 1], ah[ln][0], ah[ln][1], ah[ln][2], ah[ln][3], bh2, bh3);
                    mma16816(acc[ln][2 * nn + 1], ah[ln][0], ah[ln][1], ah[ln][2], ah[ln][3], bl2, bl3);
                    mma16816(acc[ln][2 * nn + 1], al2[ln][0], al2[ln][1], al2[ln][2], al2[ln][3], bh2, bh3);
                }
            }
        }

        if (ch < 7) {
            int nb = buf ^ 1;
            uint h[4], l[4];
            split2(w0.x, w0.y, h[0], l[0]);
            split2(w0.z, w0.w, h[1], l[1]);
            split2(w1.x, w1.y, h[2], l[2]);
            split2(w1.z, w1.w, h[3], l[3]);
            *(uint4*)&Ah[nb][arow][ak] = make_uint4(h[0], h[1], h[2], h[3]);
            *(uint4*)&Al[nb][arow][ak] = make_uint4(l[0], l[1], l[2], l[3]);
            split2(a0.x, a0.y, h[0], l[0]);
            split2(a0.z, a0.w, h[1], l[1]);
            split2(a1.x, a1.y, h[2], l[2]);
            split2(a1.z, a1.w, h[3], l[3]);
            *(uint4*)&Bh[nb][bkk][bsg] = make_uint4(h[0], h[1], h[2], h[3]);
            *(uint4*)&Bl[nb][bkk][bsg] = make_uint4(l[0], l[1], l[2], l[3]);
        }
        __syncthreads();
    }

    float g = gamma[0];
#pragma unroll
    for (int ln = 0; ln < 2; ln++) {
        int o1 = o0 + wl * 32 + ln * 16 + (lane >> 2);
        int o2 = o1 + 8;
        float bb1 = b2[o1], bb2 = b2[o2];
#pragma unroll
        for (int n = 0; n < 8; n++) {
            int sp = sp0 + wc * 64 + n * 8 + (lane & 3) * 2;
            const float* x1 = x + (size_t)b * Cc * Sn + (size_t)o1 * Sn + sp;
            const float* x2 = x + (size_t)b * Cc * Sn + (size_t)o2 * Sn + sp;
            float* y1 = out + (size_t)b * Cc * Sn + (size_t)o1 * Sn + sp;
            float* y2 = out + (size_t)b * Cc * Sn + (size_t)o2 * Sn + sp;
            float2 xa = *(const float2*)(x1);
            float2 xb = *(const float2*)(x2);
            float2 r1, r2;
            r1.x = fmaf(g, acc[ln][n][0] + bb1, xa.x);
            r1.y = fmaf(g, acc[ln][n][1] + bb1, xa.y);
            r2.x = fmaf(g, acc[ln][n][2] + bb2, xb.x);
            r2.y = fmaf(g, acc[ln][n][3] + bb2, xb.y);
            *(float2*)(y1) = r1;
            *(float2*)(y2) = r2;
        }
    }
}

// ---------------------------------------------------------------------------
extern "C" void kernel_launch(void* const* d_in, const int* in_sizes, int n_in,
                              void* d_out, int out_size) {
    const float* x   = (const float*)d_in[0];
    const float* qw  = (const float*)d_in[1];
    const float* qb  = (const float*)d_in[2];
    const float* kw  = (const float*)d_in[3];
    const float* kb  = (const float*)d_in[4];
    const float* vw  = (const float*)d_in[5];
    const float* vb  = (const float*)d_in[6];
    const float* v2w = (const float*)d_in[7];
    const float* v2b = (const float*)d_in[8];
    const float* gm  = (const float*)d_in[9];
    float* out = (float*)d_out;

    conv_all_k<<<dim3(32, 3, Bn), 128>>>(x, qw, qb, kw, kb, vw, vb);
    zero_k<<<Bn * Dn / 1024, 1024>>>();
    attn_hmma_k<<<dim3(Dn / 128, Sn / 128, Bn), 256>>>();
    recip_k<<<Bn * Dn / 1024, 1024>>>();
    applied_hmma_k<<<dim3(Sn / 128, Bn), 256>>>();
    out_conv_hmma_k<<<dim3(Sn / 128, Cc / 128, Bn), 256>>>(x, v2w, v2b, gm, out);
}

// round 10
// speedup vs baseline: 2.0020x; 1.0021x over previous
#include <cuda_runtime.h>
#include <cuda_bf16.h>
#include <cstdint>

#define Bn 16
#define Cc 256
#define Sn 4096   // H*W
#define C8 32     // C/8
#define C2 128    // C/2
#define Dn 1024   // down = HW/4

typedef unsigned long long ull;
typedef unsigned int uint;

// ---- packed fp32x2 helpers ----
__device__ __forceinline__ ull ffma2(ull a, ull b, ull c) {
    ull d;
    asm("fma.rn.f32x2 %0, %1, %2, %3;" : "=l"(d) : "l"(a), "l"(b), "l"(c));
    return d;
}
__device__ __forceinline__ ull dup2(float v) {
    ull d;
    asm("mov.b64 %0, {%1, %1};" : "=l"(d) : "f"(v));
    return d;
}

// ---- mma/ldmatrix/cp.async helpers ----
__device__ __forceinline__ uint32_t smem_u32(const void* p) {
    uint32_t a;
    asm("{ .reg .u64 t; cvta.to.shared.u64 t, %1; cvt.u32.u64 %0, t; }" : "=r"(a) : "l"(p));
    return a;
}
__device__ __forceinline__ void ldsm4(uint32_t a, uint& r0, uint& r1, uint& r2, uint& r3) {
    asm volatile("ldmatrix.sync.aligned.m8n8.x4.shared.b16 {%0,%1,%2,%3}, [%4];"
                 : "=r"(r0), "=r"(r1), "=r"(r2), "=r"(r3) : "r"(a));
}
__device__ __forceinline__ void ldsm4t(uint32_t a, uint& r0, uint& r1, uint& r2, uint& r3) {
    asm volatile("ldmatrix.sync.aligned.m8n8.x4.trans.shared.b16 {%0,%1,%2,%3}, [%4];"
                 : "=r"(r0), "=r"(r1), "=r"(r2), "=r"(r3) : "r"(a));
}
__device__ __forceinline__ void mma16816(float* d, uint a0, uint a1, uint a2, uint a3,
                                         uint b0, uint b1) {
    asm volatile(
        "mma.sync.aligned.m16n8k16.row.col.f32.bf16.bf16.f32 "
        "{%0,%1,%2,%3}, {%4,%5,%6,%7}, {%8,%9}, {%0,%1,%2,%3};"
        : "+f"(d[0]), "+f"(d[1]), "+f"(d[2]), "+f"(d[3])
        : "r"(a0), "r"(a1), "r"(a2), "r"(a3), "r"(b0), "r"(b1));
}
__device__ __forceinline__ void cp16(uint32_t s, const void* g) {
    asm volatile("cp.async.ca.shared.global [%0], [%1], 16;" :: "r"(s), "l"(g));
}
#define CP_COMMIT() asm volatile("cp.async.commit_group;")
#define CP_WAIT2() asm volatile("cp.async.wait_group 2;")

// split fp32 pair -> packed bf16 hi-pair / lo-pair
__device__ __forceinline__ void split2(float x, float y, uint& hi, uint& lo) {
    __nv_bfloat16 hx = __float2bfloat16_rn(x), hy = __float2bfloat16_rn(y);
    float rx = x - __bfloat162float(hx), ry = y - __bfloat162float(hy);
    __nv_bfloat16 lx = __float2bfloat16_rn(rx), ly = __float2bfloat16_rn(ry);
    __nv_bfloat162 hp, lp;
    hp.x = hx; hp.y = hy; lp.x = lx; lp.y = ly;
    hi = *(uint*)&hp;
    lo = *(uint*)&lp;
}

// ---- scratch ----
__device__ float g_q[(size_t)Bn * C8 * Sn];
__device__ float g_k[(size_t)Bn * C8 * Dn];
__device__ float g_v[(size_t)Bn * C2 * Dn];
__device__ unsigned short g_eh[(size_t)Bn * Sn * Dn];   // exp(logit) hi bf16
__device__ unsigned short g_el[(size_t)Bn * Sn * Dn];   // exp(logit) lo bf16
__device__ unsigned short g_vhn[(size_t)Bn * C2 * Dn];  // crs*v hi
__device__ unsigned short g_vln[(size_t)Bn * C2 * Dn];  // crs*v lo
__device__ unsigned short g_aph[(size_t)Bn * Sn * C2];  // app hi
__device__ unsigned short g_apl[(size_t)Bn * Sn * C2];  // app lo
__device__ unsigned short g_w2h[Cc * C2];               // w2 hi
__device__ unsigned short g_w2l[Cc * C2];               // w2 lo
__device__ float g_colsum[Bn * Dn];
__device__ float g_crs[Bn * Dn];

// ---------------------------------------------------------------------------
// Fused conv: q / k-pooled / v-pooled (unchanged, known-good)
// ---------------------------------------------------------------------------
__global__ __launch_bounds__(128) void conv_all_k(
    const float* __restrict__ x,
    const float* __restrict__ qw, const float* __restrict__ qb,
    const float* __restrict__ kw, const float* __restrict__ kb,
    const float* __restrict__ vw, const float* __restrict__ vb) {
    int b = blockIdx.z, ot = blockIdx.y, st = blockIdx.x;
    int s0 = st * 128;
    int t = threadIdx.x;

    __shared__ __align__(16) union {
        struct { float Ws[2][16][68]; float Xs[2][16][128]; } p;
        float Cs[64][128];
    } sm;

    int wrow = t >> 1;
    int wkg = (t & 1) << 3;
    int gch = ot * 64 + wrow;
    const float* wsrc;
    if (gch < 32) wsrc = qw + (size_t)gch * Cc;
    else if (gch < 64) wsrc = kw + (size_t)(gch - 32) * Cc;
    else wsrc = vw + (size_t)(gch - 64) * Cc;
    wsrc += wkg;

    int xkk = t >> 3;
    int xsg = (t & 7) << 4;
    const float* xsrc = x + (size_t)b * Cc * Sn + (size_t)xkk * Sn + s0 + xsg;

    int ty = t >> 4, tx = t & 15;

    ull acc[8][4];
#pragma unroll
    for (int i = 0; i < 8; i++)
#pragma unroll
        for (int j = 0; j < 4; j++) acc[i][j] = 0ULL;

    {
#pragma unroll
        for (int u = 0; u < 2; u++) {
            float4 v = *(const float4*)(wsrc + u * 4);
            sm.p.Ws[0][wkg + u * 4 + 0][wrow] = v.x;
            sm.p.Ws[0][wkg + u * 4 + 1][wrow] = v.y;
            sm.p.Ws[0][wkg + u * 4 + 2][wrow] = v.z;
            sm.p.Ws[0][wkg + u * 4 + 3][wrow] = v.w;
        }
#pragma unroll
        for (int u = 0; u < 4; u++)
            *(float4*)&sm.p.Xs[0][xkk][xsg + u * 4] = *(const float4*)(xsrc + u * 4);
    }
    __syncthreads();

    for (int ch = 0; ch < 16; ch++) {
        int cb = ch & 1;
        float4 wpre[2], xpre[4];
        if (ch < 15) {
            const float* wp = wsrc + (ch + 1) * 16;
            wpre[0] = *(const float4*)(wp);
            wpre[1] = *(const float4*)(wp + 4);
            const float* xp = xsrc + (size_t)(ch + 1) * 16 * Sn;
#pragma unroll
            for (int u = 0; u < 4; u++) xpre[u] = *(const float4*)(xp + u * 4);
        }
#pragma unroll
        for (int kk = 0; kk < 16; kk++) {
            float4 a0 = *(const float4*)&sm.p.Ws[cb][kk][ty * 8];
            float4 a1 = *(const float4*)&sm.p.Ws[cb][kk][ty * 8 + 4];
            ulonglong2 b0 = *(const ulonglong2*)&sm.p.Xs[cb][kk][tx * 8];
            ulonglong2 b1 = *(const ulonglong2*)&sm.p.Xs[cb][kk][tx * 8 + 4];
            ull bp[4] = {b0.x, b0.y, b1.x, b1.y};
            float aa[8] = {a0.x, a0.y, a0.z, a0.w, a1.x, a1.y, a1.z, a1.w};
#pragma unroll
            for (int i = 0; i < 8; i++) {
                ull ad = dup2(aa[i]);
#pragma unroll
                for (int j = 0; j < 4; j++) acc[i][j] = ffma2(ad, bp[j], acc[i][j]);
            }
        }
        if (ch < 15) {
            int nb = cb ^ 1;
#pragma unroll
            for (int u = 0; u < 2; u++) {
                sm.p.Ws[nb][wkg + u * 4 + 0][wrow] = (&wpre[u].x)[0];
                sm.p.Ws[nb][wkg + u * 4 + 1][wrow] = (&wpre[u].x)[1];
                sm.p.Ws[nb][wkg + u * 4 + 2][wrow] = (&wpre[u].x)[2];
                sm.p.Ws[nb][wkg + u * 4 + 3][wrow] = (&wpre[u].x)[3];
            }
#pragma unroll
            for (int u = 0; u < 4; u++)
                *(float4*)&sm.p.Xs[nb][xkk][xsg + u * 4] = xpre[u];
        }
        __syncthreads();
    }

#pragma unroll
    for (int i = 0; i < 8; i++) {
        ulonglong2 u0, u1;
        u0.x = acc[i][0]; u0.y = acc[i][1];
        u1.x = acc[i][2]; u1.y = acc[i][3];
        *(ulonglong2*)&sm.Cs[ty * 8 + i][tx * 8] = u0;
        *(ulonglong2*)&sm.Cs[ty * 8 + i][tx * 8 + 4] = u1;
    }
    __syncthreads();

    if (ot == 0) {
#pragma unroll
        for (int i = 0; i < 8; i++) {
            int o = i * 4 + (t >> 5);
            int sp = (t & 31) * 4;
            float4 v = *(const float4*)&sm.Cs[o][sp];
            float bb = qb[o];
            v.x += bb; v.y += bb; v.z += bb; v.w += bb;
            *(float4*)(g_q + (size_t)b * C8 * Sn + (size_t)o * Sn + s0 + sp) = v;
        }
        {
            int o = 32 + (t >> 2);
            int qcb = (t & 3) * 8;
            float bb = kb[o - 32];
            float* dst = g_k + (size_t)b * C8 * Dn + (size_t)(o - 32) * Dn + st * 32;
#pragma unroll
            for (int jj = 0; jj < 8; jj++) {
                int qc = qcb + jj;
                float m = fmaxf(fmaxf(sm.Cs[o][2 * qc], sm.Cs[o][2 * qc + 1]),
                                fmaxf(sm.Cs[o][64 + 2 * qc], sm.Cs[o][64 + 2 * qc + 1]));
                dst[qc] = m + bb;
            }
        }
    } else {
        int vg0 = (ot - 1) * 64;
        int o = t >> 1;
        int qcb = (t & 1) * 16;
        float bb = vb[vg0 + o];
        float* dst = g_v + (size_t)b * C2 * Dn + (size_t)(vg0 + o) * Dn + st * 32;
#pragma unroll
        for (int jj = 0; jj < 16; jj++) {
            int qc = qcb + jj;
            float m = fmaxf(fmaxf(sm.Cs[o][2 * qc], sm.Cs[o][2 * qc + 1]),
                            fmaxf(sm.Cs[o][64 + 2 * qc], sm.Cs[o][64 + 2 * qc + 1]));
            dst[qc] = m + bb;
        }
    }
}

// ---------------------------------------------------------------------------
__global__ void zero_k() { g_colsum[blockIdx.x * 1024 + threadIdx.x] = 0.f; }
__global__ void recip_k() {
    int i = blockIdx.x * 1024 + threadIdx.x;
    g_crs[i] = 1.f / g_colsum[i];
}
// wsplit: split w2 into bf16 hi/lo (32K elts)
__global__ void wsplit_k(const float* __restrict__ w2) {
    int idx = (blockIdx.x * 256 + threadIdx.x) * 8;
    float4 v0 = *(const float4*)(w2 + idx);
    float4 v1 = *(const float4*)(w2 + idx + 4);
    uint h[4], l[4];
    split2(v0.x, v0.y, h[0], l[0]);
    split2(v0.z, v0.w, h[1], l[1]);
    split2(v1.x, v1.y, h[2], l[2]);
    split2(v1.z, v1.w, h[3], l[3]);
    *(uint4*)(g_w2h + idx) = make_uint4(h[0], h[1], h[2], h[3]);
    *(uint4*)(g_w2l + idx) = make_uint4(l[0], l[1], l[2], l[3]);
}
// vsplit: g_vhn/g_vln = split-bf16( crs[j] * v[j][c] )
__global__ void vsplit_k() {
    int idx = blockIdx.x * 256 + threadIdx.x;
    int lin = idx * 8;
    int b = lin >> 17;
    int rem = lin & (Dn * C2 - 1);
    int j = rem >> 7;
    float rs = g_crs[b * Dn + j];
    const float* vp = g_v + (size_t)b * C2 * Dn + rem;
    float4 v0 = *(const float4*)(vp);
    float4 v1 = *(const float4*)(vp + 4);
    uint h[4], l[4];
    split2(v0.x * rs, v0.y * rs, h[0], l[0]);
    split2(v0.z * rs, v0.w * rs, h[1], l[1]);
    split2(v1.x * rs, v1.y * rs, h[2], l[2]);
    split2(v1.z * rs, v1.w * rs, h[3], l[3]);
    size_t o = (size_t)b * C2 * Dn + rem;
    *(uint4*)(g_vhn + o) = make_uint4(h[0], h[1], h[2], h[3]);
    *(uint4*)(g_vln + o) = make_uint4(l[0], l[1], l[2], l[3]);
}

// ---------------------------------------------------------------------------
// attn logits via split-bf16 HMMA + fused exp/split epilogue + column sums.
// (unchanged from R9, proven)  grid (Dn/128, Sn/128, Bn)
// ---------------------------------------------------------------------------
__global__ __launch_bounds__(256) void attn_hmma_k() {
    __shared__ __align__(16) unsigned short QAh[128][40], QAl[128][40];
    __shared__ __align__(16) unsigned short KBh[128][40], KBl[128][40];
    __shared__ float sm_cp[4][128];

    int t = threadIdx.x, lane = t & 31, wid = t >> 5;
    int b = blockIdx.z, l0 = blockIdx.y * 128, j0 = blockIdx.x * 128;

    {
        int row = t >> 1, fs = (t & 1) * 16;
        const float* qp = g_q + (size_t)b * C8 * Sn + (size_t)(l0 + row) * 32 + fs;
        const float* kp = g_k + (size_t)b * C8 * Dn + (size_t)(j0 + row) * 32 + fs;
        uint h[8], l[8];
#pragma unroll
        for (int u = 0; u < 4; u++) {
            float4 v = *(const float4*)(qp + u * 4);
            split2(v.x, v.y, h[2 * u], l[2 * u]);
            split2(v.z, v.w, h[2 * u + 1], l[2 * u + 1]);
        }
        *(uint4*)&QAh[row][fs] = make_uint4(h[0], h[1], h[2], h[3]);
        *(uint4*)&QAh[row][fs + 8] = make_uint4(h[4], h[5], h[6], h[7]);
        *(uint4*)&QAl[row][fs] = make_uint4(l[0], l[1], l[2], l[3]);
        *(uint4*)&QAl[row][fs + 8] = make_uint4(l[4], l[5], l[6], l[7]);
#pragma unroll
        for (int u = 0; u < 4; u++) {
            float4 v = *(const float4*)(kp + u * 4);
            split2(v.x, v.y, h[2 * u], l[2 * u]);
            split2(v.z, v.w, h[2 * u + 1], l[2 * u + 1]);
        }
        *(uint4*)&KBh[row][fs] = make_uint4(h[0], h[1], h[2], h[3]);
        *(uint4*)&KBh[row][fs + 8] = make_uint4(h[4], h[5], h[6], h[7]);
        *(uint4*)&KBl[row][fs] = make_uint4(l[0], l[1], l[2], l[3]);
        *(uint4*)&KBl[row][fs + 8] = make_uint4(l[4], l[5], l[6], l[7]);
    }
    __syncthreads();

    int wl = wid >> 1, wc = wid & 1;
    uint32_t aoff = (uint32_t)((wl * 32 + (lane & 7) + ((lane >> 3) & 1) * 8) * 80 +
                               (lane >> 4) * 16);
    uint32_t boff = (uint32_t)((wc * 64 + (lane & 7) + ((lane >> 4) & 1) * 8) * 80 +
                               ((lane >> 3) & 1) * 16);
    uint32_t ah_b = smem_u32(QAh) + aoff, al_b = smem_u32(QAl) + aoff;
    uint32_t bh_b = smem_u32(KBh) + boff, bl_b = smem_u32(KBl) + boff;

    float acc[2][8][4];
#pragma unroll
    for (int i = 0; i < 2; i++)
#pragma unroll
        for (int n = 0; n < 8; n++)
#pragma unroll
            for (int q = 0; q < 4; q++) acc[i][n][q] = 0.f;

#pragma unroll
    for (int kc = 0; kc < 2; kc++) {
        uint ah[2][4], al2[2][4];
#pragma unroll
        for (int ln = 0; ln < 2; ln++) {
            ldsm4(ah_b + kc * 32 + ln * 16 * 80, ah[ln][0], ah[ln][1], ah[ln][2], ah[ln][3]);
            ldsm4(al_b + kc * 32 + ln * 16 * 80, al2[ln][0], al2[ln][1], al2[ln][2], al2[ln][3]);
        }
#pragma unroll
        for (int p = 0; p < 4; p++) {
            uint bh0, bh1, bh2, bh3, bl0, bl1, bl2, bl3;
            ldsm4(bh_b + kc * 32 + p * 16 * 80, bh0, bh1, bh2, bh3);
            ldsm4(bl_b + kc * 32 + p * 16 * 80, bl0, bl1, bl2, bl3);
#pragma unroll
            for (int ln = 0; ln < 2; ln++) {
                mma16816(acc[ln][2 * p], ah[ln][0], ah[ln][1], ah[ln][2], ah[ln][3], bh0, bh1);
                mma16816(acc[ln][2 * p], ah[ln][0], ah[ln][1], ah[ln][2], ah[ln][3], bl0, bl1);
                mma16816(acc[ln][2 * p], al2[ln][0], al2[ln][1], al2[ln][2], al2[ln][3], bh0, bh1);
                mma16816(acc[ln][2 * p + 1], ah[ln][0], ah[ln][1], ah[ln][2], ah[ln][3], bh2, bh3);
                mma16816(acc[ln][2 * p + 1], ah[ln][0], ah[ln][1], ah[ln][2], ah[ln][3], bl2, bl3);
                mma16816(acc[ln][2 * p + 1], al2[ln][0], al2[ln][1], al2[ln][2], al2[ln][3], bh2, bh3);
            }
        }
    }

#pragma unroll
    for (int i = 0; i < 2; i++)
#pragma unroll
        for (int n = 0; n < 8; n++)
#pragma unroll
            for (int q = 0; q < 4; q++) acc[i][n][q] = __expf(acc[i][n][q]);

    unsigned short* ehb = g_eh + (size_t)b * Sn * Dn;
    unsigned short* elb = g_el + (size_t)b * Sn * Dn;
#pragma unroll
    for (int ln = 0; ln < 2; ln++) {
        int r0 = l0 + wl * 32 + ln * 16 + (lane >> 2);
#pragma unroll
        for (int n = 0; n < 8; n++) {
            int c = j0 + wc * 64 + n * 8 + (lane & 3) * 2;
            uint h01, l01, h23, l23;
            split2(acc[ln][n][0], acc[ln][n][1], h01, l01);
            split2(acc[ln][n][2], acc[ln][n][3], h23, l23);
            *(uint*)(ehb + (size_t)r0 * Dn + c) = h01;
            *(uint*)(elb + (size_t)r0 * Dn + c) = l01;
            *(uint*)(ehb + (size_t)(r0 + 8) * Dn + c) = h23;
            *(uint*)(elb + (size_t)(r0 + 8) * Dn + c) = l23;
        }
    }

#pragma unroll
    for (int n = 0; n < 8; n++) {
        float s0 = acc[0][n][0] + acc[0][n][2] + acc[1][n][0] + acc[1][n][2];
        float s1 = acc[0][n][1] + acc[0][n][3] + acc[1][n][1] + acc[1][n][3];
        s0 += __shfl_xor_sync(0xffffffffu, s0, 4);
        s0 += __shfl_xor_sync(0xffffffffu, s0, 8);
        s0 += __shfl_xor_sync(0xffffffffu, s0, 16);
        s1 += __shfl_xor_sync(0xffffffffu, s1, 4);
        s1 += __shfl_xor_sync(0xffffffffu, s1, 8);
        s1 += __shfl_xor_sync(0xffffffffu, s1, 16);
        if ((lane >> 2) == 0) {
            int cl = wc * 64 + n * 8 + (lane & 3) * 2;
            sm_cp[wl][cl] = s0;
            sm_cp[wl][cl + 1] = s1;
        }
    }
    __syncthreads();
    if (t < 128) {
        float cs = sm_cp[0][t] + sm_cp[1][t] + sm_cp[2][t] + sm_cp[3][t];
        atomicAdd(&g_colsum[b * Dn + j0 + t], cs);
    }
}

// ---------------------------------------------------------------------------
// applied GEMM, 4-stage cp.async pipeline, pure-copy loaders:
//   app[128l x 128c] = sum_j e[l,j] * vn[j,c]   (both pre-split bf16 hi/lo)
// Dynamic smem 83968 B.  grid (Sn/128, Bn)
// ---------------------------------------------------------------------------
#define AP_AH 0
#define AP_AL 24576
#define AP_BH 49152
#define AP_BL 66560
#define AP_SMEM 83968
#define AP_ASTG 6144   // 128*48
#define AP_BSTG 4352   // 16*272

__global__ __launch_bounds__(256) void applied_hmma_k() {
    extern __shared__ __align__(16) char dsm[];
    uint32_t sb = smem_u32(dsm);

    int t = threadIdx.x, lane = t & 31, wid = t >> 5;
    int b = blockIdx.y, l0 = blockIdx.x * 128;

    int arow = t >> 1, ak = (t & 1) * 8;
    const unsigned short* ahg = g_eh + (size_t)b * Sn * Dn + (size_t)(l0 + arow) * Dn + ak;
    const unsigned short* alg = g_el + (size_t)b * Sn * Dn + (size_t)(l0 + arow) * Dn + ak;
    int bj = t >> 4, bc = (t & 15) * 8;
    const unsigned short* bhg = g_vhn + (size_t)b * C2 * Dn + (size_t)bj * C2 + bc;
    const unsigned short* blg = g_vln + (size_t)b * C2 * Dn + (size_t)bj * C2 + bc;

    uint32_t a_dst = sb + (uint32_t)(arow * 48 + (t & 1) * 16);
    uint32_t b_dst = sb + (uint32_t)(bj * 272 + bc * 2);

    int wl = wid >> 1, wc = wid & 1;
    uint32_t a_off = (uint32_t)((wl * 32 + (lane & 7) + ((lane >> 3) & 1) * 8) * 48 +
                                ((lane >> 4) * 8) * 2);
    uint32_t b_off = (uint32_t)(((lane & 7) + ((lane >> 3) & 1) * 8) * 272 +
                                (wc * 64 + (lane >> 4) * 8) * 2);

    float acc[2][8][4];
#pragma unroll
    for (int i = 0; i < 2; i++)
#pragma unroll
        for (int n = 0; n < 8; n++)
#pragma unroll
            for (int q = 0; q < 4; q++) acc[i][n][q] = 0.f;

    // prologue: stages 0..2
#pragma unroll
    for (int p = 0; p < 3; p++) {
        cp16(a_dst + AP_AH + p * AP_ASTG, ahg + p * 16);
        cp16(a_dst + AP_AL + p * AP_ASTG, alg + p * 16);
        cp16(b_dst + AP_BH + p * AP_BSTG, bhg + (size_t)p * 16 * C2);
        cp16(b_dst + AP_BL + p * AP_BSTG, blg + (size_t)p * 16 * C2);
        CP_COMMIT();
    }

    for (int ch = 0; ch < 64; ch++) {
        int st = ch & 3;
        CP_WAIT2();
        __syncthreads();

        // issue loads for ch+3 into the stage consumed at ch-1
        if (ch + 3 < 64) {
            int ns = (ch + 3) & 3;
            cp16(a_dst + AP_AH + ns * AP_ASTG, ahg + (ch + 3) * 16);
            cp16(a_dst + AP_AL + ns * AP_ASTG, alg + (ch + 3) * 16);
            cp16(b_dst + AP_BH + ns * AP_BSTG, bhg + (size_t)(ch + 3) * 16 * C2);
            cp16(b_dst + AP_BL + ns * AP_BSTG, blg + (size_t)(ch + 3) * 16 * C2);
        }
        CP_COMMIT();

        uint32_t ah_base = sb + AP_AH + st * AP_ASTG + a_off;
        uint32_t al_base = sb + AP_AL + st * AP_ASTG + a_off;
        uint32_t bh_base = sb + AP_BH + st * AP_BSTG + b_off;
        uint32_t bl_base = sb + AP_BL + st * AP_BSTG + b_off;

        uint ah[2][4], al2[2][4];
#pragma unroll
        for (int ln = 0; ln < 2; ln++) {
            ldsm4(ah_base + ln * 16 * 48, ah[ln][0], ah[ln][1], ah[ln][2], ah[ln][3]);
            ldsm4(al_base + ln * 16 * 48, al2[ln][0], al2[ln][1], al2[ln][2], al2[ln][3]);
        }
#pragma unroll
        for (int nn = 0; nn < 4; nn++) {
            uint bh0, bh1, bh2, bh3, bl0, bl1, bl2, bl3;
            ldsm4t(bh_base + nn * 32, bh0, bh1, bh2, bh3);
            ldsm4t(bl_base + nn * 32, bl0, bl1, bl2, bl3);
#pragma unroll
            for (int ln = 0; ln < 2; ln++) {
                mma16816(acc[ln][2 * nn], ah[ln][0], ah[ln][1], ah[ln][2], ah[ln][3], bh0, bh1);
                mma16816(acc[ln][2 * nn], ah[ln][0], ah[ln][1], ah[ln][2], ah[ln][3], bl0, bl1);
                mma16816(acc[ln][2 * nn], al2[ln][0], al2[ln][1], al2[ln][2], al2[ln][3], bh0, bh1);
                mma16816(acc[ln][2 * nn + 1], ah[ln][0], ah[ln][1], ah[ln][2], ah[ln][3], bh2, bh3);
                mma16816(acc[ln][2 * nn + 1], ah[ln][0], ah[ln][1], ah[ln][2], ah[ln][3], bl2, bl3);
                mma16816(acc[ln][2 * nn + 1], al2[ln][0], al2[ln][1], al2[ln][2], al2[ln][3], bh2, bh3);
            }
        }
    }

    // epilogue: write app pre-split (identical values to splitting downstream)
    unsigned short* aphb = g_aph + (size_t)b * Sn * C2;
    unsigned short* aplb = g_apl + (size_t)b * Sn * C2;
#pragma unroll
    for (int ln = 0; ln < 2; ln++) {
        int r0 = l0 + wl * 32 + ln * 16 + (lane >> 2);
#pragma unroll
        for (int n = 0; n < 8; n++) {
            int c = wc * 64 + n * 8 + (lane & 3) * 2;
            uint h01, l01, h23, l23;
            split2(acc[ln][n][0], acc[ln][n][1], h01, l01);
            split2(acc[ln][n][2], acc[ln][n][3], h23, l23);
            *(uint*)(aphb + (size_t)r0 * C2 + c) = h01;
            *(uint*)(aplb + (size_t)r0 * C2 + c) = l01;
            *(uint*)(aphb + (size_t)(r0 + 8) * C2 + c) = h23;
            *(uint*)(aplb + (size_t)(r0 + 8) * C2 + c) = l23;
        }
    }
}

// ---------------------------------------------------------------------------
// output conv + residual, 4-stage cp.async, pure-copy loaders.
// A = w2 pre-split, B = app pre-split (flat [co*4096+sp] view).
// grid (Sn/128, Cc/128, Bn)
// ---------------------------------------------------------------------------
__global__ __launch_bounds__(256) void out_conv_hmma_k(
    const float* __restrict__ x, const float* __restrict__ b2,
    const float* __restrict__ gamma, float* __restrict__ out) {
    extern __shared__ __align__(16) char dsm[];
    uint32_t sb = smem_u32(dsm);

    int t = threadIdx.x, lane = t & 31, wid = t >> 5;
    int b = blockIdx.z, o0 = blockIdx.y * 128, sp0 = blockIdx.x * 128;

    int arow = t >> 1, ak = (t & 1) * 8;
    const unsigned short* whg = g_w2h + (size_t)(o0 + arow) * C2 + ak;
    const unsigned short* wlg = g_w2l + (size_t)(o0 + arow) * C2 + ak;
    int bkk = t >> 4, bsg = (t & 15) * 8;
    const unsigned short* aphg = g_aph + (size_t)b * Sn * C2 + (size_t)bkk * Sn + sp0 + bsg;
    const unsigned short* aplg = g_apl + (size_t)b * Sn * C2 + (size_t)bkk * Sn + sp0 + bsg;

    uint32_t a_dst = sb + (uint32_t)(arow * 48 + (t & 1) * 16);
    uint32_t b_dst = sb + (uint32_t)(bkk * 272 + bsg * 2);

    int wl = wid >> 1, wc = wid & 1;
    uint32_t a_off = (uint32_t)((wl * 32 + (lane & 7) + ((lane >> 3) & 1) * 8) * 48 +
                                ((lane >> 4) * 8) * 2);
    uint32_t b_off = (uint32_t)(((lane & 7) + ((lane >> 3) & 1) * 8) * 272 +
                                (wc * 64 + (lane >> 4) * 8) * 2);

    float acc[2][8][4];
#pragma unroll
    for (int i = 0; i < 2; i++)
#pragma unroll
        for (int n = 0; n < 8; n++)
#pragma unroll
            for (int q = 0; q < 4; q++) acc[i][n][q] = 0.f;

#pragma unroll
    for (int p = 0; p < 3; p++) {
        cp16(a_dst + AP_AH + p * AP_ASTG, whg + p * 16);
        cp16(a_dst + AP_AL + p * AP_ASTG, wlg + p * 16);
        cp16(b_dst + AP_BH + p * AP_BSTG, aphg + (size_t)p * 16 * Sn);
        cp16(b_dst + AP_BL + p * AP_BSTG, aplg + (size_t)p * 16 * Sn);
        CP_COMMIT();
    }

    for (int ch = 0; ch < 8; ch++) {
        int st = ch & 3;
        CP_WAIT2();
        __syncthreads();

        if (ch + 3 < 8) {
            int ns = (ch + 3) & 3;
            cp16(a_dst + AP_AH + ns * AP_ASTG, whg + (ch + 3) * 16);
            cp16(a_dst + AP_AL + ns * AP_ASTG, wlg + (ch + 3) * 16);
            cp16(b_dst + AP_BH + ns * AP_BSTG, aphg + (size_t)(ch + 3) * 16 * Sn);
            cp16(b_dst + AP_BL + ns * AP_BSTG, aplg + (size_t)(ch + 3) * 16 * Sn);
        }
        CP_COMMIT();

        uint32_t ah_base = sb + AP_AH + st * AP_ASTG + a_off;
        uint32_t al_base = sb + AP_AL + st * AP_ASTG + a_off;
        uint32_t bh_base = sb + AP_BH + st * AP_BSTG + b_off;
        uint32_t bl_base = sb + AP_BL + st * AP_BSTG + b_off;

        uint ah[2][4], al2[2][4];
#pragma unroll
        for (int ln = 0; ln < 2; ln++) {
            ldsm4(ah_base + ln * 16 * 48, ah[ln][0], ah[ln][1], ah[ln][2], ah[ln][3]);
            ldsm4(al_base + ln * 16 * 48, al2[ln][0], al2[ln][1], al2[ln][2], al2[ln][3]);
        }
#pragma unroll
        for (int nn = 0; nn < 4; nn++) {
            uint bh0, bh1, bh2, bh3, bl0, bl1, bl2, bl3;
            ldsm4t(bh_base + nn * 32, bh0, bh1, bh2, bh3);
            ldsm4t(bl_base + nn * 32, bl0, bl1, bl2, bl3);
#pragma unroll
            for (int ln = 0; ln < 2; ln++) {
                mma16816(acc[ln][2 * nn], ah[ln][0], ah[ln][1], ah[ln][2], ah[ln][3], bh0, bh1);
                mma16816(acc[ln][2 * nn], ah[ln][0], ah[ln][1], ah[ln][2], ah[ln][3], bl0, bl1);
                mma16816(acc[ln][2 * nn], al2[ln][0], al2[ln][1], al2[ln][2], al2[ln][3], bh0, bh1);
                mma16816(acc[ln][2 * nn + 1], ah[ln][0], ah[ln][1], ah[ln][2], ah[ln][3], bh2, bh3);
                mma16816(acc[ln][2 * nn + 1], ah[ln][0], ah[ln][1], ah[ln][2], ah[ln][3], bl2, bl3);
                mma16816(acc[ln][2 * nn + 1], al2[ln][0], al2[ln][1], al2[ln][2], al2[ln][3], bh2, bh3);
            }
        }
    }

    float g = gamma[0];
#pragma unroll
    for (int ln = 0; ln < 2; ln++) {
        int o1 = o0 + wl * 32 + ln * 16 + (lane >> 2);
        int o2 = o1 + 8;
        float bb1 = b2[o1], bb2 = b2[o2];
#pragma unroll
        for (int n = 0; n < 8; n++) {
            int sp = sp0 + wc * 64 + n * 8 + (lane & 3) * 2;
            const float* x1 = x + (size_t)b * Cc * Sn + (size_t)o1 * Sn + sp;
            const float* x2 = x + (size_t)b * Cc * Sn + (size_t)o2 * Sn + sp;
            float* y1 = out + (size_t)b * Cc * Sn + (size_t)o1 * Sn + sp;
            float* y2 = out + (size_t)b * Cc * Sn + (size_t)o2 * Sn + sp;
            float2 xa = *(const float2*)(x1);
            float2 xb = *(const float2*)(x2);
            float2 r1, r2;
            r1.x = fmaf(g, acc[ln][n][0] + bb1, xa.x);
            r1.y = fmaf(g, acc[ln][n][1] + bb1, xa.y);
            r2.x = fmaf(g, acc[ln][n][2] + bb2, xb.x);
            r2.y = fmaf(g, acc[ln][n][3] + bb2, xb.y);
            *(float2*)(y1) = r1;
            *(float2*)(y2) = r2;
        }
    }
}

// ---------------------------------------------------------------------------
extern "C" void kernel_launch(void* const* d_in, const int* in_sizes, int n_in,
                              void* d_out, int out_size) {
    const float* x   = (const float*)d_in[0];
    const float* qw  = (const float*)d_in[1];
    const float* qb  = (const float*)d_in[2];
    const float* kw  = (const float*)d_in[3];
    const float* kb  = (const float*)d_in[4];
    const float* vw  = (const float*)d_in[5];
    const float* vb  = (const float*)d_in[6];
    const float* v2w = (const float*)d_in[7];
    const float* v2b = (const float*)d_in[8];
    const float* gm  = (const float*)d_in[9];
    float* out = (float*)d_out;

    static int smem_set = 0;
    if (!smem_set) {
        cudaFuncSetAttribute(applied_hmma_k,
                             cudaFuncAttributeMaxDynamicSharedMemorySize, AP_SMEM);
        cudaFuncSetAttribute(out_conv_hmma_k,
                             cudaFuncAttributeMaxDynamicSharedMemorySize, AP_SMEM);
        smem_set = 1;
    }

    conv_all_k<<<dim3(32, 3, Bn), 128>>>(x, qw, qb, kw, kb, vw, vb);
    zero_k<<<Bn * Dn / 1024, 1024>>>();
    wsplit_k<<<(Cc * C2 / 8) / 256, 256>>>(v2w);
    attn_hmma_k<<<dim3(Dn / 128, Sn / 128, Bn), 256>>>();
    recip_k<<<Bn * Dn / 1024, 1024>>>();
    vsplit_k<<<(Bn * C2 * Dn / 8) / 256, 256>>>();
    applied_hmma_k<<<dim3(Sn / 128, Bn), 256, AP_SMEM>>>();
    out_conv_hmma_k<<<dim3(Sn / 128, Cc / 128, Bn), 256, AP_SMEM>>>(x, v2b, gm, out);
}

// round 11
// speedup vs baseline: 2.3765x; 1.1871x over previous
#include <cuda_runtime.h>
#include <cuda_bf16.h>
#include <cstdint>

#define Bn 16
#define Cc 256
#define Sn 4096   // H*W
#define C8 32     // C/8
#define C2 128    // C/2
#define Dn 1024   // down = HW/4

typedef unsigned long long ull;
typedef unsigned int uint;

// ---- packed fp32x2 helpers ----
__device__ __forceinline__ ull ffma2(ull a, ull b, ull c) {
    ull d;
    asm("fma.rn.f32x2 %0, %1, %2, %3;" : "=l"(d) : "l"(a), "l"(b), "l"(c));
    return d;
}
__device__ __forceinline__ ull dup2(float v) {
    ull d;
    asm("mov.b64 %0, {%1, %1};" : "=l"(d) : "f"(v));
    return d;
}

// ---- mma/ldmatrix/cp.async helpers ----
__device__ __forceinline__ uint32_t smem_u32(const void* p) {
    uint32_t a;
    asm("{ .reg .u64 t; cvta.to.shared.u64 t, %1; cvt.u32.u64 %0, t; }" : "=r"(a) : "l"(p));
    return a;
}
__device__ __forceinline__ void ldsm4(uint32_t a, uint& r0, uint& r1, uint& r2, uint& r3) {
    asm volatile("ldmatrix.sync.aligned.m8n8.x4.shared.b16 {%0,%1,%2,%3}, [%4];"
                 : "=r"(r0), "=r"(r1), "=r"(r2), "=r"(r3) : "r"(a));
}
__device__ __forceinline__ void ldsm4t(uint32_t a, uint& r0, uint& r1, uint& r2, uint& r3) {
    asm volatile("ldmatrix.sync.aligned.m8n8.x4.trans.shared.b16 {%0,%1,%2,%3}, [%4];"
                 : "=r"(r0), "=r"(r1), "=r"(r2), "=r"(r3) : "r"(a));
}
__device__ __forceinline__ void mma16816(float* d, uint a0, uint a1, uint a2, uint a3,
                                         uint b0, uint b1) {
    asm volatile(
        "mma.sync.aligned.m16n8k16.row.col.f32.bf16.bf16.f32 "
        "{%0,%1,%2,%3}, {%4,%5,%6,%7}, {%8,%9}, {%0,%1,%2,%3};"
        : "+f"(d[0]), "+f"(d[1]), "+f"(d[2]), "+f"(d[3])
        : "r"(a0), "r"(a1), "r"(a2), "r"(a3), "r"(b0), "r"(b1));
}
__device__ __forceinline__ void cp16(uint32_t s, const void* g) {
    asm volatile("cp.async.ca.shared.global [%0], [%1], 16;" :: "r"(s), "l"(g));
}
#define CP_COMMIT() asm volatile("cp.async.commit_group;")
#define CP_WAIT2() asm volatile("cp.async.wait_group 2;")

// split fp32 pair -> packed bf16 hi-pair / lo-pair
__device__ __forceinline__ void split2(float x, float y, uint& hi, uint& lo) {
    __nv_bfloat16 hx = __float2bfloat16_rn(x), hy = __float2bfloat16_rn(y);
    float rx = x - __bfloat162float(hx), ry = y - __bfloat162float(hy);
    __nv_bfloat16 lx = __float2bfloat16_rn(rx), ly = __float2bfloat16_rn(ry);
    __nv_bfloat162 hp, lp;
    hp.x = hx; hp.y = hy; lp.x = lx; lp.y = ly;
    hi = *(uint*)&hp;
    lo = *(uint*)&lp;
}
__device__ __forceinline__ uint pack_bf16(float x, float y) {
    __nv_bfloat162 p;
    p.x = __float2bfloat16_rn(x);
    p.y = __float2bfloat16_rn(y);
    return *(uint*)&p;
}

// ---- scratch ----
__device__ float g_q[(size_t)Bn * C8 * Sn];
__device__ float g_k[(size_t)Bn * C8 * Dn];
__device__ float g_v[(size_t)Bn * C2 * Dn];
__device__ unsigned short g_eh[(size_t)Bn * Sn * Dn];   // exp(logit) bf16
__device__ unsigned short g_vhn[(size_t)Bn * C2 * Dn];  // crs*v hi
__device__ unsigned short g_vln[(size_t)Bn * C2 * Dn];  // crs*v lo
__device__ unsigned short g_aph[(size_t)Bn * Sn * C2];  // app hi
__device__ unsigned short g_apl[(size_t)Bn * Sn * C2];  // app lo
__device__ unsigned short g_w2h[Cc * C2];               // w2 hi
__device__ unsigned short g_w2l[Cc * C2];               // w2 lo
__device__ float g_colsum[Bn * Dn];
__device__ float g_crs[Bn * Dn];

// ---------------------------------------------------------------------------
// Fused conv: q / k-pooled / v-pooled (unchanged, known-good)
// ---------------------------------------------------------------------------
__global__ __launch_bounds__(128) void conv_all_k(
    const float* __restrict__ x,
    const float* __restrict__ qw, const float* __restrict__ qb,
    const float* __restrict__ kw, const float* __restrict__ kb,
    const float* __restrict__ vw, const float* __restrict__ vb) {
    int b = blockIdx.z, ot = blockIdx.y, st = blockIdx.x;
    int s0 = st * 128;
    int t = threadIdx.x;

    __shared__ __align__(16) union {
        struct { float Ws[2][16][68]; float Xs[2][16][128]; } p;
        float Cs[64][128];
    } sm;

    int wrow = t >> 1;
    int wkg = (t & 1) << 3;
    int gch = ot * 64 + wrow;
    const float* wsrc;
    if (gch < 32) wsrc = qw + (size_t)gch * Cc;
    else if (gch < 64) wsrc = kw + (size_t)(gch - 32) * Cc;
    else wsrc = vw + (size_t)(gch - 64) * Cc;
    wsrc += wkg;

    int xkk = t >> 3;
    int xsg = (t & 7) << 4;
    const float* xsrc = x + (size_t)b * Cc * Sn + (size_t)xkk * Sn + s0 + xsg;

    int ty = t >> 4, tx = t & 15;

    ull acc[8][4];
#pragma unroll
    for (int i = 0; i < 8; i++)
#pragma unroll
        for (int j = 0; j < 4; j++) acc[i][j] = 0ULL;

    {
#pragma unroll
        for (int u = 0; u < 2; u++) {
            float4 v = *(const float4*)(wsrc + u * 4);
            sm.p.Ws[0][wkg + u * 4 + 0][wrow] = v.x;
            sm.p.Ws[0][wkg + u * 4 + 1][wrow] = v.y;
            sm.p.Ws[0][wkg + u * 4 + 2][wrow] = v.z;
            sm.p.Ws[0][wkg + u * 4 + 3][wrow] = v.w;
        }
#pragma unroll
        for (int u = 0; u < 4; u++)
            *(float4*)&sm.p.Xs[0][xkk][xsg + u * 4] = *(const float4*)(xsrc + u * 4);
    }
    __syncthreads();

    for (int ch = 0; ch < 16; ch++) {
        int cb = ch & 1;
        float4 wpre[2], xpre[4];
        if (ch < 15) {
            const float* wp = wsrc + (ch + 1) * 16;
            wpre[0] = *(const float4*)(wp);
            wpre[1] = *(const float4*)(wp + 4);
            const float* xp = xsrc + (size_t)(ch + 1) * 16 * Sn;
#pragma unroll
            for (int u = 0; u < 4; u++) xpre[u] = *(const float4*)(xp + u * 4);
        }
#pragma unroll
        for (int kk = 0; kk < 16; kk++) {
            float4 a0 = *(const float4*)&sm.p.Ws[cb][kk][ty * 8];
            float4 a1 = *(const float4*)&sm.p.Ws[cb][kk][ty * 8 + 4];
            ulonglong2 b0 = *(const ulonglong2*)&sm.p.Xs[cb][kk][tx * 8];
            ulonglong2 b1 = *(const ulonglong2*)&sm.p.Xs[cb][kk][tx * 8 + 4];
            ull bp[4] = {b0.x, b0.y, b1.x, b1.y};
            float aa[8] = {a0.x, a0.y, a0.z, a0.w, a1.x, a1.y, a1.z, a1.w};
#pragma unroll
            for (int i = 0; i < 8; i++) {
                ull ad = dup2(aa[i]);
#pragma unroll
                for (int j = 0; j < 4; j++) acc[i][j] = ffma2(ad, bp[j], acc[i][j]);
            }
        }
        if (ch < 15) {
            int nb = cb ^ 1;
#pragma unroll
            for (int u = 0; u < 2; u++) {
                sm.p.Ws[nb][wkg + u * 4 + 0][wrow] = (&wpre[u].x)[0];
                sm.p.Ws[nb][wkg + u * 4 + 1][wrow] = (&wpre[u].x)[1];
                sm.p.Ws[nb][wkg + u * 4 + 2][wrow] = (&wpre[u].x)[2];
                sm.p.Ws[nb][wkg + u * 4 + 3][wrow] = (&wpre[u].x)[3];
            }
#pragma unroll
            for (int u = 0; u < 4; u++)
                *(float4*)&sm.p.Xs[nb][xkk][xsg + u * 4] = xpre[u];
        }
        __syncthreads();
    }

#pragma unroll
    for (int i = 0; i < 8; i++) {
        ulonglong2 u0, u1;
        u0.x = acc[i][0]; u0.y = acc[i][1];
        u1.x = acc[i][2]; u1.y = acc[i][3];
        *(ulonglong2*)&sm.Cs[ty * 8 + i][tx * 8] = u0;
        *(ulonglong2*)&sm.Cs[ty * 8 + i][tx * 8 + 4] = u1;
    }
    __syncthreads();

    if (ot == 0) {
#pragma unroll
        for (int i = 0; i < 8; i++) {
            int o = i * 4 + (t >> 5);
            int sp = (t & 31) * 4;
            float4 v = *(const float4*)&sm.Cs[o][sp];
            float bb = qb[o];
            v.x += bb; v.y += bb; v.z += bb; v.w += bb;
            *(float4*)(g_q + (size_t)b * C8 * Sn + (size_t)o * Sn + s0 + sp) = v;
        }
        {
            int o = 32 + (t >> 2);
            int qcb = (t & 3) * 8;
            float bb = kb[o - 32];
            float* dst = g_k + (size_t)b * C8 * Dn + (size_t)(o - 32) * Dn + st * 32;
#pragma unroll
            for (int jj = 0; jj < 8; jj++) {
                int qc = qcb + jj;
                float m = fmaxf(fmaxf(sm.Cs[o][2 * qc], sm.Cs[o][2 * qc + 1]),
                                fmaxf(sm.Cs[o][64 + 2 * qc], sm.Cs[o][64 + 2 * qc + 1]));
                dst[qc] = m + bb;
            }
        }
    } else {
        int vg0 = (ot - 1) * 64;
        int o = t >> 1;
        int qcb = (t & 1) * 16;
        float bb = vb[vg0 + o];
        float* dst = g_v + (size_t)b * C2 * Dn + (size_t)(vg0 + o) * Dn + st * 32;
#pragma unroll
        for (int jj = 0; jj < 16; jj++) {
            int qc = qcb + jj;
            float m = fmaxf(fmaxf(sm.Cs[o][2 * qc], sm.Cs[o][2 * qc + 1]),
                            fmaxf(sm.Cs[o][64 + 2 * qc], sm.Cs[o][64 + 2 * qc + 1]));
            dst[qc] = m + bb;
        }
    }
}

// ---------------------------------------------------------------------------
__global__ void zero_k() { g_colsum[blockIdx.x * 1024 + threadIdx.x] = 0.f; }
__global__ void recip_k() {
    int i = blockIdx.x * 1024 + threadIdx.x;
    g_crs[i] = 1.f / g_colsum[i];
}
__global__ void wsplit_k(const float* __restrict__ w2) {
    int idx = (blockIdx.x * 256 + threadIdx.x) * 8;
    float4 v0 = *(const float4*)(w2 + idx);
    float4 v1 = *(const float4*)(w2 + idx + 4);
    uint h[4], l[4];
    split2(v0.x, v0.y, h[0], l[0]);
    split2(v0.z, v0.w, h[1], l[1]);
    split2(v1.x, v1.y, h[2], l[2]);
    split2(v1.z, v1.w, h[3], l[3]);
    *(uint4*)(g_w2h + idx) = make_uint4(h[0], h[1], h[2], h[3]);
    *(uint4*)(g_w2l + idx) = make_uint4(l[0], l[1], l[2], l[3]);
}
__global__ void vsplit_k() {
    int idx = blockIdx.x * 256 + threadIdx.x;
    int lin = idx * 8;
    int b = lin >> 17;
    int rem = lin & (Dn * C2 - 1);
    int j = rem >> 7;
    float rs = g_crs[b * Dn + j];
    const float* vp = g_v + (size_t)b * C2 * Dn + rem;
    float4 v0 = *(const float4*)(vp);
    float4 v1 = *(const float4*)(vp + 4);
    uint h[4], l[4];
    split2(v0.x * rs, v0.y * rs, h[0], l[0]);
    split2(v0.z * rs, v0.w * rs, h[1], l[1]);
    split2(v1.x * rs, v1.y * rs, h[2], l[2]);
    split2(v1.z * rs, v1.w * rs, h[3], l[3]);
    size_t o = (size_t)b * C2 * Dn + rem;
    *(uint4*)(g_vhn + o) = make_uint4(h[0], h[1], h[2], h[3]);
    *(uint4*)(g_vln + o) = make_uint4(l[0], l[1], l[2], l[3]);
}

// ---------------------------------------------------------------------------
// attn logits via split-bf16 HMMA + fused exp epilogue (bf16 E) + column sums.
// grid (Dn/128, Sn/128, Bn)
// ---------------------------------------------------------------------------
__global__ __launch_bounds__(256) void attn_hmma_k() {
    __shared__ __align__(16) unsigned short QAh[128][40], QAl[128][40];
    __shared__ __align__(16) unsigned short KBh[128][40], KBl[128][40];
    __shared__ float sm_cp[4][128];

    int t = threadIdx.x, lane = t & 31, wid = t >> 5;
    int b = blockIdx.z, l0 = blockIdx.y * 128, j0 = blockIdx.x * 128;

    {
        int row = t >> 1, fs = (t & 1) * 16;
        const float* qp = g_q + (size_t)b * C8 * Sn + (size_t)(l0 + row) * 32 + fs;
        const float* kp = g_k + (size_t)b * C8 * Dn + (size_t)(j0 + row) * 32 + fs;
        uint h[8], l[8];
#pragma unroll
        for (int u = 0; u < 4; u++) {
            float4 v = *(const float4*)(qp + u * 4);
            split2(v.x, v.y, h[2 * u], l[2 * u]);
            split2(v.z, v.w, h[2 * u + 1], l[2 * u + 1]);
        }
        *(uint4*)&QAh[row][fs] = make_uint4(h[0], h[1], h[2], h[3]);
        *(uint4*)&QAh[row][fs + 8] = make_uint4(h[4], h[5], h[6], h[7]);
        *(uint4*)&QAl[row][fs] = make_uint4(l[0], l[1], l[2], l[3]);
        *(uint4*)&QAl[row][fs + 8] = make_uint4(l[4], l[5], l[6], l[7]);
#pragma unroll
        for (int u = 0; u < 4; u++) {
            float4 v = *(const float4*)(kp + u * 4);
            split2(v.x, v.y, h[2 * u], l[2 * u]);
            split2(v.z, v.w, h[2 * u + 1], l[2 * u + 1]);
        }
        *(uint4*)&KBh[row][fs] = make_uint4(h[0], h[1], h[2], h[3]);
        *(uint4*)&KBh[row][fs + 8] = make_uint4(h[4], h[5], h[6], h[7]);
        *(uint4*)&KBl[row][fs] = make_uint4(l[0], l[1], l[2], l[3]);
        *(uint4*)&KBl[row][fs + 8] = make_uint4(l[4], l[5], l[6], l[7]);
    }
    __syncthreads();

    int wl = wid >> 1, wc = wid & 1;
    uint32_t aoff = (uint32_t)((wl * 32 + (lane & 7) + ((lane >> 3) & 1) * 8) * 80 +
                               (lane >> 4) * 16);
    uint32_t boff = (uint32_t)((wc * 64 + (lane & 7) + ((lane >> 4) & 1) * 8) * 80 +
                               ((lane >> 3) & 1) * 16);
    uint32_t ah_b = smem_u32(QAh) + aoff, al_b = smem_u32(QAl) + aoff;
    uint32_t bh_b = smem_u32(KBh) + boff, bl_b = smem_u32(KBl) + boff;

    float acc[2][8][4];
#pragma unroll
    for (int i = 0; i < 2; i++)
#pragma unroll
        for (int n = 0; n < 8; n++)
#pragma unroll
            for (int q = 0; q < 4; q++) acc[i][n][q] = 0.f;

#pragma unroll
    for (int kc = 0; kc < 2; kc++) {
        uint ah[2][4], al2[2][4];
#pragma unroll
        for (int ln = 0; ln < 2; ln++) {
            ldsm4(ah_b + kc * 32 + ln * 16 * 80, ah[ln][0], ah[ln][1], ah[ln][2], ah[ln][3]);
            ldsm4(al_b + kc * 32 + ln * 16 * 80, al2[ln][0], al2[ln][1], al2[ln][2], al2[ln][3]);
        }
#pragma unroll
        for (int p = 0; p < 4; p++) {
            uint bh0, bh1, bh2, bh3, bl0, bl1, bl2, bl3;
            ldsm4(bh_b + kc * 32 + p * 16 * 80, bh0, bh1, bh2, bh3);
            ldsm4(bl_b + kc * 32 + p * 16 * 80, bl0, bl1, bl2, bl3);
#pragma unroll
            for (int ln = 0; ln < 2; ln++) {
                mma16816(acc[ln][2 * p], ah[ln][0], ah[ln][1], ah[ln][2], ah[ln][3], bh0, bh1);
                mma16816(acc[ln][2 * p], ah[ln][0], ah[ln][1], ah[ln][2], ah[ln][3], bl0, bl1);
                mma16816(acc[ln][2 * p], al2[ln][0], al2[ln][1], al2[ln][2], al2[ln][3], bh0, bh1);
                mma16816(acc[ln][2 * p + 1], ah[ln][0], ah[ln][1], ah[ln][2], ah[ln][3], bh2, bh3);
                mma16816(acc[ln][2 * p + 1], ah[ln][0], ah[ln][1], ah[ln][2], ah[ln][3], bl2, bl3);
                mma16816(acc[ln][2 * p + 1], al2[ln][0], al2[ln][1], al2[ln][2], al2[ln][3], bh2, bh3);
            }
        }
    }

#pragma unroll
    for (int i = 0; i < 2; i++)
#pragma unroll
        for (int n = 0; n < 8; n++)
#pragma unroll
            for (int q = 0; q < 4; q++) acc[i][n][q] = __expf(acc[i][n][q]);

    unsigned short* ehb = g_eh + (size_t)b * Sn * Dn;
#pragma unroll
    for (int ln = 0; ln < 2; ln++) {
        int r0 = l0 + wl * 32 + ln * 16 + (lane >> 2);
#pragma unroll
        for (int n = 0; n < 8; n++) {
            int c = j0 + wc * 64 + n * 8 + (lane & 3) * 2;
            *(uint*)(ehb + (size_t)r0 * Dn + c) = pack_bf16(acc[ln][n][0], acc[ln][n][1]);
            *(uint*)(ehb + (size_t)(r0 + 8) * Dn + c) = pack_bf16(acc[ln][n][2], acc[ln][n][3]);
        }
    }

#pragma unroll
    for (int n = 0; n < 8; n++) {
        float s0 = acc[0][n][0] + acc[0][n][2] + acc[1][n][0] + acc[1][n][2];
        float s1 = acc[0][n][1] + acc[0][n][3] + acc[1][n][1] + acc[1][n][3];
        s0 += __shfl_xor_sync(0xffffffffu, s0, 4);
        s0 += __shfl_xor_sync(0xffffffffu, s0, 8);
        s0 += __shfl_xor_sync(0xffffffffu, s0, 16);
        s1 += __shfl_xor_sync(0xffffffffu, s1, 4);
        s1 += __shfl_xor_sync(0xffffffffu, s1, 8);
        s1 += __shfl_xor_sync(0xffffffffu, s1, 16);
        if ((lane >> 2) == 0) {
            int cl = wc * 64 + n * 8 + (lane & 3) * 2;
            sm_cp[wl][cl] = s0;
            sm_cp[wl][cl + 1] = s1;
        }
    }
    __syncthreads();
    if (t < 128) {
        float cs = sm_cp[0][t] + sm_cp[1][t] + sm_cp[2][t] + sm_cp[3][t];
        atomicAdd(&g_colsum[b * Dn + j0 + t], cs);
    }
}

// ---------------------------------------------------------------------------
// applied GEMM, 4-stage cp.async, A = bf16 E (single), B = split crs*v:
//   app[128l x 128c] = sum_j e[l,j] * vn[j,c]
// 2 MMAs per sub-tile (ah*bh + ah*bl).  Dynamic smem 59392 B.
// grid (Sn/128, Bn)
// ---------------------------------------------------------------------------
#define AP_AH 0
#define AP_BH 24576
#define AP_BL 41984
#define AP_SMEM 59392
#define AP_ASTG 6144   // 128*48
#define AP_BSTG 4352   // 16*272

__global__ __launch_bounds__(256) void applied_hmma_k() {
    extern __shared__ __align__(16) char dsm[];
    uint32_t sb = smem_u32(dsm);

    int t = threadIdx.x, lane = t & 31, wid = t >> 5;
    int b = blockIdx.y, l0 = blockIdx.x * 128;

    int arow = t >> 1, ak = (t & 1) * 8;
    const unsigned short* ahg = g_eh + (size_t)b * Sn * Dn + (size_t)(l0 + arow) * Dn + ak;
    int bj = t >> 4, bc = (t & 15) * 8;
    const unsigned short* bhg = g_vhn + (size_t)b * C2 * Dn + (size_t)bj * C2 + bc;
    const unsigned short* blg = g_vln + (size_t)b * C2 * Dn + (size_t)bj * C2 + bc;

    uint32_t a_dst = sb + (uint32_t)(arow * 48 + (t & 1) * 16);
    uint32_t b_dst = sb + (uint32_t)(bj * 272 + bc * 2);

    int wl = wid >> 1, wc = wid & 1;
    uint32_t a_off = (uint32_t)((wl * 32 + (lane & 7) + ((lane >> 3) & 1) * 8) * 48 +
                                ((lane >> 4) * 8) * 2);
    uint32_t b_off = (uint32_t)(((lane & 7) + ((lane >> 3) & 1) * 8) * 272 +
                                (wc * 64 + (lane >> 4) * 8) * 2);

    float acc[2][8][4];
#pragma unroll
    for (int i = 0; i < 2; i++)
#pragma unroll
        for (int n = 0; n < 8; n++)
#pragma unroll
            for (int q = 0; q < 4; q++) acc[i][n][q] = 0.f;

#pragma unroll
    for (int p = 0; p < 3; p++) {
        cp16(a_dst + AP_AH + p * AP_ASTG, ahg + p * 16);
        cp16(b_dst + AP_BH + p * AP_BSTG, bhg + (size_t)p * 16 * C2);
        cp16(b_dst + AP_BL + p * AP_BSTG, blg + (size_t)p * 16 * C2);
        CP_COMMIT();
    }

    for (int ch = 0; ch < 64; ch++) {
        int st = ch & 3;
        CP_WAIT2();
        __syncthreads();

        if (ch + 3 < 64) {
            int ns = (ch + 3) & 3;
            cp16(a_dst + AP_AH + ns * AP_ASTG, ahg + (ch + 3) * 16);
            cp16(b_dst + AP_BH + ns * AP_BSTG, bhg + (size_t)(ch + 3) * 16 * C2);
            cp16(b_dst + AP_BL + ns * AP_BSTG, blg + (size_t)(ch + 3) * 16 * C2);
        }
        CP_COMMIT();

        uint32_t ah_base = sb + AP_AH + st * AP_ASTG + a_off;
        uint32_t bh_base = sb + AP_BH + st * AP_BSTG + b_off;
        uint32_t bl_base = sb + AP_BL + st * AP_BSTG + b_off;

        uint ah[2][4];
#pragma unroll
        for (int ln = 0; ln < 2; ln++)
            ldsm4(ah_base + ln * 16 * 48, ah[ln][0], ah[ln][1], ah[ln][2], ah[ln][3]);
#pragma unroll
        for (int nn = 0; nn < 4; nn++) {
            uint bh0, bh1, bh2, bh3, bl0, bl1, bl2, bl3;
            ldsm4t(bh_base + nn * 32, bh0, bh1, bh2, bh3);
            ldsm4t(bl_base + nn * 32, bl0, bl1, bl2, bl3);
#pragma unroll
            for (int ln = 0; ln < 2; ln++) {
                mma16816(acc[ln][2 * nn], ah[ln][0], ah[ln][1], ah[ln][2], ah[ln][3], bh0, bh1);
                mma16816(acc[ln][2 * nn], ah[ln][0], ah[ln][1], ah[ln][2], ah[ln][3], bl0, bl1);
                mma16816(acc[ln][2 * nn + 1], ah[ln][0], ah[ln][1], ah[ln][2], ah[ln][3], bh2, bh3);
                mma16816(acc[ln][2 * nn + 1], ah[ln][0], ah[ln][1], ah[ln][2], ah[ln][3], bl2, bl3);
            }
        }
    }

    unsigned short* aphb = g_aph + (size_t)b * Sn * C2;
    unsigned short* aplb = g_apl + (size_t)b * Sn * C2;
#pragma unroll
    for (int ln = 0; ln < 2; ln++) {
        int r0 = l0 + wl * 32 + ln * 16 + (lane >> 2);
#pragma unroll
        for (int n = 0; n < 8; n++) {
            int c = wc * 64 + n * 8 + (lane & 3) * 2;
            uint h01, l01, h23, l23;
            split2(acc[ln][n][0], acc[ln][n][1], h01, l01);
            split2(acc[ln][n][2], acc[ln][n][3], h23, l23);
            *(uint*)(aphb + (size_t)r0 * C2 + c) = h01;
            *(uint*)(aplb + (size_t)r0 * C2 + c) = l01;
            *(uint*)(aphb + (size_t)(r0 + 8) * C2 + c) = h23;
            *(uint*)(aplb + (size_t)(r0 + 8) * C2 + c) = l23;
        }
    }
}

// ---------------------------------------------------------------------------
// output conv + residual, 4-stage cp.async (unchanged from R10).
// grid (Sn/128, Cc/128, Bn)
// ---------------------------------------------------------------------------
#define OC_AH 0
#define OC_AL 24576
#define OC_BH 49152
#define OC_BL 66560
#define OC_SMEM 83968

__global__ __launch_bounds__(256) void out_conv_hmma_k(
    const float* __restrict__ x, const float* __restrict__ b2,
    const float* __restrict__ gamma, float* __restrict__ out) {
    extern __shared__ __align__(16) char dsm[];
    uint32_t sb = smem_u32(dsm);

    int t = threadIdx.x, lane = t & 31, wid = t >> 5;
    int b = blockIdx.z, o0 = blockIdx.y * 128, sp0 = blockIdx.x * 128;

    int arow = t >> 1, ak = (t & 1) * 8;
    const unsigned short* whg = g_w2h + (size_t)(o0 + arow) * C2 + ak;
    const unsigned short* wlg = g_w2l + (size_t)(o0 + arow) * C2 + ak;
    int bkk = t >> 4, bsg = (t & 15) * 8;
    const unsigned short* aphg = g_aph + (size_t)b * Sn * C2 + (size_t)bkk * Sn + sp0 + bsg;
    const unsigned short* aplg = g_apl + (size_t)b * Sn * C2 + (size_t)bkk * Sn + sp0 + bsg;

    uint32_t a_dst = sb + (uint32_t)(arow * 48 + (t & 1) * 16);
    uint32_t b_dst = sb + (uint32_t)(bkk * 272 + bsg * 2);

    int wl = wid >> 1, wc = wid & 1;
    uint32_t a_off = (uint32_t)((wl * 32 + (lane & 7) + ((lane >> 3) & 1) * 8) * 48 +
                                ((lane >> 4) * 8) * 2);
    uint32_t b_off = (uint32_t)(((lane & 7) + ((lane >> 3) & 1) * 8) * 272 +
                                (wc * 64 + (lane >> 4) * 8) * 2);

    float acc[2][8][4];
#pragma unroll
    for (int i = 0; i < 2; i++)
#pragma unroll
        for (int n = 0; n < 8; n++)
#pragma unroll
            for (int q = 0; q < 4; q++) acc[i][n][q] = 0.f;

#pragma unroll
    for (int p = 0; p < 3; p++) {
        cp16(a_dst + OC_AH + p * AP_ASTG, whg + p * 16);
        cp16(a_dst + OC_AL + p * AP_ASTG, wlg + p * 16);
        cp16(b_dst + OC_BH + p * AP_BSTG, aphg + (size_t)p * 16 * Sn);
        cp16(b_dst + OC_BL + p * AP_BSTG, aplg + (size_t)p * 16 * Sn);
        CP_COMMIT();
    }

    for (int ch = 0; ch < 8; ch++) {
        int st = ch & 3;
        CP_WAIT2();
        __syncthreads();

        if (ch + 3 < 8) {
            int ns = (ch + 3) & 3;
            cp16(a_dst + OC_AH + ns * AP_ASTG, whg + (ch + 3) * 16);
            cp16(a_dst + OC_AL + ns * AP_ASTG, wlg + (ch + 3) * 16);
            cp16(b_dst + OC_BH + ns * AP_BSTG, aphg + (size_t)(ch + 3) * 16 * Sn);
            cp16(b_dst + OC_BL + ns * AP_BSTG, aplg + (size_t)(ch + 3) * 16 * Sn);
        }
        CP_COMMIT();

        uint32_t ah_base = sb + OC_AH + st * AP_ASTG + a_off;
        uint32_t al_base = sb + OC_AL + st * AP_ASTG + a_off;
        uint32_t bh_base = sb + OC_BH + st * AP_BSTG + b_off;
        uint32_t bl_base = sb + OC_BL + st * AP_BSTG + b_off;

        uint ah[2][4], al2[2][4];
#pragma unroll
        for (int ln = 0; ln < 2; ln++) {
            ldsm4(ah_base + ln * 16 * 48, ah[ln][0], ah[ln][1], ah[ln][2], ah[ln][3]);
            ldsm4(al_base + ln * 16 * 48, al2[ln][0], al2[ln][1], al2[ln][2], al2[ln][3]);
        }
#pragma unroll
        for (int nn = 0; nn < 4; nn++) {
            uint bh0, bh1, bh2, bh3, bl0, bl1, bl2, bl3;
            ldsm4t(bh_base + nn * 32, bh0, bh1, bh2, bh3);
            ldsm4t(bl_base + nn * 32, bl0, bl1, bl2, bl3);
#pragma unroll
            for (int ln = 0; ln < 2; ln++) {
                mma16816(acc[ln][2 * nn], ah[ln][0], ah[ln][1], ah[ln][2], ah[ln][3], bh0, bh1);
                mma16816(acc[ln][2 * nn], ah[ln][0], ah[ln][1], ah[ln][2], ah[ln][3], bl0, bl1);
                mma16816(acc[ln][2 * nn], al2[ln][0], al2[ln][1], al2[ln][2], al2[ln][3], bh0, bh1);
                mma16816(acc[ln][2 * nn + 1], ah[ln][0], ah[ln][1], ah[ln][2], ah[ln][3], bh2, bh3);
                mma16816(acc[ln][2 * nn + 1], ah[ln][0], ah[ln][1], ah[ln][2], ah[ln][3], bl2, bl3);
                mma16816(acc[ln][2 * nn + 1], al2[ln][0], al2[ln][1], al2[ln][2], al2[ln][3], bh2, bh3);
            }
        }
    }

    float g = gamma[0];
#pragma unroll
    for (int ln = 0; ln < 2; ln++) {
        int o1 = o0 + wl * 32 + ln * 16 + (lane >> 2);
        int o2 = o1 + 8;
        float bb1 = b2[o1], bb2 = b2[o2];
#pragma unroll
        for (int n = 0; n < 8; n++) {
            int sp = sp0 + wc * 64 + n * 8 + (lane & 3) * 2;
            const float* x1 = x + (size_t)b * Cc * Sn + (size_t)o1 * Sn + sp;
            const float* x2 = x + (size_t)b * Cc * Sn + (size_t)o2 * Sn + sp;
            float* y1 = out + (size_t)b * Cc * Sn + (size_t)o1 * Sn + sp;
            float* y2 = out + (size_t)b * Cc * Sn + (size_t)o2 * Sn + sp;
            float2 xa = *(const float2*)(x1);
            float2 xb = *(const float2*)(x2);
            float2 r1, r2;
            r1.x = fmaf(g, acc[ln][n][0] + bb1, xa.x);
            r1.y = fmaf(g, acc[ln][n][1] + bb1, xa.y);
            r2.x = fmaf(g, acc[ln][n][2] + bb2, xb.x);
            r2.y = fmaf(g, acc[ln][n][3] + bb2, xb.y);
            *(float2*)(y1) = r1;
            *(float2*)(y2) = r2;
        }
    }
}

// ---------------------------------------------------------------------------
extern "C" void kernel_launch(void* const* d_in, const int* in_sizes, int n_in,
                              void* d_out, int out_size) {
    const float* x   = (const float*)d_in[0];
    const float* qw  = (const float*)d_in[1];
    const float* qb  = (const float*)d_in[2];
    const float* kw  = (const float*)d_in[3];
    const float* kb  = (const float*)d_in[4];
    const float* vw  = (const float*)d_in[5];
    const float* vb  = (const float*)d_in[6];
    const float* v2w = (const float*)d_in[7];
    const float* v2b = (const float*)d_in[8];
    const float* gm  = (const float*)d_in[9];
    float* out = (float*)d_out;

    static int smem_set = 0;
    if (!smem_set) {
        cudaFuncSetAttribute(applied_hmma_k,
                             cudaFuncAttributeMaxDynamicSharedMemorySize, AP_SMEM);
        cudaFuncSetAttribute(out_conv_hmma_k,
                             cudaFuncAttributeMaxDynamicSharedMemorySize, OC_SMEM);
        smem_set = 1;
    }

    conv_all_k<<<dim3(32, 3, Bn), 128>>>(x, qw, qb, kw, kb, vw, vb);
    zero_k<<<Bn * Dn / 1024, 1024>>>();
    wsplit_k<<<(Cc * C2 / 8) / 256, 256>>>(v2w);
    attn_hmma_k<<<dim3(Dn / 128, Sn / 128, Bn), 256>>>();
    recip_k<<<Bn * Dn / 1024, 1024>>>();
    vsplit_k<<<(Bn * C2 * Dn / 8) / 256, 256>>>();
    applied_hmma_k<<<dim3(Sn / 128, Bn), 256, AP_SMEM>>>();
    out_conv_hmma_k<<<dim3(Sn / 128, Cc / 128, Bn), 256, OC_SMEM>>>(x, v2b, gm, out);
}

// round 13
// speedup vs baseline: 2.5845x; 1.0875x over previous
#include <cuda_runtime.h>
#include <cuda_bf16.h>
#include <cstdint>

#define Bn 16
#define Cc 256
#define Sn 4096   // H*W
#define C8 32     // C/8
#define C2 128    // C/2
#define Dn 1024   // down = HW/4

typedef unsigned long long ull;
typedef unsigned int uint;

// ---- packed fp32x2 helpers ----
__device__ __forceinline__ ull ffma2(ull a, ull b, ull c) {
    ull d;
    asm("fma.rn.f32x2 %0, %1, %2, %3;" : "=l"(d) : "l"(a), "l"(b), "l"(c));
    return d;
}
__device__ __forceinline__ ull dup2(float v) {
    ull d;
    asm("mov.b64 %0, {%1, %1};" : "=l"(d) : "f"(v));
    return d;
}

// ---- mma/ldmatrix/cp.async helpers ----
__device__ __forceinline__ uint32_t smem_u32(const void* p) {
    uint32_t a;
    asm("{ .reg .u64 t; cvta.to.shared.u64 t, %1; cvt.u32.u64 %0, t; }" : "=r"(a) : "l"(p));
    return a;
}
__device__ __forceinline__ void ldsm4(uint32_t a, uint& r0, uint& r1, uint& r2, uint& r3) {
    asm volatile("ldmatrix.sync.aligned.m8n8.x4.shared.b16 {%0,%1,%2,%3}, [%4];"
                 : "=r"(r0), "=r"(r1), "=r"(r2), "=r"(r3) : "r"(a));
}
__device__ __forceinline__ void ldsm4t(uint32_t a, uint& r0, uint& r1, uint& r2, uint& r3) {
    asm volatile("ldmatrix.sync.aligned.m8n8.x4.trans.shared.b16 {%0,%1,%2,%3}, [%4];"
                 : "=r"(r0), "=r"(r1), "=r"(r2), "=r"(r3) : "r"(a));
}
__device__ __forceinline__ void mma16816(float* d, uint a0, uint a1, uint a2, uint a3,
                                         uint b0, uint b1) {
    asm volatile(
        "mma.sync.aligned.m16n8k16.row.col.f32.bf16.bf16.f32 "
        "{%0,%1,%2,%3}, {%4,%5,%6,%7}, {%8,%9}, {%0,%1,%2,%3};"
        : "+f"(d[0]), "+f"(d[1]), "+f"(d[2]), "+f"(d[3])
        : "r"(a0), "r"(a1), "r"(a2), "r"(a3), "r"(b0), "r"(b1));
}
__device__ __forceinline__ void cp16(uint32_t s, const void* g) {
    asm volatile("cp.async.ca.shared.global [%0], [%1], 16;" :: "r"(s), "l"(g));
}
#define CP_COMMIT() asm volatile("cp.async.commit_group;")
#define CP_WAIT2() asm volatile("cp.async.wait_group 2;")

// split fp32 pair -> packed bf16 hi-pair / lo-pair
__device__ __forceinline__ void split2(float x, float y, uint& hi, uint& lo) {
    __nv_bfloat16 hx = __float2bfloat16_rn(x), hy = __float2bfloat16_rn(y);
    float rx = x - __bfloat162float(hx), ry = y - __bfloat162float(hy);
    __nv_bfloat16 lx = __float2bfloat16_rn(rx), ly = __float2bfloat16_rn(ry);
    __nv_bfloat162 hp, lp;
    hp.x = hx; hp.y = hy; lp.x = lx; lp.y = ly;
    hi = *(uint*)&hp;
    lo = *(uint*)&lp;
}
__device__ __forceinline__ uint pack_bf16(float x, float y) {
    __nv_bfloat162 p;
    p.x = __float2bfloat16_rn(x);
    p.y = __float2bfloat16_rn(y);
    return *(uint*)&p;
}

// ---- scratch ----
__device__ float g_q[(size_t)Bn * C8 * Sn];
__device__ float g_k[(size_t)Bn * C8 * Dn];
__device__ float g_v[(size_t)Bn * C2 * Dn];
__device__ unsigned short g_eh[(size_t)Bn * Sn * Dn];   // exp(logit) bf16 (single)
__device__ unsigned short g_vhn[(size_t)Bn * C2 * Dn];  // crs*v bf16 (single)
__device__ unsigned short g_aph[(size_t)Bn * Sn * C2];  // app hi
__device__ unsigned short g_apl[(size_t)Bn * Sn * C2];  // app lo
__device__ unsigned short g_w2h[Cc * C2];               // w2 hi
__device__ unsigned short g_w2l[Cc * C2];               // w2 lo
__device__ float g_colsum[Bn * Dn];
__device__ float g_crs[Bn * Dn];

// ---------------------------------------------------------------------------
// Fused conv: q / k-pooled / v-pooled (unchanged, known-good)
// ---------------------------------------------------------------------------
__global__ __launch_bounds__(128) void conv_all_k(
    const float* __restrict__ x,
    const float* __restrict__ qw, const float* __restrict__ qb,
    const float* __restrict__ kw, const float* __restrict__ kb,
    const float* __restrict__ vw, const float* __restrict__ vb) {
    int b = blockIdx.z, ot = blockIdx.y, st = blockIdx.x;
    int s0 = st * 128;
    int t = threadIdx.x;

    __shared__ __align__(16) union {
        struct { float Ws[2][16][68]; float Xs[2][16][128]; } p;
        float Cs[64][128];
    } sm;

    int wrow = t >> 1;
    int wkg = (t & 1) << 3;
    int gch = ot * 64 + wrow;
    const float* wsrc;
    if (gch < 32) wsrc = qw + (size_t)gch * Cc;
    else if (gch < 64) wsrc = kw + (size_t)(gch - 32) * Cc;
    else wsrc = vw + (size_t)(gch - 64) * Cc;
    wsrc += wkg;

    int xkk = t >> 3;
    int xsg = (t & 7) << 4;
    const float* xsrc = x + (size_t)b * Cc * Sn + (size_t)xkk * Sn + s0 + xsg;

    int ty = t >> 4, tx = t & 15;

    ull acc[8][4];
#pragma unroll
    for (int i = 0; i < 8; i++)
#pragma unroll
        for (int j = 0; j < 4; j++) acc[i][j] = 0ULL;

    {
#pragma unroll
        for (int u = 0; u < 2; u++) {
            float4 v = *(const float4*)(wsrc + u * 4);
            sm.p.Ws[0][wkg + u * 4 + 0][wrow] = v.x;
            sm.p.Ws[0][wkg + u * 4 + 1][wrow] = v.y;
            sm.p.Ws[0][wkg + u * 4 + 2][wrow] = v.z;
            sm.p.Ws[0][wkg + u * 4 + 3][wrow] = v.w;
        }
#pragma unroll
        for (int u = 0; u < 4; u++)
            *(float4*)&sm.p.Xs[0][xkk][xsg + u * 4] = *(const float4*)(xsrc + u * 4);
    }
    __syncthreads();

    for (int ch = 0; ch < 16; ch++) {
        int cb = ch & 1;
        float4 wpre[2], xpre[4];
        if (ch < 15) {
            const float* wp = wsrc + (ch + 1) * 16;
            wpre[0] = *(const float4*)(wp);
            wpre[1] = *(const float4*)(wp + 4);
            const float* xp = xsrc + (size_t)(ch + 1) * 16 * Sn;
#pragma unroll
            for (int u = 0; u < 4; u++) xpre[u] = *(const float4*)(xp + u * 4);
        }
#pragma unroll
        for (int kk = 0; kk < 16; kk++) {
            float4 a0 = *(const float4*)&sm.p.Ws[cb][kk][ty * 8];
            float4 a1 = *(const float4*)&sm.p.Ws[cb][kk][ty * 8 + 4];
            ulonglong2 b0 = *(const ulonglong2*)&sm.p.Xs[cb][kk][tx * 8];
            ulonglong2 b1 = *(const ulonglong2*)&sm.p.Xs[cb][kk][tx * 8 + 4];
            ull bp[4] = {b0.x, b0.y, b1.x, b1.y};
            float aa[8] = {a0.x, a0.y, a0.z, a0.w, a1.x, a1.y, a1.z, a1.w};
#pragma unroll
            for (int i = 0; i < 8; i++) {
                ull ad = dup2(aa[i]);
#pragma unroll
                for (int j = 0; j < 4; j++) acc[i][j] = ffma2(ad, bp[j], acc[i][j]);
            }
        }
        if (ch < 15) {
            int nb = cb ^ 1;
#pragma unroll
            for (int u = 0; u < 2; u++) {
                sm.p.Ws[nb][wkg + u * 4 + 0][wrow] = (&wpre[u].x)[0];
                sm.p.Ws[nb][wkg + u * 4 + 1][wrow] = (&wpre[u].x)[1];
                sm.p.Ws[nb][wkg + u * 4 + 2][wrow] = (&wpre[u].x)[2];
                sm.p.Ws[nb][wkg + u * 4 + 3][wrow] = (&wpre[u].x)[3];
            }
#pragma unroll
            for (int u = 0; u < 4; u++)
                *(float4*)&sm.p.Xs[nb][xkk][xsg + u * 4] = xpre[u];
        }
        __syncthreads();
    }

#pragma unroll
    for (int i = 0; i < 8; i++) {
        ulonglong2 u0, u1;
        u0.x = acc[i][0]; u0.y = acc[i][1];
        u1.x = acc[i][2]; u1.y = acc[i][3];
        *(ulonglong2*)&sm.Cs[ty * 8 + i][tx * 8] = u0;
        *(ulonglong2*)&sm.Cs[ty * 8 + i][tx * 8 + 4] = u1;
    }
    __syncthreads();

    if (ot == 0) {
#pragma unroll
        for (int i = 0; i < 8; i++) {
            int o = i * 4 + (t >> 5);
            int sp = (t & 31) * 4;
            float4 v = *(const float4*)&sm.Cs[o][sp];
            float bb = qb[o];
            v.x += bb; v.y += bb; v.z += bb; v.w += bb;
            *(float4*)(g_q + (size_t)b * C8 * Sn + (size_t)o * Sn + s0 + sp) = v;
        }
        {
            int o = 32 + (t >> 2);
            int qcb = (t & 3) * 8;
            float bb = kb[o - 32];
            float* dst = g_k + (size_t)b * C8 * Dn + (size_t)(o - 32) * Dn + st * 32;
#pragma unroll
            for (int jj = 0; jj < 8; jj++) {
                int qc = qcb + jj;
                float m = fmaxf(fmaxf(sm.Cs[o][2 * qc], sm.Cs[o][2 * qc + 1]),
                                fmaxf(sm.Cs[o][64 + 2 * qc], sm.Cs[o][64 + 2 * qc + 1]));
                dst[qc] = m + bb;
            }
        }
    } else {
        int vg0 = (ot - 1) * 64;
        int o = t >> 1;
        int qcb = (t & 1) * 16;
        float bb = vb[vg0 + o];
        float* dst = g_v + (size_t)b * C2 * Dn + (size_t)(vg0 + o) * Dn + st * 32;
#pragma unroll
        for (int jj = 0; jj < 16; jj++) {
            int qc = qcb + jj;
            float m = fmaxf(fmaxf(sm.Cs[o][2 * qc], sm.Cs[o][2 * qc + 1]),
                            fmaxf(sm.Cs[o][64 + 2 * qc], sm.Cs[o][64 + 2 * qc + 1]));
            dst[qc] = m + bb;
        }
    }
}

// ---------------------------------------------------------------------------
__global__ void zero_k() { g_colsum[blockIdx.x * 1024 + threadIdx.x] = 0.f; }
__global__ void recip_k() {
    int i = blockIdx.x * 1024 + threadIdx.x;
    g_crs[i] = 1.f / g_colsum[i];
}
// split w2 into bf16 hi/lo
__global__ void wsplit_k(const float* __restrict__ w2) {
    int idx = (blockIdx.x * 256 + threadIdx.x) * 8;
    float4 v0 = *(const float4*)(w2 + idx);
    float4 v1 = *(const float4*)(w2 + idx + 4);
    uint h[4], l[4];
    split2(v0.x, v0.y, h[0], l[0]);
    split2(v0.z, v0.w, h[1], l[1]);
    split2(v1.x, v1.y, h[2], l[2]);
    split2(v1.z, v1.w, h[3], l[3]);
    *(uint4*)(g_w2h + idx) = make_uint4(h[0], h[1], h[2], h[3]);
    *(uint4*)(g_w2l + idx) = make_uint4(l[0], l[1], l[2], l[3]);
}
// pack crs*v to single bf16
__global__ void vpack_k() {
    int idx = blockIdx.x * 256 + threadIdx.x;
    int lin = idx * 8;
    int b = lin >> 17;
    int rem = lin & (Dn * C2 - 1);
    int j = rem >> 7;
    float rs = g_crs[b * Dn + j];
    const float* vp = g_v + (size_t)b * C2 * Dn + rem;
    float4 v0 = *(const float4*)(vp);
    float4 v1 = *(const float4*)(vp + 4);
    uint4 o;
    o.x = pack_bf16(v0.x * rs, v0.y * rs);
    o.y = pack_bf16(v0.z * rs, v0.w * rs);
    o.z = pack_bf16(v1.x * rs, v1.y * rs);
    o.w = pack_bf16(v1.z * rs, v1.w * rs);
    *(uint4*)(g_vhn + (size_t)b * C2 * Dn + rem) = o;
}

// ---------------------------------------------------------------------------
// attn logits via split-bf16 HMMA + fused exp epilogue (bf16 E) + column sums.
// (unchanged from R11)  grid (Dn/128, Sn/128, Bn)
// ---------------------------------------------------------------------------
__global__ __launch_bounds__(256) void attn_hmma_k() {
    __shared__ __align__(16) unsigned short QAh[128][40], QAl[128][40];
    __shared__ __align__(16) unsigned short KBh[128][40], KBl[128][40];
    __shared__ float sm_cp[4][128];

    int t = threadIdx.x, lane = t & 31, wid = t >> 5;
    int b = blockIdx.z, l0 = blockIdx.y * 128, j0 = blockIdx.x * 128;

    {
        int row = t >> 1, fs = (t & 1) * 16;
        const float* qp = g_q + (size_t)b * C8 * Sn + (size_t)(l0 + row) * 32 + fs;
        const float* kp = g_k + (size_t)b * C8 * Dn + (size_t)(j0 + row) * 32 + fs;
        uint h[8], l[8];
#pragma unroll
        for (int u = 0; u < 4; u++) {
            float4 v = *(const float4*)(qp + u * 4);
            split2(v.x, v.y, h[2 * u], l[2 * u]);
            split2(v.z, v.w, h[2 * u + 1], l[2 * u + 1]);
        }
        *(uint4*)&QAh[row][fs] = make_uint4(h[0], h[1], h[2], h[3]);
        *(uint4*)&QAh[row][fs + 8] = make_uint4(h[4], h[5], h[6], h[7]);
        *(uint4*)&QAl[row][fs] = make_uint4(l[0], l[1], l[2], l[3]);
        *(uint4*)&QAl[row][fs + 8] = make_uint4(l[4], l[5], l[6], l[7]);
#pragma unroll
        for (int u = 0; u < 4; u++) {
            float4 v = *(const float4*)(kp + u * 4);
            split2(v.x, v.y, h[2 * u], l[2 * u]);
            split2(v.z, v.w, h[2 * u + 1], l[2 * u + 1]);
        }
        *(uint4*)&KBh[row][fs] = make_uint4(h[0], h[1], h[2], h[3]);
        *(uint4*)&KBh[row][fs + 8] = make_uint4(h[4], h[5], h[6], h[7]);
        *(uint4*)&KBl[row][fs] = make_uint4(l[0], l[1], l[2], l[3]);
        *(uint4*)&KBl[row][fs + 8] = make_uint4(l[4], l[5], l[6], l[7]);
    }
    __syncthreads();

    int wl = wid >> 1, wc = wid & 1;
    uint32_t aoff = (uint32_t)((wl * 32 + (lane & 7) + ((lane >> 3) & 1) * 8) * 80 +
                               (lane >> 4) * 16);
    uint32_t boff = (uint32_t)((wc * 64 + (lane & 7) + ((lane >> 4) & 1) * 8) * 80 +
                               ((lane >> 3) & 1) * 16);
    uint32_t ah_b = smem_u32(QAh) + aoff, al_b = smem_u32(QAl) + aoff;
    uint32_t bh_b = smem_u32(KBh) + boff, bl_b = smem_u32(KBl) + boff;

    float acc[2][8][4];
#pragma unroll
    for (int i = 0; i < 2; i++)
#pragma unroll
        for (int n = 0; n < 8; n++)
#pragma unroll
            for (int q = 0; q < 4; q++) acc[i][n][q] = 0.f;

#pragma unroll
    for (int kc = 0; kc < 2; kc++) {
        uint ah[2][4], al2[2][4];
#pragma unroll
        for (int ln = 0; ln < 2; ln++) {
            ldsm4(ah_b + kc * 32 + ln * 16 * 80, ah[ln][0], ah[ln][1], ah[ln][2], ah[ln][3]);
            ldsm4(al_b + kc * 32 + ln * 16 * 80, al2[ln][0], al2[ln][1], al2[ln][2], al2[ln][3]);
        }
#pragma unroll
        for (int p = 0; p < 4; p++) {
            uint bh0, bh1, bh2, bh3, bl0, bl1, bl2, bl3;
            ldsm4(bh_b + kc * 32 + p * 16 * 80, bh0, bh1, bh2, bh3);
            ldsm4(bl_b + kc * 32 + p * 16 * 80, bl0, bl1, bl2, bl3);
#pragma unroll
            for (int ln = 0; ln < 2; ln++) {
                mma16816(acc[ln][2 * p], ah[ln][0], ah[ln][1], ah[ln][2], ah[ln][3], bh0, bh1);
                mma16816(acc[ln][2 * p], ah[ln][0], ah[ln][1], ah[ln][2], ah[ln][3], bl0, bl1);
                mma16816(acc[ln][2 * p], al2[ln][0], al2[ln][1], al2[ln][2], al2[ln][3], bh0, bh1);
                mma16816(acc[ln][2 * p + 1], ah[ln][0], ah[ln][1], ah[ln][2], ah[ln][3], bh2, bh3);
                mma16816(acc[ln][2 * p + 1], ah[ln][0], ah[ln][1], ah[ln][2], ah[ln][3], bl2, bl3);
                mma16816(acc[ln][2 * p + 1], al2[ln][0], al2[ln][1], al2[ln][2], al2[ln][3], bh2, bh3);
            }
        }
    }

#pragma unroll
    for (int i = 0; i < 2; i++)
#pragma unroll
        for (int n = 0; n < 8; n++)
#pragma unroll
            for (int q = 0; q < 4; q++) acc[i][n][q] = __expf(acc[i][n][q]);

    unsigned short* ehb = g_eh + (size_t)b * Sn * Dn;
#pragma unroll
    for (int ln = 0; ln < 2; ln++) {
        int r0 = l0 + wl * 32 + ln * 16 + (lane >> 2);
#pragma unroll
        for (int n = 0; n < 8; n++) {
            int c = j0 + wc * 64 + n * 8 + (lane & 3) * 2;
            *(uint*)(ehb + (size_t)r0 * Dn + c) = pack_bf16(acc[ln][n][0], acc[ln][n][1]);
            *(uint*)(ehb + (size_t)(r0 + 8) * Dn + c) = pack_bf16(acc[ln][n][2], acc[ln][n][3]);
        }
    }

#pragma unroll
    for (int n = 0; n < 8; n++) {
        float s0 = acc[0][n][0] + acc[0][n][2] + acc[1][n][0] + acc[1][n][2];
        float s1 = acc[0][n][1] + acc[0][n][3] + acc[1][n][1] + acc[1][n][3];
        s0 += __shfl_xor_sync(0xffffffffu, s0, 4);
        s0 += __shfl_xor_sync(0xffffffffu, s0, 8);
        s0 += __shfl_xor_sync(0xffffffffu, s0, 16);
        s1 += __shfl_xor_sync(0xffffffffu, s1, 4);
        s1 += __shfl_xor_sync(0xffffffffu, s1, 8);
        s1 += __shfl_xor_sync(0xffffffffu, s1, 16);
        if ((lane >> 2) == 0) {
            int cl = wc * 64 + n * 8 + (lane & 3) * 2;
            sm_cp[wl][cl] = s0;
            sm_cp[wl][cl + 1] = s1;
        }
    }
    __syncthreads();
    if (t < 128) {
        float cs = sm_cp[0][t] + sm_cp[1][t] + sm_cp[2][t] + sm_cp[3][t];
        atomicAdd(&g_colsum[b * Dn + j0 + t], cs);
    }
}

// ---------------------------------------------------------------------------
// applied GEMM, 4-stage cp.async, A = bf16 E, B = bf16 crs*v (both single):
//   app = E x Vn;  1 MMA per n-subtile.  Epilogue writes app SPLIT hi/lo.
// Dynamic smem 41984 B.  grid (Sn/128, Bn)
// ---------------------------------------------------------------------------
#define AP_AH 0
#define AP_BH 24576
#define AP_SMEM 41984
#define AP_ASTG 6144   // 128*48
#define AP_BSTG 4352   // 16*272

__global__ __launch_bounds__(256) void applied_hmma_k() {
    extern __shared__ __align__(16) char dsm[];
    uint32_t sb = smem_u32(dsm);

    int t = threadIdx.x, lane = t & 31, wid = t >> 5;
    int b = blockIdx.y, l0 = blockIdx.x * 128;

    int arow = t >> 1, ak = (t & 1) * 8;
    const unsigned short* ahg = g_eh + (size_t)b * Sn * Dn + (size_t)(l0 + arow) * Dn + ak;
    int bj = t >> 4, bc = (t & 15) * 8;
    const unsigned short* bhg = g_vhn + (size_t)b * C2 * Dn + (size_t)bj * C2 + bc;

    uint32_t a_dst = sb + (uint32_t)(arow * 48 + (t & 1) * 16);
    uint32_t b_dst = sb + (uint32_t)(bj * 272 + bc * 2);

    int wl = wid >> 1, wc = wid & 1;
    uint32_t a_off = (uint32_t)((wl * 32 + (lane & 7) + ((lane >> 3) & 1) * 8) * 48 +
                                ((lane >> 4) * 8) * 2);
    uint32_t b_off = (uint32_t)(((lane & 7) + ((lane >> 3) & 1) * 8) * 272 +
                                (wc * 64 + (lane >> 4) * 8) * 2);

    float acc[2][8][4];
#pragma unroll
    for (int i = 0; i < 2; i++)
#pragma unroll
        for (int n = 0; n < 8; n++)
#pragma unroll
            for (int q = 0; q < 4; q++) acc[i][n][q] = 0.f;

#pragma unroll
    for (int p = 0; p < 3; p++) {
        cp16(a_dst + AP_AH + p * AP_ASTG, ahg + p * 16);
        cp16(b_dst + AP_BH + p * AP_BSTG, bhg + (size_t)p * 16 * C2);
        CP_COMMIT();
    }

    for (int ch = 0; ch < 64; ch++) {
        int st = ch & 3;
        CP_WAIT2();
        __syncthreads();

        if (ch + 3 < 64) {
            int ns = (ch + 3) & 3;
            cp16(a_dst + AP_AH + ns * AP_ASTG, ahg + (ch + 3) * 16);
            cp16(b_dst + AP_BH + ns * AP_BSTG, bhg + (size_t)(ch + 3) * 16 * C2);
        }
        CP_COMMIT();

        uint32_t ah_base = sb + AP_AH + st * AP_ASTG + a_off;
        uint32_t bh_base = sb + AP_BH + st * AP_BSTG + b_off;

        uint ah[2][4];
#pragma unroll
        for (int ln = 0; ln < 2; ln++)
            ldsm4(ah_base + ln * 16 * 48, ah[ln][0], ah[ln][1], ah[ln][2], ah[ln][3]);
#pragma unroll
        for (int nn = 0; nn < 4; nn++) {
            uint bh0, bh1, bh2, bh3;
            ldsm4t(bh_base + nn * 32, bh0, bh1, bh2, bh3);
#pragma unroll
            for (int ln = 0; ln < 2; ln++) {
                mma16816(acc[ln][2 * nn], ah[ln][0], ah[ln][1], ah[ln][2], ah[ln][3], bh0, bh1);
                mma16816(acc[ln][2 * nn + 1], ah[ln][0], ah[ln][1], ah[ln][2], ah[ln][3], bh2, bh3);
            }
        }
    }

    // epilogue: write app SPLIT (hi/lo), as in the passing R11 config
    unsigned short* aphb = g_aph + (size_t)b * Sn * C2;
    unsigned short* aplb = g_apl + (size_t)b * Sn * C2;
#pragma unroll
    for (int ln = 0; ln < 2; ln++) {
        int r0 = l0 + wl * 32 + ln * 16 + (lane >> 2);
#pragma unroll
        for (int n = 0; n < 8; n++) {
            int c = wc * 64 + n * 8 + (lane & 3) * 2;
            uint h01, l01, h23, l23;
            split2(acc[ln][n][0], acc[ln][n][1], h01, l01);
            split2(acc[ln][n][2], acc[ln][n][3], h23, l23);
            *(uint*)(aphb + (size_t)r0 * C2 + c) = h01;
            *(uint*)(aplb + (size_t)r0 * C2 + c) = l01;
            *(uint*)(aphb + (size_t)(r0 + 8) * C2 + c) = h23;
            *(uint*)(aplb + (size_t)(r0 + 8) * C2 + c) = l23;
        }
    }
}

// ---------------------------------------------------------------------------
// output conv + residual, 4-stage cp.async, SPLIT w2 x SPLIT app (R11-proven).
// grid (Sn/128, Cc/128, Bn)
// ---------------------------------------------------------------------------
#define OC_AH 0
#define OC_AL 24576
#define OC_BH 49152
#define OC_BL 66560
#define OC_SMEM 83968

__global__ __launch_bounds__(256) void out_conv_hmma_k(
    const float* __restrict__ x, const float* __restrict__ b2,
    const float* __restrict__ gamma, float* __restrict__ out) {
    extern __shared__ __align__(16) char dsm[];
    uint32_t sb = smem_u32(dsm);

    int t = threadIdx.x, lane = t & 31, wid = t >> 5;
    int b = blockIdx.z, o0 = blockIdx.y * 128, sp0 = blockIdx.x * 128;

    int arow = t >> 1, ak = (t & 1) * 8;
    const unsigned short* whg = g_w2h + (size_t)(o0 + arow) * C2 + ak;
    const unsigned short* wlg = g_w2l + (size_t)(o0 + arow) * C2 + ak;
    int bkk = t >> 4, bsg = (t & 15) * 8;
    const unsigned short* aphg = g_aph + (size_t)b * Sn * C2 + (size_t)bkk * Sn + sp0 + bsg;
    const unsigned short* aplg = g_apl + (size_t)b * Sn * C2 + (size_t)bkk * Sn + sp0 + bsg;

    uint32_t a_dst = sb + (uint32_t)(arow * 48 + (t & 1) * 16);
    uint32_t b_dst = sb + (uint32_t)(bkk * 272 + bsg * 2);

    int wl = wid >> 1, wc = wid & 1;
    uint32_t a_off = (uint32_t)((wl * 32 + (lane & 7) + ((lane >> 3) & 1) * 8) * 48 +
                                ((lane >> 4) * 8) * 2);
    uint32_t b_off = (uint32_t)(((lane & 7) + ((lane >> 3) & 1) * 8) * 272 +
                                (wc * 64 + (lane >> 4) * 8) * 2);

    float acc[2][8][4];
#pragma unroll
    for (int i = 0; i < 2; i++)
#pragma unroll
        for (int n = 0; n < 8; n++)
#pragma unroll
            for (int q = 0; q < 4; q++) acc[i][n][q] = 0.f;

#pragma unroll
    for (int p = 0; p < 3; p++) {
        cp16(a_dst + OC_AH + p * AP_ASTG, whg + p * 16);
        cp16(a_dst + OC_AL + p * AP_ASTG, wlg + p * 16);
        cp16(b_dst + OC_BH + p * AP_BSTG, aphg + (size_t)p * 16 * Sn);
        cp16(b_dst + OC_BL + p * AP_BSTG, aplg + (size_t)p * 16 * Sn);
        CP_COMMIT();
    }

    for (int ch = 0; ch < 8; ch++) {
        int st = ch & 3;
        CP_WAIT2();
        __syncthreads();

        if (ch + 3 < 8) {
            int ns = (ch + 3) & 3;
            cp16(a_dst + OC_AH + ns * AP_ASTG, whg + (ch + 3) * 16);
            cp16(a_dst + OC_AL + ns * AP_ASTG, wlg + (ch + 3) * 16);
            cp16(b_dst + OC_BH + ns * AP_BSTG, aphg + (size_t)(ch + 3) * 16 * Sn);
            cp16(b_dst + OC_BL + ns * AP_BSTG, aplg + (size_t)(ch + 3) * 16 * Sn);
        }
        CP_COMMIT();

        uint32_t ah_base = sb + OC_AH + st * AP_ASTG + a_off;
        uint32_t al_base = sb + OC_AL + st * AP_ASTG + a_off;
        uint32_t bh_base = sb + OC_BH + st * AP_BSTG + b_off;
        uint32_t bl_base = sb + OC_BL + st * AP_BSTG + b_off;

        uint ah[2][4], al2[2][4];
#pragma unroll
        for (int ln = 0; ln < 2; ln++) {
            ldsm4(ah_base + ln * 16 * 48, ah[ln][0], ah[ln][1], ah[ln][2], ah[ln][3]);
            ldsm4(al_base + ln * 16 * 48, al2[ln][0], al2[ln][1], al2[ln][2], al2[ln][3]);
        }
#pragma unroll
        for (int nn = 0; nn < 4; nn++) {
            uint bh0, bh1, bh2, bh3, bl0, bl1, bl2, bl3;
            ldsm4t(bh_base + nn * 32, bh0, bh1, bh2, bh3);
            ldsm4t(bl_base + nn * 32, bl0, bl1, bl2, bl3);
#pragma unroll
            for (int ln = 0; ln < 2; ln++) {
                mma16816(acc[ln][2 * nn], ah[ln][0], ah[ln][1], ah[ln][2], ah[ln][3], bh0, bh1);
                mma16816(acc[ln][2 * nn], ah[ln][0], ah[ln][1], ah[ln][2], ah[ln][3], bl0, bl1);
                mma16816(acc[ln][2 * nn], al2[ln][0], al2[ln][1], al2[ln][2], al2[ln][3], bh0, bh1);
                mma16816(acc[ln][2 * nn + 1], ah[ln][0], ah[ln][1], ah[ln][2], ah[ln][3], bh2, bh3);
                mma16816(acc[ln][2 * nn + 1], ah[ln][0], ah[ln][1], ah[ln][2], ah[ln][3], bl2, bl3);
                mma16816(acc[ln][2 * nn + 1], al2[ln][0], al2[ln][1], al2[ln][2], al2[ln][3], bh2, bh3);
            }
        }
    }

    float g = gamma[0];
#pragma unroll
    for (int ln = 0; ln < 2; ln++) {
        int o1 = o0 + wl * 32 + ln * 16 + (lane >> 2);
        int o2 = o1 + 8;
        float bb1 = b2[o1], bb2 = b2[o2];
#pragma unroll
        for (int n = 0; n < 8; n++) {
            int sp = sp0 + wc * 64 + n * 8 + (lane & 3) * 2;
            const float* x1 = x + (size_t)b * Cc * Sn + (size_t)o1 * Sn + sp;
            const float* x2 = x + (size_t)b * Cc * Sn + (size_t)o2 * Sn + sp;
            float* y1 = out + (size_t)b * Cc * Sn + (size_t)o1 * Sn + sp;
            float* y2 = out + (size_t)b * Cc * Sn + (size_t)o2 * Sn + sp;
            float2 xa = *(const float2*)(x1);
            float2 xb = *(const float2*)(x2);
            float2 r1, r2;
            r1.x = fmaf(g, acc[ln][n][0] + bb1, xa.x);
            r1.y = fmaf(g, acc[ln][n][1] + bb1, xa.y);
            r2.x = fmaf(g, acc[ln][n][2] + bb2, xb.x);
            r2.y = fmaf(g, acc[ln][n][3] + bb2, xb.y);
            *(float2*)(y1) = r1;
            *(float2*)(y2) = r2;
        }
    }
}

// ---------------------------------------------------------------------------
extern "C" void kernel_launch(void* const* d_in, const int* in_sizes, int n_in,
                              void* d_out, int out_size) {
    const float* x   = (const float*)d_in[0];
    const float* qw  = (const float*)d_in[1];
    const float* qb  = (const float*)d_in[2];
    const float* kw  = (const float*)d_in[3];
    const float* kb  = (const float*)d_in[4];
    const float* vw  = (const float*)d_in[5];
    const float* vb  = (const float*)d_in[6];
    const float* v2w = (const float*)d_in[7];
    const float* v2b = (const float*)d_in[8];
    const float* gm  = (const float*)d_in[9];
    float* out = (float*)d_out;

    static int smem_set = 0;
    if (!smem_set) {
        cudaFuncSetAttribute(applied_hmma_k,
                             cudaFuncAttributeMaxDynamicSharedMemorySize, AP_SMEM);
        cudaFuncSetAttribute(out_conv_hmma_k,
                             cudaFuncAttributeMaxDynamicSharedMemorySize, OC_SMEM);
        smem_set = 1;
    }

    conv_all_k<<<dim3(32, 3, Bn), 128>>>(x, qw, qb, kw, kb, vw, vb);
    zero_k<<<Bn * Dn / 1024, 1024>>>();
    wsplit_k<<<(Cc * C2 / 8) / 256, 256>>>(v2w);
    attn_hmma_k<<<dim3(Dn / 128, Sn / 128, Bn), 256>>>();
    recip_k<<<Bn * Dn / 1024, 1024>>>();
    vpack_k<<<(Bn * C2 * Dn / 8) / 256, 256>>>();
    applied_hmma_k<<<dim3(Sn / 128, Bn), 256, AP_SMEM>>>();
    out_conv_hmma_k<<<dim3(Sn / 128, Cc / 128, Bn), 256, OC_SMEM>>>(x, v2b, gm, out);
}

// round 16
// speedup vs baseline: 2.6092x; 1.0096x over previous
#include <cuda_runtime.h>
#include <cuda_bf16.h>
#include <cstdint>

#define Bn 16
#define Cc 256
#define Sn 4096   // H*W
#define C8 32     // C/8
#define C2 128    // C/2
#define Dn 1024   // down = HW/4

typedef unsigned long long ull;
typedef unsigned int uint;

// ---- packed fp32x2 helpers ----
__device__ __forceinline__ ull ffma2(ull a, ull b, ull c) {
    ull d;
    asm("fma.rn.f32x2 %0, %1, %2, %3;" : "=l"(d) : "l"(a), "l"(b), "l"(c));
    return d;
}
__device__ __forceinline__ ull dup2(float v) {
    ull d;
    asm("mov.b64 %0, {%1, %1};" : "=l"(d) : "f"(v));
    return d;
}

// ---- mma/ldmatrix/cp.async helpers ----
__device__ __forceinline__ uint32_t smem_u32(const void* p) {
    uint32_t a;
    asm("{ .reg .u64 t; cvta.to.shared.u64 t, %1; cvt.u32.u64 %0, t; }" : "=r"(a) : "l"(p));
    return a;
}
__device__ __forceinline__ void ldsm4(uint32_t a, uint& r0, uint& r1, uint& r2, uint& r3) {
    asm volatile("ldmatrix.sync.aligned.m8n8.x4.shared.b16 {%0,%1,%2,%3}, [%4];"
                 : "=r"(r0), "=r"(r1), "=r"(r2), "=r"(r3) : "r"(a));
}
__device__ __forceinline__ void ldsm4t(uint32_t a, uint& r0, uint& r1, uint& r2, uint& r3) {
    asm volatile("ldmatrix.sync.aligned.m8n8.x4.trans.shared.b16 {%0,%1,%2,%3}, [%4];"
                 : "=r"(r0), "=r"(r1), "=r"(r2), "=r"(r3) : "r"(a));
}
__device__ __forceinline__ void mma16816(float* d, uint a0, uint a1, uint a2, uint a3,
                                         uint b0, uint b1) {
    asm volatile(
        "mma.sync.aligned.m16n8k16.row.col.f32.bf16.bf16.f32 "
        "{%0,%1,%2,%3}, {%4,%5,%6,%7}, {%8,%9}, {%0,%1,%2,%3};"
        : "+f"(d[0]), "+f"(d[1]), "+f"(d[2]), "+f"(d[3])
        : "r"(a0), "r"(a1), "r"(a2), "r"(a3), "r"(b0), "r"(b1));
}
__device__ __forceinline__ void cp16(uint32_t s, const void* g) {
    asm volatile("cp.async.ca.shared.global [%0], [%1], 16;" :: "r"(s), "l"(g));
}
#define CP_COMMIT() asm volatile("cp.async.commit_group;")
#define CP_WAIT2() asm volatile("cp.async.wait_group 2;")

// split fp32 pair -> packed bf16 hi-pair / lo-pair
__device__ __forceinline__ void split2(float x, float y, uint& hi, uint& lo) {
    __nv_bfloat16 hx = __float2bfloat16_rn(x), hy = __float2bfloat16_rn(y);
    float rx = x - __bfloat162float(hx), ry = y - __bfloat162float(hy);
    __nv_bfloat16 lx = __float2bfloat16_rn(rx), ly = __float2bfloat16_rn(ry);
    __nv_bfloat162 hp, lp;
    hp.x = hx; hp.y = hy; lp.x = lx; lp.y = ly;
    hi = *(uint*)&hp;
    lo = *(uint*)&lp;
}
__device__ __forceinline__ void split1(float x, unsigned short& h, unsigned short& l) {
    __nv_bfloat16 hb = __float2bfloat16_rn(x);
    float r = x - __bfloat162float(hb);
    __nv_bfloat16 lb = __float2bfloat16_rn(r);
    h = *(unsigned short*)&hb;
    l = *(unsigned short*)&lb;
}
__device__ __forceinline__ uint pack_bf16(float x, float y) {
    __nv_bfloat162 p;
    p.x = __float2bfloat16_rn(x);
    p.y = __float2bfloat16_rn(y);
    return *(uint*)&p;
}

// ---- scratch ----
__device__ unsigned short g_qh[(size_t)Bn * C8 * Sn];   // q hi (flat conv layout)
__device__ unsigned short g_ql[(size_t)Bn * C8 * Sn];   // q lo
__device__ unsigned short g_kh[(size_t)Bn * C8 * Dn];   // k hi
__device__ unsigned short g_kl[(size_t)Bn * C8 * Dn];   // k lo
__device__ float g_v[(size_t)Bn * C2 * Dn];
__device__ unsigned short g_eh[(size_t)Bn * Sn * Dn];   // exp(logit) bf16
__device__ unsigned short g_vhn[(size_t)Bn * C2 * Dn];  // crs*v bf16
__device__ unsigned short g_aph[(size_t)Bn * Sn * C2];  // app hi
__device__ unsigned short g_apl[(size_t)Bn * Sn * C2];  // app lo
__device__ unsigned short g_w2h[Cc * C2];               // w2 hi
__device__ unsigned short g_w2l[Cc * C2];               // w2 lo
__device__ float g_colsum[Bn * Dn];
__device__ float g_crs[Bn * Dn];

// ---------------------------------------------------------------------------
// Fused conv (R13-proven FFMA2 core): q / k-pooled / v-pooled.
// Epilogue change ONLY: q,k stored pre-split bf16 hi/lo.
// ---------------------------------------------------------------------------
__global__ __launch_bounds__(128) void conv_all_k(
    const float* __restrict__ x,
    const float* __restrict__ qw, const float* __restrict__ qb,
    const float* __restrict__ kw, const float* __restrict__ kb,
    const float* __restrict__ vw, const float* __restrict__ vb) {
    int b = blockIdx.z, ot = blockIdx.y, st = blockIdx.x;
    int s0 = st * 128;
    int t = threadIdx.x;

    __shared__ __align__(16) union {
        struct { float Ws[2][16][68]; float Xs[2][16][128]; } p;
        float Cs[64][128];
    } sm;

    int wrow = t >> 1;
    int wkg = (t & 1) << 3;
    int gch = ot * 64 + wrow;
    const float* wsrc;
    if (gch < 32) wsrc = qw + (size_t)gch * Cc;
    else if (gch < 64) wsrc = kw + (size_t)(gch - 32) * Cc;
    else wsrc = vw + (size_t)(gch - 64) * Cc;
    wsrc += wkg;

    int xkk = t >> 3;
    int xsg = (t & 7) << 4;
    const float* xsrc = x + (size_t)b * Cc * Sn + (size_t)xkk * Sn + s0 + xsg;

    int ty = t >> 4, tx = t & 15;

    ull acc[8][4];
#pragma unroll
    for (int i = 0; i < 8; i++)
#pragma unroll
        for (int j = 0; j < 4; j++) acc[i][j] = 0ULL;

    {
#pragma unroll
        for (int u = 0; u < 2; u++) {
            float4 v = *(const float4*)(wsrc + u * 4);
            sm.p.Ws[0][wkg + u * 4 + 0][wrow] = v.x;
            sm.p.Ws[0][wkg + u * 4 + 1][wrow] = v.y;
            sm.p.Ws[0][wkg + u * 4 + 2][wrow] = v.z;
            sm.p.Ws[0][wkg + u * 4 + 3][wrow] = v.w;
        }
#pragma unroll
        for (int u = 0; u < 4; u++)
            *(float4*)&sm.p.Xs[0][xkk][xsg + u * 4] = *(const float4*)(xsrc + u * 4);
    }
    __syncthreads();

    for (int ch = 0; ch < 16; ch++) {
        int cb = ch & 1;
        float4 wpre[2], xpre[4];
        if (ch < 15) {
            const float* wp = wsrc + (ch + 1) * 16;
            wpre[0] = *(const float4*)(wp);
            wpre[1] = *(const float4*)(wp + 4);
            const float* xp = xsrc + (size_t)(ch + 1) * 16 * Sn;
#pragma unroll
            for (int u = 0; u < 4; u++) xpre[u] = *(const float4*)(xp + u * 4);
        }
#pragma unroll
        for (int kk = 0; kk < 16; kk++) {
            float4 a0 = *(const float4*)&sm.p.Ws[cb][kk][ty * 8];
            float4 a1 = *(const float4*)&sm.p.Ws[cb][kk][ty * 8 + 4];
            ulonglong2 b0 = *(const ulonglong2*)&sm.p.Xs[cb][kk][tx * 8];
            ulonglong2 b1 = *(const ulonglong2*)&sm.p.Xs[cb][kk][tx * 8 + 4];
            ull bp[4] = {b0.x, b0.y, b1.x, b1.y};
            float aa[8] = {a0.x, a0.y, a0.z, a0.w, a1.x, a1.y, a1.z, a1.w};
#pragma unroll
            for (int i = 0; i < 8; i++) {
                ull ad = dup2(aa[i]);
#pragma unroll
                for (int j = 0; j < 4; j++) acc[i][j] = ffma2(ad, bp[j], acc[i][j]);
            }
        }
        if (ch < 15) {
            int nb = cb ^ 1;
#pragma unroll
            for (int u = 0; u < 2; u++) {
                sm.p.Ws[nb][wkg + u * 4 + 0][wrow] = (&wpre[u].x)[0];
                sm.p.Ws[nb][wkg + u * 4 + 1][wrow] = (&wpre[u].x)[1];
                sm.p.Ws[nb][wkg + u * 4 + 2][wrow] = (&wpre[u].x)[2];
                sm.p.Ws[nb][wkg + u * 4 + 3][wrow] = (&wpre[u].x)[3];
            }
#pragma unroll
            for (int u = 0; u < 4; u++)
                *(float4*)&sm.p.Xs[nb][xkk][xsg + u * 4] = xpre[u];
        }
        __syncthreads();
    }

#pragma unroll
    for (int i = 0; i < 8; i++) {
        ulonglong2 u0, u1;
        u0.x = acc[i][0]; u0.y = acc[i][1];
        u1.x = acc[i][2]; u1.y = acc[i][3];
        *(ulonglong2*)&sm.Cs[ty * 8 + i][tx * 8] = u0;
        *(ulonglong2*)&sm.Cs[ty * 8 + i][tx * 8 + 4] = u1;
    }
    __syncthreads();

    if (ot == 0) {
        // q: rows 0..31, +bias, SPLIT store
#pragma unroll
        for (int i = 0; i < 8; i++) {
            int o = i * 4 + (t >> 5);
            int sp = (t & 31) * 4;
            float4 v = *(const float4*)&sm.Cs[o][sp];
            float bb = qb[o];
            v.x += bb; v.y += bb; v.z += bb; v.w += bb;
            uint h01, l01, h23, l23;
            split2(v.x, v.y, h01, l01);
            split2(v.z, v.w, h23, l23);
            size_t off = (size_t)b * C8 * Sn + (size_t)o * Sn + s0 + sp;
            *(uint2*)(g_qh + off) = make_uint2(h01, h23);
            *(uint2*)(g_ql + off) = make_uint2(l01, l23);
        }
        // k: rows 32..63, pool, +bias, SPLIT store
        {
            int o = 32 + (t >> 2);
            int qcb = (t & 3) * 8;
            float bb = kb[o - 32];
            size_t off = (size_t)b * C8 * Dn + (size_t)(o - 32) * Dn + st * 32;
#pragma unroll
            for (int jj = 0; jj < 8; jj++) {
                int qc = qcb + jj;
                float m = fmaxf(fmaxf(sm.Cs[o][2 * qc], sm.Cs[o][2 * qc + 1]),
                                fmaxf(sm.Cs[o][64 + 2 * qc], sm.Cs[o][64 + 2 * qc + 1])) + bb;
                unsigned short hh, ll;
                split1(m, hh, ll);
                g_kh[off + qc] = hh;
                g_kl[off + qc] = ll;
            }
        }
    } else {
        int vg0 = (ot - 1) * 64;
        int o = t >> 1;
        int qcb = (t & 1) * 16;
        float bb = vb[vg0 + o];
        float* dst = g_v + (size_t)b * C2 * Dn + (size_t)(vg0 + o) * Dn + st * 32;
#pragma unroll
        for (int jj = 0; jj < 16; jj++) {
            int qc = qcb + jj;
            float m = fmaxf(fmaxf(sm.Cs[o][2 * qc], sm.Cs[o][2 * qc + 1]),
                            fmaxf(sm.Cs[o][64 + 2 * qc], sm.Cs[o][64 + 2 * qc + 1]));
            dst[qc] = m + bb;
        }
    }
}

// ---------------------------------------------------------------------------
__global__ void zero_k() { g_colsum[blockIdx.x * 1024 + threadIdx.x] = 0.f; }
__global__ void recip_k() {
    int i = blockIdx.x * 1024 + threadIdx.x;
    g_crs[i] = 1.f / g_colsum[i];
}
__global__ void wsplit_k(const float* __restrict__ w2) {
    int idx = (blockIdx.x * 256 + threadIdx.x) * 8;
    float4 v0 = *(const float4*)(w2 + idx);
    float4 v1 = *(const float4*)(w2 + idx + 4);
    uint h[4], l[4];
    split2(v0.x, v0.y, h[0], l[0]);
    split2(v0.z, v0.w, h[1], l[1]);
    split2(v1.x, v1.y, h[2], l[2]);
    split2(v1.z, v1.w, h[3], l[3]);
    *(uint4*)(g_w2h + idx) = make_uint4(h[0], h[1], h[2], h[3]);
    *(uint4*)(g_w2l + idx) = make_uint4(l[0], l[1], l[2], l[3]);
}
__global__ void vpack_k() {
    int idx = blockIdx.x * 256 + threadIdx.x;
    int lin = idx * 8;
    int b = lin >> 17;
    int rem = lin & (Dn * C2 - 1);
    int j = rem >> 7;
    float rs = g_crs[b * Dn + j];
    const float* vp = g_v + (size_t)b * C2 * Dn + rem;
    float4 v0 = *(const float4*)(vp);
    float4 v1 = *(const float4*)(vp + 4);
    uint4 o;
    o.x = pack_bf16(v0.x * rs, v0.y * rs);
    o.y = pack_bf16(v0.z * rs, v0.w * rs);
    o.z = pack_bf16(v1.x * rs, v1.y * rs);
    o.w = pack_bf16(v1.z * rs, v1.w * rs);
    *(uint4*)(g_vhn + (size_t)b * C2 * Dn + rem) = o;
}

// ---------------------------------------------------------------------------
// attn logits via split-bf16 HMMA, PURE-COPY loaders (q/k pre-split) +
// fused exp epilogue (bf16 E) + column sums.  grid (Dn/128, Sn/128, Bn)
// ---------------------------------------------------------------------------
__global__ __launch_bounds__(256) void attn_hmma_k() {
    __shared__ __align__(16) unsigned short QAh[128][40], QAl[128][40];
    __shared__ __align__(16) unsigned short KBh[128][40], KBl[128][40];
    __shared__ float sm_cp[4][128];

    int t = threadIdx.x, lane = t & 31, wid = t >> 5;
    int b = blockIdx.z, l0 = blockIdx.y * 128, j0 = blockIdx.x * 128;

    {
        int row = t >> 1, fs = (t & 1) * 16;
        size_t qoff = (size_t)b * C8 * Sn + (size_t)(l0 + row) * 32 + fs;
        size_t koff = (size_t)b * C8 * Dn + (size_t)(j0 + row) * 32 + fs;
        *(uint4*)&QAh[row][fs] = *(const uint4*)(g_qh + qoff);
        *(uint4*)&QAh[row][fs + 8] = *(const uint4*)(g_qh + qoff + 8);
        *(uint4*)&QAl[row][fs] = *(const uint4*)(g_ql + qoff);
        *(uint4*)&QAl[row][fs + 8] = *(const uint4*)(g_ql + qoff + 8);
        *(uint4*)&KBh[row][fs] = *(const uint4*)(g_kh + koff);
        *(uint4*)&KBh[row][fs + 8] = *(const uint4*)(g_kh + koff + 8);
        *(uint4*)&KBl[row][fs] = *(const uint4*)(g_kl + koff);
        *(uint4*)&KBl[row][fs + 8] = *(const uint4*)(g_kl + koff + 8);
    }
    __syncthreads();

    int wl = wid >> 1, wc = wid & 1;
    uint32_t aoff = (uint32_t)((wl * 32 + (lane & 7) + ((lane >> 3) & 1) * 8) * 80 +
                               (lane >> 4) * 16);
    uint32_t boff = (uint32_t)((wc * 64 + (lane & 7) + ((lane >> 4) & 1) * 8) * 80 +
                               ((lane >> 3) & 1) * 16);
    uint32_t ah_b = smem_u32(QAh) + aoff, al_b = smem_u32(QAl) + aoff;
    uint32_t bh_b = smem_u32(KBh) + boff, bl_b = smem_u32(KBl) + boff;

    float acc[2][8][4];
#pragma unroll
    for (int i = 0; i < 2; i++)
#pragma unroll
        for (int n = 0; n < 8; n++)
#pragma unroll
            for (int q = 0; q < 4; q++) acc[i][n][q] = 0.f;

#pragma unroll
    for (int kc = 0; kc < 2; kc++) {
        uint ah[2][4], al2[2][4];
#pragma unroll
        for (int ln = 0; ln < 2; ln++) {
            ldsm4(ah_b + kc * 32 + ln * 16 * 80, ah[ln][0], ah[ln][1], ah[ln][2], ah[ln][3]);
            ldsm4(al_b + kc * 32 + ln * 16 * 80, al2[ln][0], al2[ln][1], al2[ln][2], al2[ln][3]);
        }
#pragma unroll
        for (int p = 0; p < 4; p++) {
            uint bh0, bh1, bh2, bh3, bl0, bl1, bl2, bl3;
            ldsm4(bh_b + kc * 32 + p * 16 * 80, bh0, bh1, bh2, bh3);
            ldsm4(bl_b + kc * 32 + p * 16 * 80, bl0, bl1, bl2, bl3);
#pragma unroll
            for (int ln = 0; ln < 2; ln++) {
                mma16816(acc[ln][2 * p], ah[ln][0], ah[ln][1], ah[ln][2], ah[ln][3], bh0, bh1);
                mma16816(acc[ln][2 * p], ah[ln][0], ah[ln][1], ah[ln][2], ah[ln][3], bl0, bl1);
                mma16816(acc[ln][2 * p], al2[ln][0], al2[ln][1], al2[ln][2], al2[ln][3], bh0, bh1);
                mma16816(acc[ln][2 * p + 1], ah[ln][0], ah[ln][1], ah[ln][2], ah[ln][3], bh2, bh3);
                mma16816(acc[ln][2 * p + 1], ah[ln][0], ah[ln][1], ah[ln][2], ah[ln][3], bl2, bl3);
                mma16816(acc[ln][2 * p + 1], al2[ln][0], al2[ln][1], al2[ln][2], al2[ln][3], bh2, bh3);
            }
        }
    }

#pragma unroll
    for (int i = 0; i < 2; i++)
#pragma unroll
        for (int n = 0; n < 8; n++)
#pragma unroll
            for (int q = 0; q < 4; q++) acc[i][n][q] = __expf(acc[i][n][q]);

    unsigned short* ehb = g_eh + (size_t)b * Sn * Dn;
#pragma unroll
    for (int ln = 0; ln < 2; ln++) {
        int r0 = l0 + wl * 32 + ln * 16 + (lane >> 2);
#pragma unroll
        for (int n = 0; n < 8; n++) {
            int c = j0 + wc * 64 + n * 8 + (lane & 3) * 2;
            *(uint*)(ehb + (size_t)r0 * Dn + c) = pack_bf16(acc[ln][n][0], acc[ln][n][1]);
            *(uint*)(ehb + (size_t)(r0 + 8) * Dn + c) = pack_bf16(acc[ln][n][2], acc[ln][n][3]);
        }
    }

#pragma unroll
    for (int n = 0; n < 8; n++) {
        float s0 = acc[0][n][0] + acc[0][n][2] + acc[1][n][0] + acc[1][n][2];
        float s1 = acc[0][n][1] + acc[0][n][3] + acc[1][n][1] + acc[1][n][3];
        s0 += __shfl_xor_sync(0xffffffffu, s0, 4);
        s0 += __shfl_xor_sync(0xffffffffu, s0, 8);
        s0 += __shfl_xor_sync(0xffffffffu, s0, 16);
        s1 += __shfl_xor_sync(0xffffffffu, s1, 4);
        s1 += __shfl_xor_sync(0xffffffffu, s1, 8);
        s1 += __shfl_xor_sync(0xffffffffu, s1, 16);
        if ((lane >> 2) == 0) {
            int cl = wc * 64 + n * 8 + (lane & 3) * 2;
            sm_cp[wl][cl] = s0;
            sm_cp[wl][cl + 1] = s1;
        }
    }
    __syncthreads();
    if (t < 128) {
        float cs = sm_cp[0][t] + sm_cp[1][t] + sm_cp[2][t] + sm_cp[3][t];
        atomicAdd(&g_colsum[b * Dn + j0 + t], cs);
    }
}

// ---------------------------------------------------------------------------
// applied GEMM (R13-proven): A = bf16 E, B = bf16 crs*v, split app out.
// ---------------------------------------------------------------------------
#define AP_AH 0
#define AP_BH 24576
#define AP_SMEM 41984
#define AP_ASTG 6144   // 128*48
#define AP_BSTG 4352   // 16*272

__global__ __launch_bounds__(256) void applied_hmma_k() {
    extern __shared__ __align__(16) char dsm[];
    uint32_t sb = smem_u32(dsm);

    int t = threadIdx.x, lane = t & 31, wid = t >> 5;
    int b = blockIdx.y, l0 = blockIdx.x * 128;

    int arow = t >> 1, ak = (t & 1) * 8;
    const unsigned short* ahg = g_eh + (size_t)b * Sn * Dn + (size_t)(l0 + arow) * Dn + ak;
    int bj = t >> 4, bc = (t & 15) * 8;
    const unsigned short* bhg = g_vhn + (size_t)b * C2 * Dn + (size_t)bj * C2 + bc;

    uint32_t a_dst = sb + (uint32_t)(arow * 48 + (t & 1) * 16);
    uint32_t b_dst = sb + (uint32_t)(bj * 272 + bc * 2);

    int wl = wid >> 1, wc = wid & 1;
    uint32_t a_off = (uint32_t)((wl * 32 + (lane & 7) + ((lane >> 3) & 1) * 8) * 48 +
                                ((lane >> 4) * 8) * 2);
    uint32_t b_off = (uint32_t)(((lane & 7) + ((lane >> 3) & 1) * 8) * 272 +
                                (wc * 64 + (lane >> 4) * 8) * 2);

    float acc[2][8][4];
#pragma unroll
    for (int i = 0; i < 2; i++)
#pragma unroll
        for (int n = 0; n < 8; n++)
#pragma unroll
            for (int q = 0; q < 4; q++) acc[i][n][q] = 0.f;

#pragma unroll
    for (int p = 0; p < 3; p++) {
        cp16(a_dst + AP_AH + p * AP_ASTG, ahg + p * 16);
        cp16(b_dst + AP_BH + p * AP_BSTG, bhg + (size_t)p * 16 * C2);
        CP_COMMIT();
    }

    for (int ch = 0; ch < 64; ch++) {
        int stg = ch & 3;
        CP_WAIT2();
        __syncthreads();

        if (ch + 3 < 64) {
            int ns = (ch + 3) & 3;
            cp16(a_dst + AP_AH + ns * AP_ASTG, ahg + (ch + 3) * 16);
            cp16(b_dst + AP_BH + ns * AP_BSTG, bhg + (size_t)(ch + 3) * 16 * C2);
        }
        CP_COMMIT();

        uint32_t ah_base = sb + AP_AH + stg * AP_ASTG + a_off;
        uint32_t bh_base = sb + AP_BH + stg * AP_BSTG + b_off;

        uint ah[2][4];
#pragma unroll
        for (int ln = 0; ln < 2; ln++)
            ldsm4(ah_base + ln * 16 * 48, ah[ln][0], ah[ln][1], ah[ln][2], ah[ln][3]);
#pragma unroll
        for (int nn = 0; nn < 4; nn++) {
            uint bh0, bh1, bh2, bh3;
            ldsm4t(bh_base + nn * 32, bh0, bh1, bh2, bh3);
#pragma unroll
            for (int ln = 0; ln < 2; ln++) {
                mma16816(acc[ln][2 * nn], ah[ln][0], ah[ln][1], ah[ln][2], ah[ln][3], bh0, bh1);
                mma16816(acc[ln][2 * nn + 1], ah[ln][0], ah[ln][1], ah[ln][2], ah[ln][3], bh2, bh3);
            }
        }
    }

    unsigned short* aphb = g_aph + (size_t)b * Sn * C2;
    unsigned short* aplb = g_apl + (size_t)b * Sn * C2;
#pragma unroll
    for (int ln = 0; ln < 2; ln++) {
        int r0 = l0 + wl * 32 + ln * 16 + (lane >> 2);
#pragma unroll
        for (int n = 0; n < 8; n++) {
            int c = wc * 64 + n * 8 + (lane & 3) * 2;
            uint h01, l01, h23, l23;
            split2(acc[ln][n][0], acc[ln][n][1], h01, l01);
            split2(acc[ln][n][2], acc[ln][n][3], h23, l23);
            *(uint*)(aphb + (size_t)r0 * C2 + c) = h01;
            *(uint*)(aplb + (size_t)r0 * C2 + c) = l01;
            *(uint*)(aphb + (size_t)(r0 + 8) * C2 + c) = h23;
            *(uint*)(aplb + (size_t)(r0 + 8) * C2 + c) = l23;
        }
    }
}

// ---------------------------------------------------------------------------
// output conv + residual (R13-proven): SPLIT w2 x SPLIT app.
// ---------------------------------------------------------------------------
#define OC_AH 0
#define OC_AL 24576
#define OC_BH 49152
#define OC_BL 66560
#define OC_SMEM 83968

__global__ __launch_bounds__(256) void out_conv_hmma_k(
    const float* __restrict__ x, const float* __restrict__ b2,
    const float* __restrict__ gamma, float* __restrict__ out) {
    extern __shared__ __align__(16) char dsm[];
    uint32_t sb = smem_u32(dsm);

    int t = threadIdx.x, lane = t & 31, wid = t >> 5;
    int b = blockIdx.z, o0 = blockIdx.y * 128, sp0 = blockIdx.x * 128;

    int arow = t >> 1, ak = (t & 1) * 8;
    const unsigned short* whg = g_w2h + (size_t)(o0 + arow) * C2 + ak;
    const unsigned short* wlg = g_w2l + (size_t)(o0 + arow) * C2 + ak;
    int bkk = t >> 4, bsg = (t & 15) * 8;
    const unsigned short* aphg = g_aph + (size_t)b * Sn * C2 + (size_t)bkk * Sn + sp0 + bsg;
    const unsigned short* aplg = g_apl + (size_t)b * Sn * C2 + (size_t)bkk * Sn + sp0 + bsg;

    uint32_t a_dst = sb + (uint32_t)(arow * 48 + (t & 1) * 16);
    uint32_t b_dst = sb + (uint32_t)(bkk * 272 + bsg * 2);

    int wl = wid >> 1, wc = wid & 1;
    uint32_t a_off = (uint32_t)((wl * 32 + (lane & 7) + ((lane >> 3) & 1) * 8) * 48 +
                                ((lane >> 4) * 8) * 2);
    uint32_t b_off = (uint32_t)(((lane & 7) + ((lane >> 3) & 1) * 8) * 272 +
                                (wc * 64 + (lane >> 4) * 8) * 2);

    float acc[2][8][4];
#pragma unroll
    for (int i = 0; i < 2; i++)
#pragma unroll
        for (int n = 0; n < 8; n++)
#pragma unroll
            for (int q = 0; q < 4; q++) acc[i][n][q] = 0.f;

#pragma unroll
    for (int p = 0; p < 3; p++) {
        cp16(a_dst + OC_AH + p * AP_ASTG, whg + p * 16);
        cp16(a_dst + OC_AL + p * AP_ASTG, wlg + p * 16);
        cp16(b_dst + OC_BH + p * AP_BSTG, aphg + (size_t)p * 16 * Sn);
        cp16(b_dst + OC_BL + p * AP_BSTG, aplg + (size_t)p * 16 * Sn);
        CP_COMMIT();
    }

    for (int ch = 0; ch < 8; ch++) {
        int stg = ch & 3;
        CP_WAIT2();
        __syncthreads();

        if (ch + 3 < 8) {
            int ns = (ch + 3) & 3;
            cp16(a_dst + OC_AH + ns * AP_ASTG, whg + (ch + 3) * 16);
            cp16(a_dst + OC_AL + ns * AP_ASTG, wlg + (ch + 3) * 16);
            cp16(b_dst + OC_BH + ns * AP_BSTG, aphg + (size_t)(ch + 3) * 16 * Sn);
            cp16(b_dst + OC_BL + ns * AP_BSTG, aplg + (size_t)(ch + 3) * 16 * Sn);
        }
        CP_COMMIT();

        uint32_t ah_base = sb + OC_AH + stg * AP_ASTG + a_off;
        uint32_t al_base = sb + OC_AL + stg * AP_ASTG + a_off;
        uint32_t bh_base = sb + OC_BH + stg * AP_BSTG + b_off;
        uint32_t bl_base = sb + OC_BL + stg * AP_BSTG + b_off;

        uint ah[2][4], al2[2][4];
#pragma unroll
        for (int ln = 0; ln < 2; ln++) {
            ldsm4(ah_base + ln * 16 * 48, ah[ln][0], ah[ln][1], ah[ln][2], ah[ln][3]);
            ldsm4(al_base + ln * 16 * 48, al2[ln][0], al2[ln][1], al2[ln][2], al2[ln][3]);
        }
#pragma unroll
        for (int nn = 0; nn < 4; nn++) {
            uint bh0, bh1, bh2, bh3, bl0, bl1, bl2, bl3;
            ldsm4t(bh_base + nn * 32, bh0, bh1, bh2, bh3);
            ldsm4t(bl_base + nn * 32, bl0, bl1, bl2, bl3);
#pragma unroll
            for (int ln = 0; ln < 2; ln++) {
                mma16816(acc[ln][2 * nn], ah[ln][0], ah[ln][1], ah[ln][2], ah[ln][3], bh0, bh1);
                mma16816(acc[ln][2 * nn], ah[ln][0], ah[ln][1], ah[ln][2], ah[ln][3], bl0, bl1);
                mma16816(acc[ln][2 * nn], al2[ln][0], al2[ln][1], al2[ln][2], al2[ln][3], bh0, bh1);
                mma16816(acc[ln][2 * nn + 1], ah[ln][0], ah[ln][1], ah[ln][2], ah[ln][3], bh2, bh3);
                mma16816(acc[ln][2 * nn + 1], ah[ln][0], ah[ln][1], ah[ln][2], ah[ln][3], bl2, bl3);
                mma16816(acc[ln][2 * nn + 1], al2[ln][0], al2[ln][1], al2[ln][2], al2[ln][3], bh2, bh3);
            }
        }
    }

    float g = gamma[0];
#pragma unroll
    for (int ln = 0; ln < 2; ln++) {
        int o1 = o0 + wl * 32 + ln * 16 + (lane >> 2);
        int o2 = o1 + 8;
        float bb1 = b2[o1], bb2 = b2[o2];
#pragma unroll
        for (int n = 0; n < 8; n++) {
            int sp = sp0 + wc * 64 + n * 8 + (lane & 3) * 2;
            const float* x1 = x + (size_t)b * Cc * Sn + (size_t)o1 * Sn + sp;
            const float* x2 = x + (size_t)b * Cc * Sn + (size_t)o2 * Sn + sp;
            float* y1 = out + (size_t)b * Cc * Sn + (size_t)o1 * Sn + sp;
            float* y2 = out + (size_t)b * Cc * Sn + (size_t)o2 * Sn + sp;
            float2 xa = *(const float2*)(x1);
            float2 xb = *(const float2*)(x2);
            float2 r1, r2;
            r1.x = fmaf(g, acc[ln][n][0] + bb1, xa.x);
            r1.y = fmaf(g, acc[ln][n][1] + bb1, xa.y);
            r2.x = fmaf(g, acc[ln][n][2] + bb2, xb.x);
            r2.y = fmaf(g, acc[ln][n][3] + bb2, xb.y);
            *(float2*)(y1) = r1;
            *(float2*)(y2) = r2;
        }
    }
}

// ---------------------------------------------------------------------------
extern "C" void kernel_launch(void* const* d_in, const int* in_sizes, int n_in,
                              void* d_out, int out_size) {
    const float* x   = (const float*)d_in[0];
    const float* qw  = (const float*)d_in[1];
    const float* qb  = (const float*)d_in[2];
    const float* kw  = (const float*)d_in[3];
    const float* kb  = (const float*)d_in[4];
    const float* vw  = (const float*)d_in[5];
    const float* vb  = (const float*)d_in[6];
    const float* v2w = (const float*)d_in[7];
    const float* v2b = (const float*)d_in[8];
    const float* gm  = (const float*)d_in[9];
    float* out = (float*)d_out;

    static int smem_set = 0;
    if (!smem_set) {
        cudaFuncSetAttribute(applied_hmma_k,
                             cudaFuncAttributeMaxDynamicSharedMemorySize, AP_SMEM);
        cudaFuncSetAttribute(out_conv_hmma_k,
                             cudaFuncAttributeMaxDynamicSharedMemorySize, OC_SMEM);
        smem_set = 1;
    }

    conv_all_k<<<dim3(32, 3, Bn), 128>>>(x, qw, qb, kw, kb, vw, vb);
    zero_k<<<Bn * Dn / 1024, 1024>>>();
    wsplit_k<<<(Cc * C2 / 8) / 256, 256>>>(v2w);
    attn_hmma_k<<<dim3(Dn / 128, Sn / 128, Bn), 256>>>();
    recip_k<<<Bn * Dn / 1024, 1024>>>();
    vpack_k<<<(Bn * C2 * Dn / 8) / 256, 256>>>();
    applied_hmma_k<<<dim3(Sn / 128, Bn), 256, AP_SMEM>>>();
    out_conv_hmma_k<<<dim3(Sn / 128, Cc / 128, Bn), 256, OC_SMEM>>>(x, v2b, gm, out);
}